// round 10
// baseline (speedup 1.0000x reference)
#include <cuda_runtime.h>
#include <cuda_fp16.h>
#include <math.h>
#include <stddef.h>
#include <stdint.h>

#define BB   8
#define SS   1024
#define DD   1024
#define HH   16
#define DHH  64
#define FF   4096
#define MR   (BB*SS)   // 8192 rows

// ---------------- scratch (device globals) ----------------------------------
__device__ float g_t1 [MR*DD];
__device__ float g_x1 [MR*DD];

__device__ __half g_ah[MR*DD];            // activation fp16 (x / ctx / x1)
__device__ __half g_qh[MR*DD];
__device__ __half g_kh[MR*DD];
__device__ __half g_vh[MR*DD];
__device__ __half g_hh[(size_t)MR*FF];    // FFN hidden
// weights, [N,K] K-major
__device__ __half g_wqkv[3*DD*DD];        // packed Wq|Wk|Wv
__device__ float  g_bqkv[3*DD];           // packed bq|bk|bv
__device__ __half g_woh[DD*DD];
__device__ __half g_w1h[(size_t)DD*FF];
__device__ __half g_w2h[(size_t)FF*DD];

// ================= PTX helpers ==============================================
__device__ __forceinline__ uint32_t smem_u32(const void* p) {
    uint32_t a;
    asm("{ .reg .u64 t; cvta.to.shared.u64 t, %1; cvt.u32.u64 %0, t; }"
        : "=r"(a) : "l"(p));
    return a;
}
__device__ __forceinline__ uint32_t sw128(uint32_t o) {
    return o ^ ((o >> 3) & 0x70);
}
__device__ __forceinline__ void cp16(uint32_t s, const void* g) {
    asm volatile("cp.async.cg.shared.global [%0], [%1], 16;" :: "r"(s), "l"(g));
}
#define CP_COMMIT()  asm volatile("cp.async.commit_group;" ::: "memory")
#define CP_WAIT0()   asm volatile("cp.async.wait_group 0;" ::: "memory")
#define CP_WAIT1()   asm volatile("cp.async.wait_group 1;" ::: "memory")
#define CP_WAIT2()   asm volatile("cp.async.wait_group 2;" ::: "memory")
#define CP_WAIT3()   asm volatile("cp.async.wait_group 3;" ::: "memory")

__device__ __forceinline__ void ldsm4(uint32_t* r, uint32_t addr) {
    asm volatile("ldmatrix.sync.aligned.m8n8.x4.shared.b16 {%0,%1,%2,%3}, [%4];"
                 : "=r"(r[0]), "=r"(r[1]), "=r"(r[2]), "=r"(r[3]) : "r"(addr));
}
__device__ __forceinline__ void ldsm4t(uint32_t* r, uint32_t addr) {
    asm volatile("ldmatrix.sync.aligned.m8n8.x4.trans.shared.b16 {%0,%1,%2,%3}, [%4];"
                 : "=r"(r[0]), "=r"(r[1]), "=r"(r[2]), "=r"(r[3]) : "r"(addr));
}
__device__ __forceinline__ void mma16816(float* d, const uint32_t* a,
                                         const uint32_t* b) {
    asm("mma.sync.aligned.m16n8k16.row.col.f32.f16.f16.f32 "
        "{%0,%1,%2,%3}, {%4,%5,%6,%7}, {%8,%9}, {%0,%1,%2,%3};"
        : "+f"(d[0]), "+f"(d[1]), "+f"(d[2]), "+f"(d[3])
        : "r"(a[0]), "r"(a[1]), "r"(a[2]), "r"(a[3]),
          "r"(b[0]), "r"(b[1]));
}

// ================= mma.sync GEMM (fp16, 256x128 CTA tile, 4-stage) ==========
// C[M,N] = A @ B^T (B stored [N,K] K-major) + bias.
// 8 warps in 4x2, warp tile 64x64. One CTA per SM; deep cp.async pipeline.
// SPLITOUT: 0 fp32 C | 2 fp16 C | 3 QKV route (q/k/v fp16)
#define G_STAGE   49152           // A 32K | B 16K
#define G_NSTAGE  4
#define G_SMEM    (G_NSTAGE*G_STAGE)   // 192 KB

template<int ACT, int SPLITOUT>
__global__ __launch_bounds__(256, 1)
void gemm_mma(const __half* __restrict__ Ah,
              const __half* __restrict__ Bh,
              const float* __restrict__ bias,
              float* __restrict__ C,
              __half* __restrict__ Ch,
              __half* __restrict__ Kh_,
              __half* __restrict__ Vh_,
              int N, int K)
{
    extern __shared__ __align__(128) char smem[];
    const uint32_t sb = smem_u32(smem);
    const int tid  = threadIdx.x;
    const int wid  = tid >> 5;
    const int lane = tid & 31;
    const int wm   = wid & 3;        // 0..3 over M (64 rows each)
    const int wn   = wid >> 2;       // 0..1 over N (64 cols each)
    const int bc = blockIdx.x, br = blockIdx.y;

    const __half* Ah_t = Ah + (size_t)br * 256 * K;
    const __half* Bh_t = Bh + (size_t)bc * 128 * K;
    const int NT = K >> 6;

    auto load_stage = [&](int kt, int s) {
        const uint32_t base = sb + s * G_STAGE;
        const int koff = kt * 64;
        #pragma unroll
        for (int t = 0; t < 8; t++) {                  // A: 256 rows
            int idx = t * 256 + tid;
            int row = idx >> 3, ch = idx & 7;
            uint32_t so = sw128((uint32_t)(row * 128 + ch * 16));
            cp16(base + so, Ah_t + (size_t)row * K + koff + ch * 8);
        }
        #pragma unroll
        for (int t = 0; t < 4; t++) {                  // B: 128 rows
            int idx = t * 256 + tid;
            int row = idx >> 3, ch = idx & 7;
            uint32_t so = sw128((uint32_t)(row * 128 + ch * 16));
            cp16(base + 32768 + so, Bh_t + (size_t)row * K + koff + ch * 8);
        }
        CP_COMMIT();
    };

    float acc[4][8][4];
    #pragma unroll
    for (int mi = 0; mi < 4; mi++)
        #pragma unroll
        for (int nj = 0; nj < 8; nj++)
            #pragma unroll
            for (int e = 0; e < 4; e++) acc[mi][nj][e] = 0.f;

    const int g = lane >> 3, r = lane & 7;

    load_stage(0, 0);
    load_stage(1, 1);
    load_stage(2, 2);

    for (int kt = 0; kt < NT; kt++) {
        const int s = kt & 3;
        if (kt + 3 < NT) load_stage(kt + 3, (kt + 3) & 3);
        const int rem = NT - 1 - kt;
        if      (rem >= 3) CP_WAIT3();
        else if (rem == 2) CP_WAIT2();
        else if (rem == 1) CP_WAIT1();
        else               CP_WAIT0();
        __syncthreads();

        const uint32_t sA = sb + s * G_STAGE;
        const uint32_t sB = sA + 32768;

        #pragma unroll
        for (int kc = 0; kc < 4; kc++) {
            uint32_t a_h[4][4];
            #pragma unroll
            for (int mi = 0; mi < 4; mi++) {
                int arow = wm * 64 + mi * 16 + r + ((g & 1) << 3);
                uint32_t off = sw128((uint32_t)(arow * 128 + kc * 32 +
                                                ((g >> 1) << 4)));
                ldsm4(a_h[mi], sA + off);
            }
            uint32_t b_h[4][4];
            #pragma unroll
            for (int np = 0; np < 4; np++) {
                int brow = wn * 64 + np * 16 + r + ((g >> 1) << 3);
                uint32_t off = sw128((uint32_t)(brow * 128 + kc * 32 +
                                                ((g & 1) << 4)));
                ldsm4(b_h[np], sB + off);
            }
            #pragma unroll
            for (int np = 0; np < 4; np++)
                #pragma unroll
                for (int t = 0; t < 2; t++)
                    #pragma unroll
                    for (int mi = 0; mi < 4; mi++)
                        mma16816(acc[mi][np * 2 + t], a_h[mi], &b_h[np][2 * t]);
        }
        __syncthreads();
    }

    const int rbase = br * 256 + wm * 64 + (lane >> 2);

    if (SPLITOUT == 3) {
        // QKV routing: bc 0-7 -> Q, 8-15 -> K, 16-23 -> V (all fp16)
        const int sel   = bc >> 3;
        const int cloc0 = (bc & 7) * 128 + wn * 64 + (lane & 3) * 2;
        const int cgl0  = bc * 128 + wn * 64 + (lane & 3) * 2;
        __half* dst = (sel == 0) ? Ch : (sel == 1) ? Kh_ : Vh_;
        #pragma unroll
        for (int mi = 0; mi < 4; mi++) {
            #pragma unroll
            for (int nj = 0; nj < 8; nj++) {
                float2 bv = *(const float2*)(bias + cgl0 + nj * 8);
                float v0 = acc[mi][nj][0] + bv.x;
                float v1 = acc[mi][nj][1] + bv.y;
                float v2 = acc[mi][nj][2] + bv.x;
                float v3 = acc[mi][nj][3] + bv.y;
                size_t i0 = (size_t)(rbase + mi * 16)     * DD + cloc0 + nj * 8;
                size_t i1 = (size_t)(rbase + mi * 16 + 8) * DD + cloc0 + nj * 8;
                *(__half2*)(dst + i0) = __floats2half2_rn(v0, v1);
                *(__half2*)(dst + i1) = __floats2half2_rn(v2, v3);
            }
        }
        return;
    }

    const int cbase = bc * 128 + wn * 64 + (lane & 3) * 2;
    #pragma unroll
    for (int mi = 0; mi < 4; mi++) {
        #pragma unroll
        for (int nj = 0; nj < 8; nj++) {
            int c = cbase + nj * 8;
            float2 bv = *(const float2*)(bias + c);
            float v0 = acc[mi][nj][0] + bv.x;
            float v1 = acc[mi][nj][1] + bv.y;
            float v2 = acc[mi][nj][2] + bv.x;
            float v3 = acc[mi][nj][3] + bv.y;
            if (ACT) {
                v0 = fmaxf(v0, 0.f); v1 = fmaxf(v1, 0.f);
                v2 = fmaxf(v2, 0.f); v3 = fmaxf(v3, 0.f);
            }
            size_t i0 = (size_t)(rbase + mi * 16)     * N + c;
            size_t i1 = (size_t)(rbase + mi * 16 + 8) * N + c;
            if (SPLITOUT == 2) {
                *(__half2*)(Ch + i0) = __floats2half2_rn(v0, v1);
                *(__half2*)(Ch + i1) = __floats2half2_rn(v2, v3);
            } else {
                float2 o0; o0.x = v0; o0.y = v1;
                float2 o1; o1.x = v2; o1.y = v3;
                *(float2*)(C + i0) = o0;
                *(float2*)(C + i1) = o1;
            }
        }
    }
}

// ================= Flash attention (pure fp16, fp32 softmax) ================
#define A_QH   0
#define A_ST   16384            // 2 stages x (Kh 8K | Vh 8K)
#define A_MK   49152            // 2 x 256 B mask
#define A_SMEM (49152 + 512)

__global__ __launch_bounds__(256, 2)
void attn_mma(const __half* __restrict__ qh,
              const __half* __restrict__ kh,
              const __half* __restrict__ vh,
              const float* __restrict__ mask,
              __half* __restrict__ ch)
{
    extern __shared__ __align__(128) char smem[];
    const uint32_t sb = smem_u32(smem);
    const int tid  = threadIdx.x;
    const int wid  = tid >> 5;
    const int lane = tid & 31;
    const int g    = lane >> 3, r8 = lane & 7;
    const int c2   = (lane & 3) * 2;

    const int qt = blockIdx.x;
    const int bh = blockIdx.y;
    const int b  = bh >> 4;
    const int h  = bh & 15;

    const size_t qrow0 = (size_t)b * SS + (size_t)qt * 128;
    const __half* qhg = qh + qrow0 * DD + h * DHH;
    const __half* khg = kh + (size_t)b * SS * DD + h * DHH;
    const __half* vhg = vh + (size_t)b * SS * DD + h * DHH;
    const float* mkg = mask + (size_t)b * SS;

    auto load_kv = [&](int t, int s) {
        const uint32_t base = sb + A_ST + s * 16384;
        const size_t koff = (size_t)(t * 64) * DD;
        #pragma unroll
        for (int it = 0; it < 4; it++) {
            int idx = it * 256 + tid;
            int mat = idx >> 9;
            int sub = idx & 511;
            int row = sub >> 3, chk = sub & 7;
            uint32_t so = sw128((uint32_t)(row * 128 + chk * 16));
            size_t go = koff + (size_t)row * DD + chk * 8;
            cp16(base + mat * 8192 + so, (mat ? vhg : khg) + go);
        }
        if (tid < 16)
            cp16(sb + A_MK + s * 256 + tid * 16, mkg + t * 64 + tid * 4);
        CP_COMMIT();
    };

    #pragma unroll
    for (int it = 0; it < 4; it++) {
        int idx = it * 256 + tid;
        int row = idx >> 3, chk = idx & 7;
        uint32_t so = sw128((uint32_t)(row * 128 + chk * 16));
        cp16(sb + A_QH + so, qhg + (size_t)row * DD + chk * 8);
    }
    load_kv(0, 0);

    float mA = -INFINITY, mB = -INFINITY, lA = 0.f, lB = 0.f;
    float O[8][4];
    #pragma unroll
    for (int j = 0; j < 8; j++)
        #pragma unroll
        for (int e = 0; e < 4; e++) O[j][e] = 0.f;

    #pragma unroll 1
    for (int t = 0; t < 16; t++) {
        const int buf = t & 1;
        if (t + 1 < 16) { load_kv(t + 1, buf ^ 1); CP_WAIT1(); }
        else            { CP_WAIT0(); }
        __syncthreads();

        const uint32_t sKh = sb + A_ST + buf * 16384;
        const uint32_t sVh = sKh + 8192;
        const float* mkv = (const float*)(smem + A_MK + buf * 256);

        float s_[8][4];
        #pragma unroll
        for (int j = 0; j < 8; j++)
            #pragma unroll
            for (int e = 0; e < 4; e++) s_[j][e] = 0.f;

        #pragma unroll
        for (int kc = 0; kc < 4; kc++) {
            uint32_t aqh[4];
            {
                int arow = wid * 16 + r8 + ((g & 1) << 3);
                uint32_t off = sw128((uint32_t)(arow * 128 + kc * 32 +
                                                ((g >> 1) << 4)));
                ldsm4(aqh, sb + A_QH + off);
            }
            uint32_t bkh[4][4];
            #pragma unroll
            for (int np = 0; np < 4; np++) {
                int brow = np * 16 + r8 + ((g >> 1) << 3);
                uint32_t off = sw128((uint32_t)(brow * 128 + kc * 32 +
                                                ((g & 1) << 4)));
                ldsm4(bkh[np], sKh + off);
            }
            #pragma unroll
            for (int np = 0; np < 4; np++)
                #pragma unroll
                for (int t2 = 0; t2 < 2; t2++)
                    mma16816(s_[np * 2 + t2], aqh, &bkh[np][2 * t2]);
        }

        float tmA = -INFINITY, tmB = -INFINITY;
        #pragma unroll
        for (int j = 0; j < 8; j++) {
            float mk0 = mkv[j * 8 + c2]     * (-1e9f);
            float mk1 = mkv[j * 8 + c2 + 1] * (-1e9f);
            s_[j][0] = s_[j][0] * 0.125f + mk0;
            s_[j][1] = s_[j][1] * 0.125f + mk1;
            s_[j][2] = s_[j][2] * 0.125f + mk0;
            s_[j][3] = s_[j][3] * 0.125f + mk1;
            tmA = fmaxf(tmA, fmaxf(s_[j][0], s_[j][1]));
            tmB = fmaxf(tmB, fmaxf(s_[j][2], s_[j][3]));
        }
        tmA = fmaxf(tmA, __shfl_xor_sync(0xffffffffu, tmA, 1));
        tmA = fmaxf(tmA, __shfl_xor_sync(0xffffffffu, tmA, 2));
        tmB = fmaxf(tmB, __shfl_xor_sync(0xffffffffu, tmB, 1));
        tmB = fmaxf(tmB, __shfl_xor_sync(0xffffffffu, tmB, 2));

        const float nmA = fmaxf(mA, tmA), nmB = fmaxf(mB, tmB);
        const float fA = __expf(mA - nmA), fB = __expf(mB - nmB);

        float sumA = 0.f, sumB = 0.f;
        #pragma unroll
        for (int j = 0; j < 8; j++) {
            s_[j][0] = __expf(s_[j][0] - nmA);
            s_[j][1] = __expf(s_[j][1] - nmA);
            s_[j][2] = __expf(s_[j][2] - nmB);
            s_[j][3] = __expf(s_[j][3] - nmB);
            sumA += s_[j][0] + s_[j][1];
            sumB += s_[j][2] + s_[j][3];
        }
        sumA += __shfl_xor_sync(0xffffffffu, sumA, 1);
        sumA += __shfl_xor_sync(0xffffffffu, sumA, 2);
        sumB += __shfl_xor_sync(0xffffffffu, sumB, 1);
        sumB += __shfl_xor_sync(0xffffffffu, sumB, 2);
        lA = lA * fA + sumA;  mA = nmA;
        lB = lB * fB + sumB;  mB = nmB;

        #pragma unroll
        for (int j = 0; j < 8; j++) {
            O[j][0] *= fA; O[j][1] *= fA;
            O[j][2] *= fB; O[j][3] *= fB;
        }

        #pragma unroll
        for (int c = 0; c < 4; c++) {
            uint32_t ap_h[4];
            __half2 p0 = __floats2half2_rn(s_[2 * c][0],     s_[2 * c][1]);
            __half2 p1 = __floats2half2_rn(s_[2 * c][2],     s_[2 * c][3]);
            __half2 p2 = __floats2half2_rn(s_[2 * c + 1][0], s_[2 * c + 1][1]);
            __half2 p3 = __floats2half2_rn(s_[2 * c + 1][2], s_[2 * c + 1][3]);
            ap_h[0] = *(uint32_t*)&p0; ap_h[1] = *(uint32_t*)&p1;
            ap_h[2] = *(uint32_t*)&p2; ap_h[3] = *(uint32_t*)&p3;
            uint32_t bvh[4][4];
            #pragma unroll
            for (int np2 = 0; np2 < 4; np2++) {
                int vrow = c * 16 + r8 + ((g & 1) << 3);
                uint32_t off = sw128((uint32_t)(vrow * 128 + np2 * 32 +
                                                ((g >> 1) << 4)));
                ldsm4t(bvh[np2], sVh + off);
            }
            #pragma unroll
            for (int np2 = 0; np2 < 4; np2++)
                #pragma unroll
                for (int t2 = 0; t2 < 2; t2++)
                    mma16816(O[np2 * 2 + t2], ap_h, &bvh[np2][2 * t2]);
        }
        __syncthreads();
    }

    const float liA = 1.f / lA, liB = 1.f / lB;
    const size_t rowA = qrow0 + wid * 16 + (lane >> 2);
    const size_t rowB = rowA + 8;
    const int    colb = h * DHH + c2;
    #pragma unroll
    for (int j = 0; j < 8; j++) {
        *(__half2*)(ch + rowA * DD + colb + j * 8) =
            __floats2half2_rn(O[j][0] * liA, O[j][1] * liA);
        *(__half2*)(ch + rowB * DD + colb + j * 8) =
            __floats2half2_rn(O[j][2] * liB, O[j][3] * liB);
    }
}

// ================= fp32 -> fp16 convert =====================================
__global__ __launch_bounds__(256) void convert_kernel(
    const float4* __restrict__ in, __half2* __restrict__ oh, int n4)
{
    int i = blockIdx.x * 256 + threadIdx.x;
    if (i >= n4) return;
    float4 v = in[i];
    oh[2 * i]     = __floats2half2_rn(v.x, v.y);
    oh[2 * i + 1] = __floats2half2_rn(v.z, v.w);
}

// W[K,N] fp32 -> fp16 [N,K] (transpose)
__global__ __launch_bounds__(256) void split_tr_kernel(
    const float* __restrict__ W, __half* __restrict__ oh, int K, int N)
{
    __shared__ float t[32][33];
    const int bx = blockIdx.x, by = blockIdx.y;
    const int tx = threadIdx.x, ty = threadIdx.y;
    #pragma unroll
    for (int i = 0; i < 4; i++) {
        int rr = ty + i * 8;
        t[rr][tx] = W[(size_t)(by * 32 + rr) * N + bx * 32 + tx];
    }
    __syncthreads();
    #pragma unroll
    for (int i = 0; i < 4; i++) {
        int rr = ty + i * 8;
        size_t o = (size_t)(bx * 32 + rr) * K + by * 32 + tx;
        oh[o] = __float2half_rn(t[tx][rr]);
    }
}

__global__ void pack_bias_kernel(const float* __restrict__ b0,
                                 const float* __restrict__ b1,
                                 const float* __restrict__ b2,
                                 float* __restrict__ dst)
{
    const float* src = (blockIdx.x == 0) ? b0 : (blockIdx.x == 1) ? b1 : b2;
    dst[blockIdx.x * DD + threadIdx.x] = src[threadIdx.x];
}

// ================= residual + LayerNorm =====================================
template<int SPL>
__global__ __launch_bounds__(256) void residual_ln_kernel(
    const float* __restrict__ X, const float* __restrict__ Y,
    const float* __restrict__ g, const float* __restrict__ beta,
    float* __restrict__ out, __half* __restrict__ oh)
{
    __shared__ float ws[8], ws2[8];
    const int row = blockIdx.x;
    const int tid = threadIdx.x;
    const int lane = tid & 31, warp = tid >> 5;
    const float* px = X + (size_t)row * DD;
    const float* py = Y + (size_t)row * DD;

    float v[4];
    float s = 0.f, s2 = 0.f;
    #pragma unroll
    for (int l = 0; l < 4; l++) {
        int c = tid + l * 256;
        float t = px[c] + py[c];
        v[l] = t; s += t; s2 += t * t;
    }
    #pragma unroll
    for (int off = 16; off; off >>= 1) {
        s  += __shfl_xor_sync(0xffffffffu, s,  off);
        s2 += __shfl_xor_sync(0xffffffffu, s2, off);
    }
    if (lane == 0) { ws[warp] = s; ws2[warp] = s2; }
    __syncthreads();
    if (warp == 0) {
        s  = (lane < 8) ? ws[lane]  : 0.f;
        s2 = (lane < 8) ? ws2[lane] : 0.f;
        #pragma unroll
        for (int off = 4; off; off >>= 1) {
            s  += __shfl_xor_sync(0xffffffffu, s,  off);
            s2 += __shfl_xor_sync(0xffffffffu, s2, off);
        }
        if (lane == 0) { ws[0] = s; ws2[0] = s2; }
    }
    __syncthreads();
    float mu  = ws[0] * (1.f / 1024.f);
    float var = fmaxf(ws2[0] * (1.f / 1024.f) - mu * mu, 0.f);
    float rstd = rsqrtf(var + 1e-6f);
    #pragma unroll
    for (int l = 0; l < 4; l++) {
        int c = tid + l * 256;
        float rv = g[c] * (v[l] - mu) * rstd + beta[c];
        out[(size_t)row * DD + c] = rv;
        if (SPL) oh[(size_t)row * DD + c] = __float2half_rn(rv);
    }
}

// ================= launch ===================================================
extern "C" void kernel_launch(void* const* d_in, const int* in_sizes, int n_in,
                              void* d_out, int out_size)
{
    const float* x    = (const float*)d_in[0];
    const float* mask = (const float*)d_in[1];
    const float* Wq   = (const float*)d_in[2];
    const float* bq   = (const float*)d_in[3];
    const float* Wk   = (const float*)d_in[4];
    const float* bk   = (const float*)d_in[5];
    const float* Wv   = (const float*)d_in[6];
    const float* bv   = (const float*)d_in[7];
    const float* Wo   = (const float*)d_in[8];
    const float* bo   = (const float*)d_in[9];
    const float* g1   = (const float*)d_in[10];
    const float* be1  = (const float*)d_in[11];
    const float* W1   = (const float*)d_in[12];
    const float* bf1  = (const float*)d_in[13];
    const float* W2   = (const float*)d_in[14];
    const float* bf2  = (const float*)d_in[15];
    const float* g2   = (const float*)d_in[16];
    const float* be2  = (const float*)d_in[17];
    float* out = (float*)d_out;

    float *t1, *x1, *bqkv;
    __half *ah, *qh, *kh, *vh, *hh;
    __half *wqkv, *woh, *w1h, *w2h;
    cudaGetSymbolAddress((void**)&t1,   g_t1);
    cudaGetSymbolAddress((void**)&x1,   g_x1);
    cudaGetSymbolAddress((void**)&ah,   g_ah);
    cudaGetSymbolAddress((void**)&qh,   g_qh);
    cudaGetSymbolAddress((void**)&kh,   g_kh);
    cudaGetSymbolAddress((void**)&vh,   g_vh);
    cudaGetSymbolAddress((void**)&hh,   g_hh);
    cudaGetSymbolAddress((void**)&wqkv, g_wqkv);
    cudaGetSymbolAddress((void**)&bqkv, g_bqkv);
    cudaGetSymbolAddress((void**)&woh,  g_woh);
    cudaGetSymbolAddress((void**)&w1h,  g_w1h);
    cudaGetSymbolAddress((void**)&w2h,  g_w2h);

    cudaFuncSetAttribute(attn_mma,
                         cudaFuncAttributeMaxDynamicSharedMemorySize, A_SMEM);
    cudaFuncSetAttribute(gemm_mma<0, 3>,
                         cudaFuncAttributeMaxDynamicSharedMemorySize, G_SMEM);
    cudaFuncSetAttribute(gemm_mma<0, 0>,
                         cudaFuncAttributeMaxDynamicSharedMemorySize, G_SMEM);
    cudaFuncSetAttribute(gemm_mma<1, 2>,
                         cudaFuncAttributeMaxDynamicSharedMemorySize, G_SMEM);

    static cudaStream_t s2 = nullptr;
    static cudaEvent_t evF, evQKVp, evO, ev1p, ev2p;
    if (!s2) {
        cudaStreamCreateWithFlags(&s2, cudaStreamNonBlocking);
        cudaEventCreateWithFlags(&evF,    cudaEventDisableTiming);
        cudaEventCreateWithFlags(&evQKVp, cudaEventDisableTiming);
        cudaEventCreateWithFlags(&evO,    cudaEventDisableTiming);
        cudaEventCreateWithFlags(&ev1p,   cudaEventDisableTiming);
        cudaEventCreateWithFlags(&ev2p,   cudaEventDisableTiming);
    }

    const dim3 trDD(DD / 32, DD / 32);
    const dim3 trDF(FF / 32, DD / 32);
    const dim3 trFD(DD / 32, FF / 32);
    const dim3 tb(32, 8);
    const dim3 gQKV(3 * DD / 128, MR / 256);  // (24, 32)
    const dim3 gD(DD / 128, MR / 256);        // (8, 32)
    const dim3 gF(FF / 128, MR / 256);        // (32, 32)

    // ---- fork: weight prep on side stream ----
    cudaEventRecord(evF, 0);
    cudaStreamWaitEvent(s2, evF, 0);
    split_tr_kernel<<<trDD, tb, 0, s2>>>(Wq, wqkv,               DD, DD);
    split_tr_kernel<<<trDD, tb, 0, s2>>>(Wk, wqkv + DD * DD,     DD, DD);
    split_tr_kernel<<<trDD, tb, 0, s2>>>(Wv, wqkv + 2 * DD * DD, DD, DD);
    pack_bias_kernel<<<3, DD, 0, s2>>>(bq, bk, bv, bqkv);
    cudaEventRecord(evQKVp, s2);
    split_tr_kernel<<<trDD, tb, 0, s2>>>(Wo, woh, DD, DD);
    cudaEventRecord(evO, s2);
    split_tr_kernel<<<trDF, tb, 0, s2>>>(W1, w1h, DD, FF);
    cudaEventRecord(ev1p, s2);
    split_tr_kernel<<<trFD, tb, 0, s2>>>(W2, w2h, FF, DD);
    cudaEventRecord(ev2p, s2);

    // ---- main stream ----
    convert_kernel<<<(MR * DD / 4 + 255) / 256, 256>>>(
        (const float4*)x, (__half2*)ah, MR * DD / 4);

    // fused QKV projection (fp16)
    cudaStreamWaitEvent(0, evQKVp, 0);
    gemm_mma<0, 3><<<gQKV, 256, G_SMEM>>>(
        ah, wqkv, bqkv, nullptr, qh, kh, vh, 3 * DD, DD);

    // attention -> fp16 ctx into ah
    attn_mma<<<dim3(8, 128), 256, A_SMEM>>>(qh, kh, vh, mask, ah);

    // output projection + residual LN (emits fp16 x1 into ah)
    cudaStreamWaitEvent(0, evO, 0);
    gemm_mma<0, 0><<<gD, 256, G_SMEM>>>(
        ah, woh, bo, t1, nullptr, nullptr, nullptr, DD, DD);
    residual_ln_kernel<1><<<MR, 256>>>(x, t1, g1, be1, x1, ah);

    // FFN1: relu(x1 @ W1 + bf1) -> fp16 hidden
    cudaStreamWaitEvent(0, ev1p, 0);
    gemm_mma<1, 2><<<gF, 256, G_SMEM>>>(
        ah, w1h, bf1, nullptr, hh, nullptr, nullptr, FF, DD);

    // FFN2 + residual LN
    cudaStreamWaitEvent(0, ev2p, 0);
    gemm_mma<0, 0><<<gD, 256, G_SMEM>>>(
        hh, w2h, bf2, t1, nullptr, nullptr, nullptr, DD, FF);
    residual_ln_kernel<0><<<MR, 256>>>(x1, t1, g2, be2, out, nullptr);
}

// round 11
// speedup vs baseline: 1.0024x; 1.0024x over previous
#include <cuda_runtime.h>
#include <cuda_fp16.h>
#include <math.h>
#include <stddef.h>
#include <stdint.h>

#define BB   8
#define SS   1024
#define DD   1024
#define HH   16
#define DHH  64
#define FF   4096
#define MR   (BB*SS)   // 8192 rows

// ---------------- scratch (device globals) ----------------------------------
__device__ float g_t1 [MR*DD];
__device__ float g_x1 [MR*DD];

__device__ __half g_ah[MR*DD];            // activation fp16 (x / ctx / x1)
__device__ __half g_qh[MR*DD];
__device__ __half g_kh[MR*DD];
__device__ __half g_vh[MR*DD];
__device__ __half g_hh[(size_t)MR*FF];    // FFN hidden
// weights, [N,K] K-major
__device__ __half g_wqkv[3*DD*DD];        // packed Wq|Wk|Wv
__device__ float  g_bqkv[3*DD];           // packed bq|bk|bv
__device__ __half g_woh[DD*DD];
__device__ __half g_w1h[(size_t)DD*FF];
__device__ __half g_w2h[(size_t)FF*DD];

// ================= PTX helpers ==============================================
__device__ __forceinline__ uint32_t smem_u32(const void* p) {
    uint32_t a;
    asm("{ .reg .u64 t; cvta.to.shared.u64 t, %1; cvt.u32.u64 %0, t; }"
        : "=r"(a) : "l"(p));
    return a;
}
__device__ __forceinline__ uint32_t sw128(uint32_t o) {
    return o ^ ((o >> 3) & 0x70);
}
__device__ __forceinline__ void cp16(uint32_t s, const void* g) {
    asm volatile("cp.async.cg.shared.global [%0], [%1], 16;" :: "r"(s), "l"(g));
}
#define CP_COMMIT()  asm volatile("cp.async.commit_group;" ::: "memory")
#define CP_WAIT0()   asm volatile("cp.async.wait_group 0;" ::: "memory")
#define CP_WAIT1()   asm volatile("cp.async.wait_group 1;" ::: "memory")

__device__ __forceinline__ void ldsm4(uint32_t* r, uint32_t addr) {
    asm volatile("ldmatrix.sync.aligned.m8n8.x4.shared.b16 {%0,%1,%2,%3}, [%4];"
                 : "=r"(r[0]), "=r"(r[1]), "=r"(r[2]), "=r"(r[3]) : "r"(addr));
}
__device__ __forceinline__ void ldsm4t(uint32_t* r, uint32_t addr) {
    asm volatile("ldmatrix.sync.aligned.m8n8.x4.trans.shared.b16 {%0,%1,%2,%3}, [%4];"
                 : "=r"(r[0]), "=r"(r[1]), "=r"(r[2]), "=r"(r[3]) : "r"(addr));
}
__device__ __forceinline__ void mma16816(float* d, const uint32_t* a,
                                         const uint32_t* b) {
    asm("mma.sync.aligned.m16n8k16.row.col.f32.f16.f16.f32 "
        "{%0,%1,%2,%3}, {%4,%5,%6,%7}, {%8,%9}, {%0,%1,%2,%3};"
        : "+f"(d[0]), "+f"(d[1]), "+f"(d[2]), "+f"(d[3])
        : "r"(a[0]), "r"(a[1]), "r"(a[2]), "r"(a[3]),
          "r"(b[0]), "r"(b[1]));
}

// ================= mma.sync GEMM (fp16, 128x128, 3-stage, 1 sync/iter) ======
// C[M,N] = A @ B^T (B stored [N,K] K-major) + bias.
// SPLITOUT: 0 fp32 C | 2 fp16 C | 3 QKV route (q/k/v fp16)
#define G_STAGE   32768           // A 16K | B 16K
#define G_NSTAGE  3
#define G_SMEM    (G_NSTAGE*G_STAGE)   // 96 KB -> 2 CTAs/SM

template<int ACT, int SPLITOUT>
__global__ __launch_bounds__(256, 2)
void gemm_mma(const __half* __restrict__ Ah,
              const __half* __restrict__ Bh,
              const float* __restrict__ bias,
              float* __restrict__ C,
              __half* __restrict__ Ch,
              __half* __restrict__ Kh_,
              __half* __restrict__ Vh_,
              int N, int K)
{
    extern __shared__ __align__(128) char smem[];
    const uint32_t sb = smem_u32(smem);
    const int tid  = threadIdx.x;
    const int wid  = tid >> 5;
    const int lane = tid & 31;
    const int wm   = wid & 3;
    const int wn   = wid >> 2;
    const int bc = blockIdx.x, br = blockIdx.y;

    const __half* Ah_t = Ah + (size_t)br * 128 * K;
    const __half* Bh_t = Bh + (size_t)bc * 128 * K;
    const int NT = K >> 6;

    auto load_stage = [&](int kt, int s) {
        const uint32_t base = sb + s * G_STAGE;
        const int koff = kt * 64;
        #pragma unroll
        for (int t = 0; t < 4; t++) {
            int idx = t * 256 + tid;
            int row = idx >> 3, ch = idx & 7;
            uint32_t so = sw128((uint32_t)(row * 128 + ch * 16));
            size_t go = (size_t)row * K + koff + ch * 8;
            cp16(base + so,         Ah_t + go);
            cp16(base + 16384 + so, Bh_t + go);
        }
        CP_COMMIT();
    };

    float acc[2][8][4];
    #pragma unroll
    for (int mi = 0; mi < 2; mi++)
        #pragma unroll
        for (int nj = 0; nj < 8; nj++)
            #pragma unroll
            for (int e = 0; e < 4; e++) acc[mi][nj][e] = 0.f;

    const int g = lane >> 3, r = lane & 7;

    load_stage(0, 0);
    load_stage(1, 1);

    int s = 0;                 // stage index of current iter (kt % 3)
    for (int kt = 0; kt < NT; kt++) {
        if (kt + 1 < NT) CP_WAIT1();   // stage kt resident, kt+1 in flight
        else             CP_WAIT0();
        __syncthreads();               // all warps done with buffer (kt-1)%3

        // prefetch kt+2 into buffer (kt+2)%3 == (kt-1)%3 (just freed)
        if (kt + 2 < NT) {
            int s2 = s + 2; if (s2 >= 3) s2 -= 3;
            load_stage(kt + 2, s2);
        }

        const uint32_t sA = sb + s * G_STAGE;
        const uint32_t sB = sA + 16384;

        #pragma unroll
        for (int kc = 0; kc < 4; kc++) {
            uint32_t a_h[2][4];
            #pragma unroll
            for (int mi = 0; mi < 2; mi++) {
                int arow = wm * 32 + mi * 16 + r + ((g & 1) << 3);
                uint32_t off = sw128((uint32_t)(arow * 128 + kc * 32 +
                                                ((g >> 1) << 4)));
                ldsm4(a_h[mi], sA + off);
            }
            uint32_t b_h[4][4];
            #pragma unroll
            for (int np = 0; np < 4; np++) {
                int brow = wn * 64 + np * 16 + r + ((g >> 1) << 3);
                uint32_t off = sw128((uint32_t)(brow * 128 + kc * 32 +
                                                ((g & 1) << 4)));
                ldsm4(b_h[np], sB + off);
            }
            #pragma unroll
            for (int np = 0; np < 4; np++)
                #pragma unroll
                for (int t = 0; t < 2; t++)
                    #pragma unroll
                    for (int mi = 0; mi < 2; mi++)
                        mma16816(acc[mi][np * 2 + t], a_h[mi], &b_h[np][2 * t]);
        }
        if (++s == 3) s = 0;
    }

    const int rbase = br * 128 + wm * 32 + (lane >> 2);

    if (SPLITOUT == 3) {
        // QKV routing: bc 0-7 -> Q, 8-15 -> K, 16-23 -> V (all fp16)
        const int sel   = bc >> 3;
        const int cloc0 = (bc & 7) * 128 + wn * 64 + (lane & 3) * 2;
        const int cgl0  = bc * 128 + wn * 64 + (lane & 3) * 2;
        __half* dst = (sel == 0) ? Ch : (sel == 1) ? Kh_ : Vh_;
        #pragma unroll
        for (int mi = 0; mi < 2; mi++) {
            #pragma unroll
            for (int nj = 0; nj < 8; nj++) {
                float2 bv = *(const float2*)(bias + cgl0 + nj * 8);
                float v0 = acc[mi][nj][0] + bv.x;
                float v1 = acc[mi][nj][1] + bv.y;
                float v2 = acc[mi][nj][2] + bv.x;
                float v3 = acc[mi][nj][3] + bv.y;
                size_t i0 = (size_t)(rbase + mi * 16)     * DD + cloc0 + nj * 8;
                size_t i1 = (size_t)(rbase + mi * 16 + 8) * DD + cloc0 + nj * 8;
                *(__half2*)(dst + i0) = __floats2half2_rn(v0, v1);
                *(__half2*)(dst + i1) = __floats2half2_rn(v2, v3);
            }
        }
        return;
    }

    const int cbase = bc * 128 + wn * 64 + (lane & 3) * 2;
    #pragma unroll
    for (int mi = 0; mi < 2; mi++) {
        #pragma unroll
        for (int nj = 0; nj < 8; nj++) {
            int c = cbase + nj * 8;
            float2 bv = *(const float2*)(bias + c);
            float v0 = acc[mi][nj][0] + bv.x;
            float v1 = acc[mi][nj][1] + bv.y;
            float v2 = acc[mi][nj][2] + bv.x;
            float v3 = acc[mi][nj][3] + bv.y;
            if (ACT) {
                v0 = fmaxf(v0, 0.f); v1 = fmaxf(v1, 0.f);
                v2 = fmaxf(v2, 0.f); v3 = fmaxf(v3, 0.f);
            }
            size_t i0 = (size_t)(rbase + mi * 16)     * N + c;
            size_t i1 = (size_t)(rbase + mi * 16 + 8) * N + c;
            if (SPLITOUT == 2) {
                *(__half2*)(Ch + i0) = __floats2half2_rn(v0, v1);
                *(__half2*)(Ch + i1) = __floats2half2_rn(v2, v3);
            } else {
                float2 o0; o0.x = v0; o0.y = v1;
                float2 o1; o1.x = v2; o1.y = v3;
                *(float2*)(C + i0) = o0;
                *(float2*)(C + i1) = o1;
            }
        }
    }
}

// ================= Flash attention (pure fp16, fp32 softmax) ================
#define A_QH   0
#define A_ST   16384            // 2 stages x (Kh 8K | Vh 8K)
#define A_MK   49152            // 2 x 256 B mask
#define A_SMEM (49152 + 512)

__global__ __launch_bounds__(256, 2)
void attn_mma(const __half* __restrict__ qh,
              const __half* __restrict__ kh,
              const __half* __restrict__ vh,
              const float* __restrict__ mask,
              __half* __restrict__ ch)
{
    extern __shared__ __align__(128) char smem[];
    const uint32_t sb = smem_u32(smem);
    const int tid  = threadIdx.x;
    const int wid  = tid >> 5;
    const int lane = tid & 31;
    const int g    = lane >> 3, r8 = lane & 7;
    const int c2   = (lane & 3) * 2;

    const int qt = blockIdx.x;
    const int bh = blockIdx.y;
    const int b  = bh >> 4;
    const int h  = bh & 15;

    const size_t qrow0 = (size_t)b * SS + (size_t)qt * 128;
    const __half* qhg = qh + qrow0 * DD + h * DHH;
    const __half* khg = kh + (size_t)b * SS * DD + h * DHH;
    const __half* vhg = vh + (size_t)b * SS * DD + h * DHH;
    const float* mkg = mask + (size_t)b * SS;

    auto load_kv = [&](int t, int s) {
        const uint32_t base = sb + A_ST + s * 16384;
        const size_t koff = (size_t)(t * 64) * DD;
        #pragma unroll
        for (int it = 0; it < 4; it++) {
            int idx = it * 256 + tid;
            int mat = idx >> 9;
            int sub = idx & 511;
            int row = sub >> 3, chk = sub & 7;
            uint32_t so = sw128((uint32_t)(row * 128 + chk * 16));
            size_t go = koff + (size_t)row * DD + chk * 8;
            cp16(base + mat * 8192 + so, (mat ? vhg : khg) + go);
        }
        if (tid < 16)
            cp16(sb + A_MK + s * 256 + tid * 16, mkg + t * 64 + tid * 4);
        CP_COMMIT();
    };

    #pragma unroll
    for (int it = 0; it < 4; it++) {
        int idx = it * 256 + tid;
        int row = idx >> 3, chk = idx & 7;
        uint32_t so = sw128((uint32_t)(row * 128 + chk * 16));
        cp16(sb + A_QH + so, qhg + (size_t)row * DD + chk * 8);
    }
    load_kv(0, 0);

    float mA = -INFINITY, mB = -INFINITY, lA = 0.f, lB = 0.f;
    float O[8][4];
    #pragma unroll
    for (int j = 0; j < 8; j++)
        #pragma unroll
        for (int e = 0; e < 4; e++) O[j][e] = 0.f;

    #pragma unroll 1
    for (int t = 0; t < 16; t++) {
        const int buf = t & 1;
        if (t + 1 < 16) { load_kv(t + 1, buf ^ 1); CP_WAIT1(); }
        else            { CP_WAIT0(); }
        __syncthreads();

        const uint32_t sKh = sb + A_ST + buf * 16384;
        const uint32_t sVh = sKh + 8192;
        const float* mkv = (const float*)(smem + A_MK + buf * 256);

        float s_[8][4];
        #pragma unroll
        for (int j = 0; j < 8; j++)
            #pragma unroll
            for (int e = 0; e < 4; e++) s_[j][e] = 0.f;

        #pragma unroll
        for (int kc = 0; kc < 4; kc++) {
            uint32_t aqh[4];
            {
                int arow = wid * 16 + r8 + ((g & 1) << 3);
                uint32_t off = sw128((uint32_t)(arow * 128 + kc * 32 +
                                                ((g >> 1) << 4)));
                ldsm4(aqh, sb + A_QH + off);
            }
            uint32_t bkh[4][4];
            #pragma unroll
            for (int np = 0; np < 4; np++) {
                int brow = np * 16 + r8 + ((g >> 1) << 3);
                uint32_t off = sw128((uint32_t)(brow * 128 + kc * 32 +
                                                ((g & 1) << 4)));
                ldsm4(bkh[np], sKh + off);
            }
            #pragma unroll
            for (int np = 0; np < 4; np++)
                #pragma unroll
                for (int t2 = 0; t2 < 2; t2++)
                    mma16816(s_[np * 2 + t2], aqh, &bkh[np][2 * t2]);
        }

        float tmA = -INFINITY, tmB = -INFINITY;
        #pragma unroll
        for (int j = 0; j < 8; j++) {
            float mk0 = mkv[j * 8 + c2]     * (-1e9f);
            float mk1 = mkv[j * 8 + c2 + 1] * (-1e9f);
            s_[j][0] = s_[j][0] * 0.125f + mk0;
            s_[j][1] = s_[j][1] * 0.125f + mk1;
            s_[j][2] = s_[j][2] * 0.125f + mk0;
            s_[j][3] = s_[j][3] * 0.125f + mk1;
            tmA = fmaxf(tmA, fmaxf(s_[j][0], s_[j][1]));
            tmB = fmaxf(tmB, fmaxf(s_[j][2], s_[j][3]));
        }
        tmA = fmaxf(tmA, __shfl_xor_sync(0xffffffffu, tmA, 1));
        tmA = fmaxf(tmA, __shfl_xor_sync(0xffffffffu, tmA, 2));
        tmB = fmaxf(tmB, __shfl_xor_sync(0xffffffffu, tmB, 1));
        tmB = fmaxf(tmB, __shfl_xor_sync(0xffffffffu, tmB, 2));

        const float nmA = fmaxf(mA, tmA), nmB = fmaxf(mB, tmB);
        const float fA = __expf(mA - nmA), fB = __expf(mB - nmB);

        float sumA = 0.f, sumB = 0.f;
        #pragma unroll
        for (int j = 0; j < 8; j++) {
            s_[j][0] = __expf(s_[j][0] - nmA);
            s_[j][1] = __expf(s_[j][1] - nmA);
            s_[j][2] = __expf(s_[j][2] - nmB);
            s_[j][3] = __expf(s_[j][3] - nmB);
            sumA += s_[j][0] + s_[j][1];
            sumB += s_[j][2] + s_[j][3];
        }
        sumA += __shfl_xor_sync(0xffffffffu, sumA, 1);
        sumA += __shfl_xor_sync(0xffffffffu, sumA, 2);
        sumB += __shfl_xor_sync(0xffffffffu, sumB, 1);
        sumB += __shfl_xor_sync(0xffffffffu, sumB, 2);
        lA = lA * fA + sumA;  mA = nmA;
        lB = lB * fB + sumB;  mB = nmB;

        #pragma unroll
        for (int j = 0; j < 8; j++) {
            O[j][0] *= fA; O[j][1] *= fA;
            O[j][2] *= fB; O[j][3] *= fB;
        }

        #pragma unroll
        for (int c = 0; c < 4; c++) {
            uint32_t ap_h[4];
            __half2 p0 = __floats2half2_rn(s_[2 * c][0],     s_[2 * c][1]);
            __half2 p1 = __floats2half2_rn(s_[2 * c][2],     s_[2 * c][3]);
            __half2 p2 = __floats2half2_rn(s_[2 * c + 1][0], s_[2 * c + 1][1]);
            __half2 p3 = __floats2half2_rn(s_[2 * c + 1][2], s_[2 * c + 1][3]);
            ap_h[0] = *(uint32_t*)&p0; ap_h[1] = *(uint32_t*)&p1;
            ap_h[2] = *(uint32_t*)&p2; ap_h[3] = *(uint32_t*)&p3;
            uint32_t bvh[4][4];
            #pragma unroll
            for (int np2 = 0; np2 < 4; np2++) {
                int vrow = c * 16 + r8 + ((g & 1) << 3);
                uint32_t off = sw128((uint32_t)(vrow * 128 + np2 * 32 +
                                                ((g >> 1) << 4)));
                ldsm4t(bvh[np2], sVh + off);
            }
            #pragma unroll
            for (int np2 = 0; np2 < 4; np2++)
                #pragma unroll
                for (int t2 = 0; t2 < 2; t2++)
                    mma16816(O[np2 * 2 + t2], ap_h, &bvh[np2][2 * t2]);
        }
        __syncthreads();
    }

    const float liA = 1.f / lA, liB = 1.f / lB;
    const size_t rowA = qrow0 + wid * 16 + (lane >> 2);
    const size_t rowB = rowA + 8;
    const int    colb = h * DHH + c2;
    #pragma unroll
    for (int j = 0; j < 8; j++) {
        *(__half2*)(ch + rowA * DD + colb + j * 8) =
            __floats2half2_rn(O[j][0] * liA, O[j][1] * liA);
        *(__half2*)(ch + rowB * DD + colb + j * 8) =
            __floats2half2_rn(O[j][2] * liB, O[j][3] * liB);
    }
}

// ================= fp32 -> fp16 convert =====================================
__global__ __launch_bounds__(256) void convert_kernel(
    const float4* __restrict__ in, __half2* __restrict__ oh, int n4)
{
    int i = blockIdx.x * 256 + threadIdx.x;
    if (i >= n4) return;
    float4 v = in[i];
    oh[2 * i]     = __floats2half2_rn(v.x, v.y);
    oh[2 * i + 1] = __floats2half2_rn(v.z, v.w);
}

// W[K,N] fp32 -> fp16 [N,K] (transpose)
__global__ __launch_bounds__(256) void split_tr_kernel(
    const float* __restrict__ W, __half* __restrict__ oh, int K, int N)
{
    __shared__ float t[32][33];
    const int bx = blockIdx.x, by = blockIdx.y;
    const int tx = threadIdx.x, ty = threadIdx.y;
    #pragma unroll
    for (int i = 0; i < 4; i++) {
        int rr = ty + i * 8;
        t[rr][tx] = W[(size_t)(by * 32 + rr) * N + bx * 32 + tx];
    }
    __syncthreads();
    #pragma unroll
    for (int i = 0; i < 4; i++) {
        int rr = ty + i * 8;
        size_t o = (size_t)(bx * 32 + rr) * K + by * 32 + tx;
        oh[o] = __float2half_rn(t[tx][rr]);
    }
}

__global__ void pack_bias_kernel(const float* __restrict__ b0,
                                 const float* __restrict__ b1,
                                 const float* __restrict__ b2,
                                 float* __restrict__ dst)
{
    const float* src = (blockIdx.x == 0) ? b0 : (blockIdx.x == 1) ? b1 : b2;
    dst[blockIdx.x * DD + threadIdx.x] = src[threadIdx.x];
}

// ================= residual + LayerNorm =====================================
template<int SPL>
__global__ __launch_bounds__(256) void residual_ln_kernel(
    const float* __restrict__ X, const float* __restrict__ Y,
    const float* __restrict__ g, const float* __restrict__ beta,
    float* __restrict__ out, __half* __restrict__ oh)
{
    __shared__ float ws[8], ws2[8];
    const int row = blockIdx.x;
    const int tid = threadIdx.x;
    const int lane = tid & 31, warp = tid >> 5;
    const float* px = X + (size_t)row * DD;
    const float* py = Y + (size_t)row * DD;

    float v[4];
    float s = 0.f, s2 = 0.f;
    #pragma unroll
    for (int l = 0; l < 4; l++) {
        int c = tid + l * 256;
        float t = px[c] + py[c];
        v[l] = t; s += t; s2 += t * t;
    }
    #pragma unroll
    for (int off = 16; off; off >>= 1) {
        s  += __shfl_xor_sync(0xffffffffu, s,  off);
        s2 += __shfl_xor_sync(0xffffffffu, s2, off);
    }
    if (lane == 0) { ws[warp] = s; ws2[warp] = s2; }
    __syncthreads();
    if (warp == 0) {
        s  = (lane < 8) ? ws[lane]  : 0.f;
        s2 = (lane < 8) ? ws2[lane] : 0.f;
        #pragma unroll
        for (int off = 4; off; off >>= 1) {
            s  += __shfl_xor_sync(0xffffffffu, s,  off);
            s2 += __shfl_xor_sync(0xffffffffu, s2, off);
        }
        if (lane == 0) { ws[0] = s; ws2[0] = s2; }
    }
    __syncthreads();
    float mu  = ws[0] * (1.f / 1024.f);
    float var = fmaxf(ws2[0] * (1.f / 1024.f) - mu * mu, 0.f);
    float rstd = rsqrtf(var + 1e-6f);
    #pragma unroll
    for (int l = 0; l < 4; l++) {
        int c = tid + l * 256;
        float rv = g[c] * (v[l] - mu) * rstd + beta[c];
        out[(size_t)row * DD + c] = rv;
        if (SPL) oh[(size_t)row * DD + c] = __float2half_rn(rv);
    }
}

// ================= launch ===================================================
extern "C" void kernel_launch(void* const* d_in, const int* in_sizes, int n_in,
                              void* d_out, int out_size)
{
    const float* x    = (const float*)d_in[0];
    const float* mask = (const float*)d_in[1];
    const float* Wq   = (const float*)d_in[2];
    const float* bq   = (const float*)d_in[3];
    const float* Wk   = (const float*)d_in[4];
    const float* bk   = (const float*)d_in[5];
    const float* Wv   = (const float*)d_in[6];
    const float* bv   = (const float*)d_in[7];
    const float* Wo   = (const float*)d_in[8];
    const float* bo   = (const float*)d_in[9];
    const float* g1   = (const float*)d_in[10];
    const float* be1  = (const float*)d_in[11];
    const float* W1   = (const float*)d_in[12];
    const float* bf1  = (const float*)d_in[13];
    const float* W2   = (const float*)d_in[14];
    const float* bf2  = (const float*)d_in[15];
    const float* g2   = (const float*)d_in[16];
    const float* be2  = (const float*)d_in[17];
    float* out = (float*)d_out;

    float *t1, *x1, *bqkv;
    __half *ah, *qh, *kh, *vh, *hh;
    __half *wqkv, *woh, *w1h, *w2h;
    cudaGetSymbolAddress((void**)&t1,   g_t1);
    cudaGetSymbolAddress((void**)&x1,   g_x1);
    cudaGetSymbolAddress((void**)&ah,   g_ah);
    cudaGetSymbolAddress((void**)&qh,   g_qh);
    cudaGetSymbolAddress((void**)&kh,   g_kh);
    cudaGetSymbolAddress((void**)&vh,   g_vh);
    cudaGetSymbolAddress((void**)&hh,   g_hh);
    cudaGetSymbolAddress((void**)&wqkv, g_wqkv);
    cudaGetSymbolAddress((void**)&bqkv, g_bqkv);
    cudaGetSymbolAddress((void**)&woh,  g_woh);
    cudaGetSymbolAddress((void**)&w1h,  g_w1h);
    cudaGetSymbolAddress((void**)&w2h,  g_w2h);

    cudaFuncSetAttribute(attn_mma,
                         cudaFuncAttributeMaxDynamicSharedMemorySize, A_SMEM);
    cudaFuncSetAttribute(gemm_mma<0, 3>,
                         cudaFuncAttributeMaxDynamicSharedMemorySize, G_SMEM);
    cudaFuncSetAttribute(gemm_mma<0, 0>,
                         cudaFuncAttributeMaxDynamicSharedMemorySize, G_SMEM);
    cudaFuncSetAttribute(gemm_mma<1, 2>,
                         cudaFuncAttributeMaxDynamicSharedMemorySize, G_SMEM);

    static cudaStream_t s2 = nullptr;
    static cudaEvent_t evF, evQKVp, evO, ev1p, ev2p;
    if (!s2) {
        cudaStreamCreateWithFlags(&s2, cudaStreamNonBlocking);
        cudaEventCreateWithFlags(&evF,    cudaEventDisableTiming);
        cudaEventCreateWithFlags(&evQKVp, cudaEventDisableTiming);
        cudaEventCreateWithFlags(&evO,    cudaEventDisableTiming);
        cudaEventCreateWithFlags(&ev1p,   cudaEventDisableTiming);
        cudaEventCreateWithFlags(&ev2p,   cudaEventDisableTiming);
    }

    const dim3 trDD(DD / 32, DD / 32);
    const dim3 trDF(FF / 32, DD / 32);
    const dim3 trFD(DD / 32, FF / 32);
    const dim3 tb(32, 8);
    const dim3 gQKV(3 * DD / 128, MR / 128);  // (24, 64)
    const dim3 gD(DD / 128, MR / 128);        // (8, 64)
    const dim3 gF(FF / 128, MR / 128);        // (32, 64)

    // ---- fork: weight prep on side stream ----
    cudaEventRecord(evF, 0);
    cudaStreamWaitEvent(s2, evF, 0);
    split_tr_kernel<<<trDD, tb, 0, s2>>>(Wq, wqkv,               DD, DD);
    split_tr_kernel<<<trDD, tb, 0, s2>>>(Wk, wqkv + DD * DD,     DD, DD);
    split_tr_kernel<<<trDD, tb, 0, s2>>>(Wv, wqkv + 2 * DD * DD, DD, DD);
    pack_bias_kernel<<<3, DD, 0, s2>>>(bq, bk, bv, bqkv);
    cudaEventRecord(evQKVp, s2);
    split_tr_kernel<<<trDD, tb, 0, s2>>>(Wo, woh, DD, DD);
    cudaEventRecord(evO, s2);
    split_tr_kernel<<<trDF, tb, 0, s2>>>(W1, w1h, DD, FF);
    cudaEventRecord(ev1p, s2);
    split_tr_kernel<<<trFD, tb, 0, s2>>>(W2, w2h, FF, DD);
    cudaEventRecord(ev2p, s2);

    // ---- main stream ----
    convert_kernel<<<(MR * DD / 4 + 255) / 256, 256>>>(
        (const float4*)x, (__half2*)ah, MR * DD / 4);

    // fused QKV projection (fp16)
    cudaStreamWaitEvent(0, evQKVp, 0);
    gemm_mma<0, 3><<<gQKV, 256, G_SMEM>>>(
        ah, wqkv, bqkv, nullptr, qh, kh, vh, 3 * DD, DD);

    // attention -> fp16 ctx into ah
    attn_mma<<<dim3(8, 128), 256, A_SMEM>>>(qh, kh, vh, mask, ah);

    // output projection + residual LN (emits fp16 x1 into ah)
    cudaStreamWaitEvent(0, evO, 0);
    gemm_mma<0, 0><<<gD, 256, G_SMEM>>>(
        ah, woh, bo, t1, nullptr, nullptr, nullptr, DD, DD);
    residual_ln_kernel<1><<<MR, 256>>>(x, t1, g1, be1, x1, ah);

    // FFN1: relu(x1 @ W1 + bf1) -> fp16 hidden
    cudaStreamWaitEvent(0, ev1p, 0);
    gemm_mma<1, 2><<<gF, 256, G_SMEM>>>(
        ah, w1h, bf1, nullptr, hh, nullptr, nullptr, FF, DD);

    // FFN2 + residual LN
    cudaStreamWaitEvent(0, ev2p, 0);
    gemm_mma<0, 0><<<gD, 256, G_SMEM>>>(
        hh, w2h, bf2, t1, nullptr, nullptr, nullptr, DD, FF);
    residual_ln_kernel<0><<<MR, 256>>>(x1, t1, g2, be2, out, nullptr);
}

// round 12
// speedup vs baseline: 1.0806x; 1.0780x over previous
#include <cuda_runtime.h>
#include <cuda_fp16.h>
#include <math.h>
#include <stddef.h>
#include <stdint.h>

#define BB   8
#define SS   1024
#define DD   1024
#define HH   16
#define DHH  64
#define FF   4096
#define MR   (BB*SS)   // 8192 rows
#define HR   (MR/2)    // 4096 rows per chain

// ---------------- scratch (device globals) ----------------------------------
__device__ float g_t1 [MR*DD];
__device__ float g_x1 [MR*DD];

__device__ __half g_ah[MR*DD];            // activation fp16 (x / ctx / x1)
__device__ __half g_qh[MR*DD];
__device__ __half g_kh[MR*DD];
__device__ __half g_vh[MR*DD];
__device__ __half g_hh[(size_t)MR*FF];    // FFN hidden
// weights, [N,K] K-major
__device__ __half g_wqkv[3*DD*DD];        // packed Wq|Wk|Wv
__device__ float  g_bqkv[3*DD];           // packed bq|bk|bv
__device__ __half g_woh[DD*DD];
__device__ __half g_w1h[(size_t)DD*FF];
__device__ __half g_w2h[(size_t)FF*DD];

// ================= PTX helpers ==============================================
__device__ __forceinline__ uint32_t smem_u32(const void* p) {
    uint32_t a;
    asm("{ .reg .u64 t; cvta.to.shared.u64 t, %1; cvt.u32.u64 %0, t; }"
        : "=r"(a) : "l"(p));
    return a;
}
__device__ __forceinline__ uint32_t sw128(uint32_t o) {
    return o ^ ((o >> 3) & 0x70);
}
__device__ __forceinline__ void cp16(uint32_t s, const void* g) {
    asm volatile("cp.async.cg.shared.global [%0], [%1], 16;" :: "r"(s), "l"(g));
}
#define CP_COMMIT()  asm volatile("cp.async.commit_group;" ::: "memory")
#define CP_WAIT0()   asm volatile("cp.async.wait_group 0;" ::: "memory")
#define CP_WAIT1()   asm volatile("cp.async.wait_group 1;" ::: "memory")

__device__ __forceinline__ void ldsm4(uint32_t* r, uint32_t addr) {
    asm volatile("ldmatrix.sync.aligned.m8n8.x4.shared.b16 {%0,%1,%2,%3}, [%4];"
                 : "=r"(r[0]), "=r"(r[1]), "=r"(r[2]), "=r"(r[3]) : "r"(addr));
}
__device__ __forceinline__ void ldsm4t(uint32_t* r, uint32_t addr) {
    asm volatile("ldmatrix.sync.aligned.m8n8.x4.trans.shared.b16 {%0,%1,%2,%3}, [%4];"
                 : "=r"(r[0]), "=r"(r[1]), "=r"(r[2]), "=r"(r[3]) : "r"(addr));
}
__device__ __forceinline__ void mma16816(float* d, const uint32_t* a,
                                         const uint32_t* b) {
    asm("mma.sync.aligned.m16n8k16.row.col.f32.f16.f16.f32 "
        "{%0,%1,%2,%3}, {%4,%5,%6,%7}, {%8,%9}, {%0,%1,%2,%3};"
        : "+f"(d[0]), "+f"(d[1]), "+f"(d[2]), "+f"(d[3])
        : "r"(a[0]), "r"(a[1]), "r"(a[2]), "r"(a[3]),
          "r"(b[0]), "r"(b[1]));
}

// ================= mma.sync GEMM (fp16, 128x128, 2-stage — R9 proven) =======
// C[M,N] = A @ B^T (B stored [N,K] K-major) + bias.
// SPLITOUT: 0 fp32 C | 2 fp16 C | 3 QKV route (q/k/v fp16)
#define G_STAGE  32768            // A 16K | B 16K
#define G_SMEM   (2*G_STAGE)      // 64 KB -> 2 CTAs/SM

template<int ACT, int SPLITOUT>
__global__ __launch_bounds__(256, 2)
void gemm_mma(const __half* __restrict__ Ah,
              const __half* __restrict__ Bh,
              const float* __restrict__ bias,
              float* __restrict__ C,
              __half* __restrict__ Ch,
              __half* __restrict__ Kh_,
              __half* __restrict__ Vh_,
              int N, int K)
{
    extern __shared__ __align__(128) char smem[];
    const uint32_t sb = smem_u32(smem);
    const int tid  = threadIdx.x;
    const int wid  = tid >> 5;
    const int lane = tid & 31;
    const int wm   = wid & 3;
    const int wn   = wid >> 2;
    const int bc = blockIdx.x, br = blockIdx.y;

    const __half* Ah_t = Ah + (size_t)br * 128 * K;
    const __half* Bh_t = Bh + (size_t)bc * 128 * K;
    const int NT = K >> 6;

    auto load_stage = [&](int kt, int s) {
        const uint32_t base = sb + s * G_STAGE;
        const int koff = kt * 64;
        #pragma unroll
        for (int t = 0; t < 4; t++) {
            int idx = t * 256 + tid;
            int row = idx >> 3, ch = idx & 7;
            uint32_t so = sw128((uint32_t)(row * 128 + ch * 16));
            size_t go = (size_t)row * K + koff + ch * 8;
            cp16(base + so,         Ah_t + go);
            cp16(base + 16384 + so, Bh_t + go);
        }
        CP_COMMIT();
    };

    float acc[2][8][4];
    #pragma unroll
    for (int mi = 0; mi < 2; mi++)
        #pragma unroll
        for (int nj = 0; nj < 8; nj++)
            #pragma unroll
            for (int e = 0; e < 4; e++) acc[mi][nj][e] = 0.f;

    const int g = lane >> 3, r = lane & 7;

    load_stage(0, 0);

    for (int kt = 0; kt < NT; kt++) {
        const int buf = kt & 1;
        if (kt + 1 < NT) { load_stage(kt + 1, buf ^ 1); CP_WAIT1(); }
        else             { CP_WAIT0(); }
        __syncthreads();

        const uint32_t sA = sb + buf * G_STAGE;
        const uint32_t sB = sA + 16384;

        #pragma unroll
        for (int kc = 0; kc < 4; kc++) {
            uint32_t a_h[2][4];
            #pragma unroll
            for (int mi = 0; mi < 2; mi++) {
                int arow = wm * 32 + mi * 16 + r + ((g & 1) << 3);
                uint32_t off = sw128((uint32_t)(arow * 128 + kc * 32 +
                                                ((g >> 1) << 4)));
                ldsm4(a_h[mi], sA + off);
            }
            uint32_t b_h[4][4];
            #pragma unroll
            for (int np = 0; np < 4; np++) {
                int brow = wn * 64 + np * 16 + r + ((g >> 1) << 3);
                uint32_t off = sw128((uint32_t)(brow * 128 + kc * 32 +
                                                ((g & 1) << 4)));
                ldsm4(b_h[np], sB + off);
            }
            #pragma unroll
            for (int np = 0; np < 4; np++)
                #pragma unroll
                for (int t = 0; t < 2; t++)
                    #pragma unroll
                    for (int mi = 0; mi < 2; mi++)
                        mma16816(acc[mi][np * 2 + t], a_h[mi], &b_h[np][2 * t]);
        }
        __syncthreads();
    }

    const int rbase = br * 128 + wm * 32 + (lane >> 2);

    if (SPLITOUT == 3) {
        // QKV routing: bc 0-7 -> Q, 8-15 -> K, 16-23 -> V (all fp16)
        const int sel   = bc >> 3;
        const int cloc0 = (bc & 7) * 128 + wn * 64 + (lane & 3) * 2;
        const int cgl0  = bc * 128 + wn * 64 + (lane & 3) * 2;
        __half* dst = (sel == 0) ? Ch : (sel == 1) ? Kh_ : Vh_;
        #pragma unroll
        for (int mi = 0; mi < 2; mi++) {
            #pragma unroll
            for (int nj = 0; nj < 8; nj++) {
                float2 bv = *(const float2*)(bias + cgl0 + nj * 8);
                float v0 = acc[mi][nj][0] + bv.x;
                float v1 = acc[mi][nj][1] + bv.y;
                float v2 = acc[mi][nj][2] + bv.x;
                float v3 = acc[mi][nj][3] + bv.y;
                size_t i0 = (size_t)(rbase + mi * 16)     * DD + cloc0 + nj * 8;
                size_t i1 = (size_t)(rbase + mi * 16 + 8) * DD + cloc0 + nj * 8;
                *(__half2*)(dst + i0) = __floats2half2_rn(v0, v1);
                *(__half2*)(dst + i1) = __floats2half2_rn(v2, v3);
            }
        }
        return;
    }

    const int cbase = bc * 128 + wn * 64 + (lane & 3) * 2;
    #pragma unroll
    for (int mi = 0; mi < 2; mi++) {
        #pragma unroll
        for (int nj = 0; nj < 8; nj++) {
            int c = cbase + nj * 8;
            float2 bv = *(const float2*)(bias + c);
            float v0 = acc[mi][nj][0] + bv.x;
            float v1 = acc[mi][nj][1] + bv.y;
            float v2 = acc[mi][nj][2] + bv.x;
            float v3 = acc[mi][nj][3] + bv.y;
            if (ACT) {
                v0 = fmaxf(v0, 0.f); v1 = fmaxf(v1, 0.f);
                v2 = fmaxf(v2, 0.f); v3 = fmaxf(v3, 0.f);
            }
            size_t i0 = (size_t)(rbase + mi * 16)     * N + c;
            size_t i1 = (size_t)(rbase + mi * 16 + 8) * N + c;
            if (SPLITOUT == 2) {
                *(__half2*)(Ch + i0) = __floats2half2_rn(v0, v1);
                *(__half2*)(Ch + i1) = __floats2half2_rn(v2, v3);
            } else {
                float2 o0; o0.x = v0; o0.y = v1;
                float2 o1; o1.x = v2; o1.y = v3;
                *(float2*)(C + i0) = o0;
                *(float2*)(C + i1) = o1;
            }
        }
    }
}

// ================= Flash attention (pure fp16, fp32 softmax) ================
// bh_base: global (b*16+h) offset for this launch (chain splitting).
#define A_QH   0
#define A_ST   16384            // 2 stages x (Kh 8K | Vh 8K)
#define A_MK   49152            // 2 x 256 B mask
#define A_SMEM (49152 + 512)

__global__ __launch_bounds__(256, 2)
void attn_mma(const __half* __restrict__ qh,
              const __half* __restrict__ kh,
              const __half* __restrict__ vh,
              const float* __restrict__ mask,
              __half* __restrict__ ch,
              int bh_base)
{
    extern __shared__ __align__(128) char smem[];
    const uint32_t sb = smem_u32(smem);
    const int tid  = threadIdx.x;
    const int wid  = tid >> 5;
    const int lane = tid & 31;
    const int g    = lane >> 3, r8 = lane & 7;
    const int c2   = (lane & 3) * 2;

    const int qt = blockIdx.x;
    const int bh = bh_base + blockIdx.y;
    const int b  = bh >> 4;
    const int h  = bh & 15;

    const size_t qrow0 = (size_t)b * SS + (size_t)qt * 128;
    const __half* qhg = qh + qrow0 * DD + h * DHH;
    const __half* khg = kh + (size_t)b * SS * DD + h * DHH;
    const __half* vhg = vh + (size_t)b * SS * DD + h * DHH;
    const float* mkg = mask + (size_t)b * SS;

    auto load_kv = [&](int t, int s) {
        const uint32_t base = sb + A_ST + s * 16384;
        const size_t koff = (size_t)(t * 64) * DD;
        #pragma unroll
        for (int it = 0; it < 4; it++) {
            int idx = it * 256 + tid;
            int mat = idx >> 9;
            int sub = idx & 511;
            int row = sub >> 3, chk = sub & 7;
            uint32_t so = sw128((uint32_t)(row * 128 + chk * 16));
            size_t go = koff + (size_t)row * DD + chk * 8;
            cp16(base + mat * 8192 + so, (mat ? vhg : khg) + go);
        }
        if (tid < 16)
            cp16(sb + A_MK + s * 256 + tid * 16, mkg + t * 64 + tid * 4);
        CP_COMMIT();
    };

    #pragma unroll
    for (int it = 0; it < 4; it++) {
        int idx = it * 256 + tid;
        int row = idx >> 3, chk = idx & 7;
        uint32_t so = sw128((uint32_t)(row * 128 + chk * 16));
        cp16(sb + A_QH + so, qhg + (size_t)row * DD + chk * 8);
    }
    load_kv(0, 0);

    float mA = -INFINITY, mB = -INFINITY, lA = 0.f, lB = 0.f;
    float O[8][4];
    #pragma unroll
    for (int j = 0; j < 8; j++)
        #pragma unroll
        for (int e = 0; e < 4; e++) O[j][e] = 0.f;

    #pragma unroll 1
    for (int t = 0; t < 16; t++) {
        const int buf = t & 1;
        if (t + 1 < 16) { load_kv(t + 1, buf ^ 1); CP_WAIT1(); }
        else            { CP_WAIT0(); }
        __syncthreads();

        const uint32_t sKh = sb + A_ST + buf * 16384;
        const uint32_t sVh = sKh + 8192;
        const float* mkv = (const float*)(smem + A_MK + buf * 256);

        float s_[8][4];
        #pragma unroll
        for (int j = 0; j < 8; j++)
            #pragma unroll
            for (int e = 0; e < 4; e++) s_[j][e] = 0.f;

        #pragma unroll
        for (int kc = 0; kc < 4; kc++) {
            uint32_t aqh[4];
            {
                int arow = wid * 16 + r8 + ((g & 1) << 3);
                uint32_t off = sw128((uint32_t)(arow * 128 + kc * 32 +
                                                ((g >> 1) << 4)));
                ldsm4(aqh, sb + A_QH + off);
            }
            uint32_t bkh[4][4];
            #pragma unroll
            for (int np = 0; np < 4; np++) {
                int brow = np * 16 + r8 + ((g >> 1) << 3);
                uint32_t off = sw128((uint32_t)(brow * 128 + kc * 32 +
                                                ((g & 1) << 4)));
                ldsm4(bkh[np], sKh + off);
            }
            #pragma unroll
            for (int np = 0; np < 4; np++)
                #pragma unroll
                for (int t2 = 0; t2 < 2; t2++)
                    mma16816(s_[np * 2 + t2], aqh, &bkh[np][2 * t2]);
        }

        float tmA = -INFINITY, tmB = -INFINITY;
        #pragma unroll
        for (int j = 0; j < 8; j++) {
            float mk0 = mkv[j * 8 + c2]     * (-1e9f);
            float mk1 = mkv[j * 8 + c2 + 1] * (-1e9f);
            s_[j][0] = s_[j][0] * 0.125f + mk0;
            s_[j][1] = s_[j][1] * 0.125f + mk1;
            s_[j][2] = s_[j][2] * 0.125f + mk0;
            s_[j][3] = s_[j][3] * 0.125f + mk1;
            tmA = fmaxf(tmA, fmaxf(s_[j][0], s_[j][1]));
            tmB = fmaxf(tmB, fmaxf(s_[j][2], s_[j][3]));
        }
        tmA = fmaxf(tmA, __shfl_xor_sync(0xffffffffu, tmA, 1));
        tmA = fmaxf(tmA, __shfl_xor_sync(0xffffffffu, tmA, 2));
        tmB = fmaxf(tmB, __shfl_xor_sync(0xffffffffu, tmB, 1));
        tmB = fmaxf(tmB, __shfl_xor_sync(0xffffffffu, tmB, 2));

        const float nmA = fmaxf(mA, tmA), nmB = fmaxf(mB, tmB);
        const float fA = __expf(mA - nmA), fB = __expf(mB - nmB);

        float sumA = 0.f, sumB = 0.f;
        #pragma unroll
        for (int j = 0; j < 8; j++) {
            s_[j][0] = __expf(s_[j][0] - nmA);
            s_[j][1] = __expf(s_[j][1] - nmA);
            s_[j][2] = __expf(s_[j][2] - nmB);
            s_[j][3] = __expf(s_[j][3] - nmB);
            sumA += s_[j][0] + s_[j][1];
            sumB += s_[j][2] + s_[j][3];
        }
        sumA += __shfl_xor_sync(0xffffffffu, sumA, 1);
        sumA += __shfl_xor_sync(0xffffffffu, sumA, 2);
        sumB += __shfl_xor_sync(0xffffffffu, sumB, 1);
        sumB += __shfl_xor_sync(0xffffffffu, sumB, 2);
        lA = lA * fA + sumA;  mA = nmA;
        lB = lB * fB + sumB;  mB = nmB;

        #pragma unroll
        for (int j = 0; j < 8; j++) {
            O[j][0] *= fA; O[j][1] *= fA;
            O[j][2] *= fB; O[j][3] *= fB;
        }

        #pragma unroll
        for (int c = 0; c < 4; c++) {
            uint32_t ap_h[4];
            __half2 p0 = __floats2half2_rn(s_[2 * c][0],     s_[2 * c][1]);
            __half2 p1 = __floats2half2_rn(s_[2 * c][2],     s_[2 * c][3]);
            __half2 p2 = __floats2half2_rn(s_[2 * c + 1][0], s_[2 * c + 1][1]);
            __half2 p3 = __floats2half2_rn(s_[2 * c + 1][2], s_[2 * c + 1][3]);
            ap_h[0] = *(uint32_t*)&p0; ap_h[1] = *(uint32_t*)&p1;
            ap_h[2] = *(uint32_t*)&p2; ap_h[3] = *(uint32_t*)&p3;
            uint32_t bvh[4][4];
            #pragma unroll
            for (int np2 = 0; np2 < 4; np2++) {
                int vrow = c * 16 + r8 + ((g & 1) << 3);
                uint32_t off = sw128((uint32_t)(vrow * 128 + np2 * 32 +
                                                ((g >> 1) << 4)));
                ldsm4t(bvh[np2], sVh + off);
            }
            #pragma unroll
            for (int np2 = 0; np2 < 4; np2++)
                #pragma unroll
                for (int t2 = 0; t2 < 2; t2++)
                    mma16816(O[np2 * 2 + t2], ap_h, &bvh[np2][2 * t2]);
        }
        __syncthreads();
    }

    const float liA = 1.f / lA, liB = 1.f / lB;
    const size_t rowA = qrow0 + wid * 16 + (lane >> 2);
    const size_t rowB = rowA + 8;
    const int    colb = h * DHH + c2;
    #pragma unroll
    for (int j = 0; j < 8; j++) {
        *(__half2*)(ch + rowA * DD + colb + j * 8) =
            __floats2half2_rn(O[j][0] * liA, O[j][1] * liA);
        *(__half2*)(ch + rowB * DD + colb + j * 8) =
            __floats2half2_rn(O[j][2] * liB, O[j][3] * liB);
    }
}

// ================= fp32 -> fp16 convert =====================================
__global__ __launch_bounds__(256) void convert_kernel(
    const float4* __restrict__ in, __half2* __restrict__ oh, int n4)
{
    int i = blockIdx.x * 256 + threadIdx.x;
    if (i >= n4) return;
    float4 v = in[i];
    oh[2 * i]     = __floats2half2_rn(v.x, v.y);
    oh[2 * i + 1] = __floats2half2_rn(v.z, v.w);
}

// W[K,N] fp32 -> fp16 [N,K] (transpose)
__global__ __launch_bounds__(256) void split_tr_kernel(
    const float* __restrict__ W, __half* __restrict__ oh, int K, int N)
{
    __shared__ float t[32][33];
    const int bx = blockIdx.x, by = blockIdx.y;
    const int tx = threadIdx.x, ty = threadIdx.y;
    #pragma unroll
    for (int i = 0; i < 4; i++) {
        int rr = ty + i * 8;
        t[rr][tx] = W[(size_t)(by * 32 + rr) * N + bx * 32 + tx];
    }
    __syncthreads();
    #pragma unroll
    for (int i = 0; i < 4; i++) {
        int rr = ty + i * 8;
        size_t o = (size_t)(bx * 32 + rr) * K + by * 32 + tx;
        oh[o] = __float2half_rn(t[tx][rr]);
    }
}

__global__ void pack_bias_kernel(const float* __restrict__ b0,
                                 const float* __restrict__ b1,
                                 const float* __restrict__ b2,
                                 float* __restrict__ dst)
{
    const float* src = (blockIdx.x == 0) ? b0 : (blockIdx.x == 1) ? b1 : b2;
    dst[blockIdx.x * DD + threadIdx.x] = src[threadIdx.x];
}

// ================= residual + LayerNorm =====================================
template<int SPL>
__global__ __launch_bounds__(256) void residual_ln_kernel(
    const float* __restrict__ X, const float* __restrict__ Y,
    const float* __restrict__ g, const float* __restrict__ beta,
    float* __restrict__ out, __half* __restrict__ oh)
{
    __shared__ float ws[8], ws2[8];
    const int row = blockIdx.x;
    const int tid = threadIdx.x;
    const int lane = tid & 31, warp = tid >> 5;
    const float* px = X + (size_t)row * DD;
    const float* py = Y + (size_t)row * DD;

    float v[4];
    float s = 0.f, s2 = 0.f;
    #pragma unroll
    for (int l = 0; l < 4; l++) {
        int c = tid + l * 256;
        float t = px[c] + py[c];
        v[l] = t; s += t; s2 += t * t;
    }
    #pragma unroll
    for (int off = 16; off; off >>= 1) {
        s  += __shfl_xor_sync(0xffffffffu, s,  off);
        s2 += __shfl_xor_sync(0xffffffffu, s2, off);
    }
    if (lane == 0) { ws[warp] = s; ws2[warp] = s2; }
    __syncthreads();
    if (warp == 0) {
        s  = (lane < 8) ? ws[lane]  : 0.f;
        s2 = (lane < 8) ? ws2[lane] : 0.f;
        #pragma unroll
        for (int off = 4; off; off >>= 1) {
            s  += __shfl_xor_sync(0xffffffffu, s,  off);
            s2 += __shfl_xor_sync(0xffffffffu, s2, off);
        }
        if (lane == 0) { ws[0] = s; ws2[0] = s2; }
    }
    __syncthreads();
    float mu  = ws[0] * (1.f / 1024.f);
    float var = fmaxf(ws2[0] * (1.f / 1024.f) - mu * mu, 0.f);
    float rstd = rsqrtf(var + 1e-6f);
    #pragma unroll
    for (int l = 0; l < 4; l++) {
        int c = tid + l * 256;
        float rv = g[c] * (v[l] - mu) * rstd + beta[c];
        out[(size_t)row * DD + c] = rv;
        if (SPL) oh[(size_t)row * DD + c] = __float2half_rn(rv);
    }
}

// ================= launch ===================================================
extern "C" void kernel_launch(void* const* d_in, const int* in_sizes, int n_in,
                              void* d_out, int out_size)
{
    const float* x    = (const float*)d_in[0];
    const float* mask = (const float*)d_in[1];
    const float* Wq   = (const float*)d_in[2];
    const float* bq   = (const float*)d_in[3];
    const float* Wk   = (const float*)d_in[4];
    const float* bk   = (const float*)d_in[5];
    const float* Wv   = (const float*)d_in[6];
    const float* bv   = (const float*)d_in[7];
    const float* Wo   = (const float*)d_in[8];
    const float* bo   = (const float*)d_in[9];
    const float* g1   = (const float*)d_in[10];
    const float* be1  = (const float*)d_in[11];
    const float* W1   = (const float*)d_in[12];
    const float* bf1  = (const float*)d_in[13];
    const float* W2   = (const float*)d_in[14];
    const float* bf2  = (const float*)d_in[15];
    const float* g2   = (const float*)d_in[16];
    const float* be2  = (const float*)d_in[17];
    float* out = (float*)d_out;

    float *t1, *x1, *bqkv;
    __half *ah, *qh, *kh, *vh, *hh;
    __half *wqkv, *woh, *w1h, *w2h;
    cudaGetSymbolAddress((void**)&t1,   g_t1);
    cudaGetSymbolAddress((void**)&x1,   g_x1);
    cudaGetSymbolAddress((void**)&ah,   g_ah);
    cudaGetSymbolAddress((void**)&qh,   g_qh);
    cudaGetSymbolAddress((void**)&kh,   g_kh);
    cudaGetSymbolAddress((void**)&vh,   g_vh);
    cudaGetSymbolAddress((void**)&hh,   g_hh);
    cudaGetSymbolAddress((void**)&wqkv, g_wqkv);
    cudaGetSymbolAddress((void**)&bqkv, g_bqkv);
    cudaGetSymbolAddress((void**)&woh,  g_woh);
    cudaGetSymbolAddress((void**)&w1h,  g_w1h);
    cudaGetSymbolAddress((void**)&w2h,  g_w2h);

    cudaFuncSetAttribute(attn_mma,
                         cudaFuncAttributeMaxDynamicSharedMemorySize, A_SMEM);
    cudaFuncSetAttribute(gemm_mma<0, 3>,
                         cudaFuncAttributeMaxDynamicSharedMemorySize, G_SMEM);
    cudaFuncSetAttribute(gemm_mma<0, 0>,
                         cudaFuncAttributeMaxDynamicSharedMemorySize, G_SMEM);
    cudaFuncSetAttribute(gemm_mma<1, 2>,
                         cudaFuncAttributeMaxDynamicSharedMemorySize, G_SMEM);

    // streams: 0 = chain A (rows 0-4095), s2 = chain B (rows 4096-8191),
    //          s3 = weight prep
    static cudaStream_t s2 = nullptr, s3 = nullptr;
    static cudaEvent_t evF, evQKVp, evO, ev1p, ev2p, evB;
    if (!s2) {
        cudaStreamCreateWithFlags(&s2, cudaStreamNonBlocking);
        cudaStreamCreateWithFlags(&s3, cudaStreamNonBlocking);
        cudaEventCreateWithFlags(&evF,    cudaEventDisableTiming);
        cudaEventCreateWithFlags(&evQKVp, cudaEventDisableTiming);
        cudaEventCreateWithFlags(&evO,    cudaEventDisableTiming);
        cudaEventCreateWithFlags(&ev1p,   cudaEventDisableTiming);
        cudaEventCreateWithFlags(&ev2p,   cudaEventDisableTiming);
        cudaEventCreateWithFlags(&evB,    cudaEventDisableTiming);
    }

    const dim3 trDD(DD / 32, DD / 32);
    const dim3 trDF(FF / 32, DD / 32);
    const dim3 trFD(DD / 32, FF / 32);
    const dim3 tb(32, 8);
    // per-chain grids (half the rows)
    const dim3 gQKV(3 * DD / 128, HR / 128);  // (24, 32)
    const dim3 gD(DD / 128, HR / 128);        // (8, 32)
    const dim3 gF(FF / 128, HR / 128);        // (32, 32)
    const dim3 gAttn(8, 64);                  // 4 batches x 16 heads
    const int  cvt_n4 = HR * DD / 4;

    // ---- fork ----
    cudaEventRecord(evF, 0);
    cudaStreamWaitEvent(s2, evF, 0);
    cudaStreamWaitEvent(s3, evF, 0);

    // s3: weight prep
    split_tr_kernel<<<trDD, tb, 0, s3>>>(Wq, wqkv,               DD, DD);
    split_tr_kernel<<<trDD, tb, 0, s3>>>(Wk, wqkv + DD * DD,     DD, DD);
    split_tr_kernel<<<trDD, tb, 0, s3>>>(Wv, wqkv + 2 * DD * DD, DD, DD);
    pack_bias_kernel<<<3, DD, 0, s3>>>(bq, bk, bv, bqkv);
    cudaEventRecord(evQKVp, s3);
    split_tr_kernel<<<trDD, tb, 0, s3>>>(Wo, woh, DD, DD);
    cudaEventRecord(evO, s3);
    split_tr_kernel<<<trDF, tb, 0, s3>>>(W1, w1h, DD, FF);
    cudaEventRecord(ev1p, s3);
    split_tr_kernel<<<trFD, tb, 0, s3>>>(W2, w2h, FF, DD);
    cudaEventRecord(ev2p, s3);

    // ---- two independent batch-half chains ----
    for (int c = 0; c < 2; c++) {
        cudaStream_t st = (c == 0) ? (cudaStream_t)0 : s2;
        const size_t R  = (size_t)c * HR;          // row offset
        const size_t RD = R * DD;
        const size_t RF = R * FF;

        // x -> fp16
        convert_kernel<<<(cvt_n4 + 255) / 256, 256, 0, st>>>(
            (const float4*)(x + RD), (__half2*)(ah + RD), cvt_n4);

        // fused QKV projection
        cudaStreamWaitEvent(st, evQKVp, 0);
        gemm_mma<0, 3><<<gQKV, 256, G_SMEM, st>>>(
            ah + RD, wqkv, bqkv, nullptr, qh + RD, kh + RD, vh + RD,
            3 * DD, DD);

        // attention for this half's 4 batches (bh_base = c*64)
        attn_mma<<<gAttn, 256, A_SMEM, st>>>(qh, kh, vh, mask, ah, c * 64);

        // output projection + residual LN
        cudaStreamWaitEvent(st, evO, 0);
        gemm_mma<0, 0><<<gD, 256, G_SMEM, st>>>(
            ah + RD, woh, bo, t1 + RD, nullptr, nullptr, nullptr, DD, DD);
        residual_ln_kernel<1><<<HR, 256, 0, st>>>(
            x + RD, t1 + RD, g1, be1, x1 + RD, ah + RD);

        // FFN1
        cudaStreamWaitEvent(st, ev1p, 0);
        gemm_mma<1, 2><<<gF, 256, G_SMEM, st>>>(
            ah + RD, w1h, bf1, nullptr, hh + RF, nullptr, nullptr, FF, DD);

        // FFN2 + final residual LN
        cudaStreamWaitEvent(st, ev2p, 0);
        gemm_mma<0, 0><<<gD, 256, G_SMEM, st>>>(
            hh + RF, w2h, bf2, t1 + RD, nullptr, nullptr, nullptr, DD, FF);
        residual_ln_kernel<0><<<HR, 256, 0, st>>>(
            x1 + RD, t1 + RD, g2, be2, out + RD, nullptr);
    }

    // join: default stream waits for chain B
    cudaEventRecord(evB, s2);
    cudaStreamWaitEvent(0, evB, 0);
}

// round 14
// speedup vs baseline: 1.0807x; 1.0000x over previous
#include <cuda_runtime.h>
#include <cuda_fp16.h>
#include <math.h>
#include <stddef.h>
#include <stdint.h>

#define BB   8
#define SS   1024
#define DD   1024
#define HH   16
#define DHH  64
#define FF   4096
#define MR   (BB*SS)   // 8192 rows
#define HR   (MR/2)    // 4096 rows per chain

// ---------------- scratch (device globals) ----------------------------------
__device__ float  g_x1 [MR*DD];
__device__ __half g_t1h[MR*DD];           // fp16 GEMM outputs for LN

__device__ __half g_ah[MR*DD];            // activation fp16 (x / ctx / x1)
__device__ __half g_qh[MR*DD];
__device__ __half g_kh[MR*DD];
__device__ __half g_vh[MR*DD];
__device__ __half g_hh[(size_t)MR*FF];    // FFN hidden
// weights, [N,K] K-major
__device__ __half g_wqkv[3*DD*DD];        // packed Wq|Wk|Wv
__device__ float  g_bqkv[3*DD];           // packed bq|bk|bv
__device__ __half g_woh[DD*DD];
__device__ __half g_w1h[(size_t)DD*FF];
__device__ __half g_w2h[(size_t)FF*DD];

// ================= PTX helpers ==============================================
__device__ __forceinline__ uint32_t smem_u32(const void* p) {
    uint32_t a;
    asm("{ .reg .u64 t; cvta.to.shared.u64 t, %1; cvt.u32.u64 %0, t; }"
        : "=r"(a) : "l"(p));
    return a;
}
__device__ __forceinline__ uint32_t sw128(uint32_t o) {
    return o ^ ((o >> 3) & 0x70);
}
__device__ __forceinline__ void cp16(uint32_t s, const void* g) {
    asm volatile("cp.async.cg.shared.global [%0], [%1], 16;" :: "r"(s), "l"(g));
}
#define CP_COMMIT()  asm volatile("cp.async.commit_group;" ::: "memory")
#define CP_WAIT0()   asm volatile("cp.async.wait_group 0;" ::: "memory")
#define CP_WAIT1()   asm volatile("cp.async.wait_group 1;" ::: "memory")

__device__ __forceinline__ void ldsm4(uint32_t* r, uint32_t addr) {
    asm volatile("ldmatrix.sync.aligned.m8n8.x4.shared.b16 {%0,%1,%2,%3}, [%4];"
                 : "=r"(r[0]), "=r"(r[1]), "=r"(r[2]), "=r"(r[3]) : "r"(addr));
}
__device__ __forceinline__ void ldsm4t(uint32_t* r, uint32_t addr) {
    asm volatile("ldmatrix.sync.aligned.m8n8.x4.trans.shared.b16 {%0,%1,%2,%3}, [%4];"
                 : "=r"(r[0]), "=r"(r[1]), "=r"(r[2]), "=r"(r[3]) : "r"(addr));
}
__device__ __forceinline__ void mma16816(float* d, const uint32_t* a,
                                         const uint32_t* b) {
    asm("mma.sync.aligned.m16n8k16.row.col.f32.f16.f16.f32 "
        "{%0,%1,%2,%3}, {%4,%5,%6,%7}, {%8,%9}, {%0,%1,%2,%3};"
        : "+f"(d[0]), "+f"(d[1]), "+f"(d[2]), "+f"(d[3])
        : "r"(a[0]), "r"(a[1]), "r"(a[2]), "r"(a[3]),
          "r"(b[0]), "r"(b[1]));
}

// ================= mma.sync GEMM (fp16, 128x128, 2-stage) ===================
// C[M,N] = A @ B^T (B stored [N,K] K-major) + bias.
// SPLITOUT: 2 fp16 C | 3 QKV route (q/k/v fp16)
#define G_STAGE  32768            // A 16K | B 16K
#define G_SMEM   (2*G_STAGE)      // 64 KB -> 2 CTAs/SM

template<int ACT, int SPLITOUT>
__global__ __launch_bounds__(256, 2)
void gemm_mma(const __half* __restrict__ Ah,
              const __half* __restrict__ Bh,
              const float* __restrict__ bias,
              __half* __restrict__ Ch,
              __half* __restrict__ Kh_,
              __half* __restrict__ Vh_,
              int N, int K)
{
    extern __shared__ __align__(128) char smem[];
    const uint32_t sb = smem_u32(smem);
    const int tid  = threadIdx.x;
    const int wid  = tid >> 5;
    const int lane = tid & 31;
    const int wm   = wid & 3;
    const int wn   = wid >> 2;
    const int bc = blockIdx.x, br = blockIdx.y;

    const __half* Ah_t = Ah + (size_t)br * 128 * K;
    const __half* Bh_t = Bh + (size_t)bc * 128 * K;
    const int NT = K >> 6;

    auto load_stage = [&](int kt, int s) {
        const uint32_t base = sb + s * G_STAGE;
        const int koff = kt * 64;
        #pragma unroll
        for (int t = 0; t < 4; t++) {
            int idx = t * 256 + tid;
            int row = idx >> 3, ch = idx & 7;
            uint32_t so = sw128((uint32_t)(row * 128 + ch * 16));
            size_t go = (size_t)row * K + koff + ch * 8;
            cp16(base + so,         Ah_t + go);
            cp16(base + 16384 + so, Bh_t + go);
        }
        CP_COMMIT();
    };

    float acc[2][8][4];
    #pragma unroll
    for (int mi = 0; mi < 2; mi++)
        #pragma unroll
        for (int nj = 0; nj < 8; nj++)
            #pragma unroll
            for (int e = 0; e < 4; e++) acc[mi][nj][e] = 0.f;

    const int g = lane >> 3, r = lane & 7;

    load_stage(0, 0);

    for (int kt = 0; kt < NT; kt++) {
        const int buf = kt & 1;
        if (kt + 1 < NT) { load_stage(kt + 1, buf ^ 1); CP_WAIT1(); }
        else             { CP_WAIT0(); }
        __syncthreads();

        const uint32_t sA = sb + buf * G_STAGE;
        const uint32_t sB = sA + 16384;

        #pragma unroll
        for (int kc = 0; kc < 4; kc++) {
            uint32_t a_h[2][4];
            #pragma unroll
            for (int mi = 0; mi < 2; mi++) {
                int arow = wm * 32 + mi * 16 + r + ((g & 1) << 3);
                uint32_t off = sw128((uint32_t)(arow * 128 + kc * 32 +
                                                ((g >> 1) << 4)));
                ldsm4(a_h[mi], sA + off);
            }
            uint32_t b_h[4][4];
            #pragma unroll
            for (int np = 0; np < 4; np++) {
                int brow = wn * 64 + np * 16 + r + ((g >> 1) << 3);
                uint32_t off = sw128((uint32_t)(brow * 128 + kc * 32 +
                                                ((g & 1) << 4)));
                ldsm4(b_h[np], sB + off);
            }
            #pragma unroll
            for (int np = 0; np < 4; np++)
                #pragma unroll
                for (int t = 0; t < 2; t++)
                    #pragma unroll
                    for (int mi = 0; mi < 2; mi++)
                        mma16816(acc[mi][np * 2 + t], a_h[mi], &b_h[np][2 * t]);
        }
        __syncthreads();
    }

    const int rbase = br * 128 + wm * 32 + (lane >> 2);

    if (SPLITOUT == 3) {
        // QKV routing: bc 0-7 -> Q, 8-15 -> K, 16-23 -> V (all fp16)
        const int sel   = bc >> 3;
        const int cloc0 = (bc & 7) * 128 + wn * 64 + (lane & 3) * 2;
        const int cgl0  = bc * 128 + wn * 64 + (lane & 3) * 2;
        __half* dst = (sel == 0) ? Ch : (sel == 1) ? Kh_ : Vh_;
        #pragma unroll
        for (int mi = 0; mi < 2; mi++) {
            #pragma unroll
            for (int nj = 0; nj < 8; nj++) {
                float2 bv = *(const float2*)(bias + cgl0 + nj * 8);
                float v0 = acc[mi][nj][0] + bv.x;
                float v1 = acc[mi][nj][1] + bv.y;
                float v2 = acc[mi][nj][2] + bv.x;
                float v3 = acc[mi][nj][3] + bv.y;
                size_t i0 = (size_t)(rbase + mi * 16)     * DD + cloc0 + nj * 8;
                size_t i1 = (size_t)(rbase + mi * 16 + 8) * DD + cloc0 + nj * 8;
                *(__half2*)(dst + i0) = __floats2half2_rn(v0, v1);
                *(__half2*)(dst + i1) = __floats2half2_rn(v2, v3);
            }
        }
        return;
    }

    const int cbase = bc * 128 + wn * 64 + (lane & 3) * 2;
    #pragma unroll
    for (int mi = 0; mi < 2; mi++) {
        #pragma unroll
        for (int nj = 0; nj < 8; nj++) {
            int c = cbase + nj * 8;
            float2 bv = *(const float2*)(bias + c);
            float v0 = acc[mi][nj][0] + bv.x;
            float v1 = acc[mi][nj][1] + bv.y;
            float v2 = acc[mi][nj][2] + bv.x;
            float v3 = acc[mi][nj][3] + bv.y;
            if (ACT) {
                v0 = fmaxf(v0, 0.f); v1 = fmaxf(v1, 0.f);
                v2 = fmaxf(v2, 0.f); v3 = fmaxf(v3, 0.f);
            }
            size_t i0 = (size_t)(rbase + mi * 16)     * N + c;
            size_t i1 = (size_t)(rbase + mi * 16 + 8) * N + c;
            *(__half2*)(Ch + i0) = __floats2half2_rn(v0, v1);
            *(__half2*)(Ch + i1) = __floats2half2_rn(v2, v3);
        }
    }
}

// ================= Flash attention (pure fp16, fp32 softmax) ================
#define A_QH   0
#define A_ST   16384            // 2 stages x (Kh 8K | Vh 8K)
#define A_MK   49152            // 2 x 256 B mask
#define A_SMEM (49152 + 512)

__global__ __launch_bounds__(256, 2)
void attn_mma(const __half* __restrict__ qh,
              const __half* __restrict__ kh,
              const __half* __restrict__ vh,
              const float* __restrict__ mask,
              __half* __restrict__ ch,
              int bh_base)
{
    extern __shared__ __align__(128) char smem[];
    const uint32_t sb = smem_u32(smem);
    const int tid  = threadIdx.x;
    const int wid  = tid >> 5;
    const int lane = tid & 31;
    const int g    = lane >> 3, r8 = lane & 7;
    const int c2   = (lane & 3) * 2;

    const int qt = blockIdx.x;
    const int bh = bh_base + blockIdx.y;
    const int b  = bh >> 4;
    const int h  = bh & 15;

    const size_t qrow0 = (size_t)b * SS + (size_t)qt * 128;
    const __half* qhg = qh + qrow0 * DD + h * DHH;
    const __half* khg = kh + (size_t)b * SS * DD + h * DHH;
    const __half* vhg = vh + (size_t)b * SS * DD + h * DHH;
    const float* mkg = mask + (size_t)b * SS;

    auto load_kv = [&](int t, int s) {
        const uint32_t base = sb + A_ST + s * 16384;
        const size_t koff = (size_t)(t * 64) * DD;
        #pragma unroll
        for (int it = 0; it < 4; it++) {
            int idx = it * 256 + tid;
            int mat = idx >> 9;
            int sub = idx & 511;
            int row = sub >> 3, chk = sub & 7;
            uint32_t so = sw128((uint32_t)(row * 128 + chk * 16));
            size_t go = koff + (size_t)row * DD + chk * 8;
            cp16(base + mat * 8192 + so, (mat ? vhg : khg) + go);
        }
        if (tid < 16)
            cp16(sb + A_MK + s * 256 + tid * 16, mkg + t * 64 + tid * 4);
        CP_COMMIT();
    };

    #pragma unroll
    for (int it = 0; it < 4; it++) {
        int idx = it * 256 + tid;
        int row = idx >> 3, chk = idx & 7;
        uint32_t so = sw128((uint32_t)(row * 128 + chk * 16));
        cp16(sb + A_QH + so, qhg + (size_t)row * DD + chk * 8);
    }
    load_kv(0, 0);

    float mA = -INFINITY, mB = -INFINITY, lA = 0.f, lB = 0.f;
    float O[8][4];
    #pragma unroll
    for (int j = 0; j < 8; j++)
        #pragma unroll
        for (int e = 0; e < 4; e++) O[j][e] = 0.f;

    #pragma unroll 1
    for (int t = 0; t < 16; t++) {
        const int buf = t & 1;
        if (t + 1 < 16) { load_kv(t + 1, buf ^ 1); CP_WAIT1(); }
        else            { CP_WAIT0(); }
        __syncthreads();

        const uint32_t sKh = sb + A_ST + buf * 16384;
        const uint32_t sVh = sKh + 8192;
        const float* mkv = (const float*)(smem + A_MK + buf * 256);

        float s_[8][4];
        #pragma unroll
        for (int j = 0; j < 8; j++)
            #pragma unroll
            for (int e = 0; e < 4; e++) s_[j][e] = 0.f;

        #pragma unroll
        for (int kc = 0; kc < 4; kc++) {
            uint32_t aqh[4];
            {
                int arow = wid * 16 + r8 + ((g & 1) << 3);
                uint32_t off = sw128((uint32_t)(arow * 128 + kc * 32 +
                                                ((g >> 1) << 4)));
                ldsm4(aqh, sb + A_QH + off);
            }
            uint32_t bkh[4][4];
            #pragma unroll
            for (int np = 0; np < 4; np++) {
                int brow = np * 16 + r8 + ((g >> 1) << 3);
                uint32_t off = sw128((uint32_t)(brow * 128 + kc * 32 +
                                                ((g & 1) << 4)));
                ldsm4(bkh[np], sKh + off);
            }
            #pragma unroll
            for (int np = 0; np < 4; np++)
                #pragma unroll
                for (int t2 = 0; t2 < 2; t2++)
                    mma16816(s_[np * 2 + t2], aqh, &bkh[np][2 * t2]);
        }

        float tmA = -INFINITY, tmB = -INFINITY;
        #pragma unroll
        for (int j = 0; j < 8; j++) {
            float mk0 = mkv[j * 8 + c2]     * (-1e9f);
            float mk1 = mkv[j * 8 + c2 + 1] * (-1e9f);
            s_[j][0] = s_[j][0] * 0.125f + mk0;
            s_[j][1] = s_[j][1] * 0.125f + mk1;
            s_[j][2] = s_[j][2] * 0.125f + mk0;
            s_[j][3] = s_[j][3] * 0.125f + mk1;
            tmA = fmaxf(tmA, fmaxf(s_[j][0], s_[j][1]));
            tmB = fmaxf(tmB, fmaxf(s_[j][2], s_[j][3]));
        }
        tmA = fmaxf(tmA, __shfl_xor_sync(0xffffffffu, tmA, 1));
        tmA = fmaxf(tmA, __shfl_xor_sync(0xffffffffu, tmA, 2));
        tmB = fmaxf(tmB, __shfl_xor_sync(0xffffffffu, tmB, 1));
        tmB = fmaxf(tmB, __shfl_xor_sync(0xffffffffu, tmB, 2));

        const float nmA = fmaxf(mA, tmA), nmB = fmaxf(mB, tmB);
        const float fA = __expf(mA - nmA), fB = __expf(mB - nmB);

        float sumA = 0.f, sumB = 0.f;
        #pragma unroll
        for (int j = 0; j < 8; j++) {
            s_[j][0] = __expf(s_[j][0] - nmA);
            s_[j][1] = __expf(s_[j][1] - nmA);
            s_[j][2] = __expf(s_[j][2] - nmB);
            s_[j][3] = __expf(s_[j][3] - nmB);
            sumA += s_[j][0] + s_[j][1];
            sumB += s_[j][2] + s_[j][3];
        }
        sumA += __shfl_xor_sync(0xffffffffu, sumA, 1);
        sumA += __shfl_xor_sync(0xffffffffu, sumA, 2);
        sumB += __shfl_xor_sync(0xffffffffu, sumB, 1);
        sumB += __shfl_xor_sync(0xffffffffu, sumB, 2);
        lA = lA * fA + sumA;  mA = nmA;
        lB = lB * fB + sumB;  mB = nmB;

        #pragma unroll
        for (int j = 0; j < 8; j++) {
            O[j][0] *= fA; O[j][1] *= fA;
            O[j][2] *= fB; O[j][3] *= fB;
        }

        #pragma unroll
        for (int c = 0; c < 4; c++) {
            uint32_t ap_h[4];
            __half2 p0 = __floats2half2_rn(s_[2 * c][0],     s_[2 * c][1]);
            __half2 p1 = __floats2half2_rn(s_[2 * c][2],     s_[2 * c][3]);
            __half2 p2 = __floats2half2_rn(s_[2 * c + 1][0], s_[2 * c + 1][1]);
            __half2 p3 = __floats2half2_rn(s_[2 * c + 1][2], s_[2 * c + 1][3]);
            ap_h[0] = *(uint32_t*)&p0; ap_h[1] = *(uint32_t*)&p1;
            ap_h[2] = *(uint32_t*)&p2; ap_h[3] = *(uint32_t*)&p3;
            uint32_t bvh[4][4];
            #pragma unroll
            for (int np2 = 0; np2 < 4; np2++) {
                int vrow = c * 16 + r8 + ((g & 1) << 3);
                uint32_t off = sw128((uint32_t)(vrow * 128 + np2 * 32 +
                                                ((g >> 1) << 4)));
                ldsm4t(bvh[np2], sVh + off);
            }
            #pragma unroll
            for (int np2 = 0; np2 < 4; np2++)
                #pragma unroll
                for (int t2 = 0; t2 < 2; t2++)
                    mma16816(O[np2 * 2 + t2], ap_h, &bvh[np2][2 * t2]);
        }
        __syncthreads();
    }

    const float liA = 1.f / lA, liB = 1.f / lB;
    const size_t rowA = qrow0 + wid * 16 + (lane >> 2);
    const size_t rowB = rowA + 8;
    const int    colb = h * DHH + c2;
    #pragma unroll
    for (int j = 0; j < 8; j++) {
        *(__half2*)(ch + rowA * DD + colb + j * 8) =
            __floats2half2_rn(O[j][0] * liA, O[j][1] * liA);
        *(__half2*)(ch + rowB * DD + colb + j * 8) =
            __floats2half2_rn(O[j][2] * liB, O[j][3] * liB);
    }
}

// ================= fp32 -> fp16 convert =====================================
__global__ __launch_bounds__(256) void convert_kernel(
    const float4* __restrict__ in, __half2* __restrict__ oh, int n4)
{
    int i = blockIdx.x * 256 + threadIdx.x;
    if (i >= n4) return;
    float4 v = in[i];
    oh[2 * i]     = __floats2half2_rn(v.x, v.y);
    oh[2 * i + 1] = __floats2half2_rn(v.z, v.w);
}

// W[K,N] fp32 -> fp16 [N,K] (transpose)
__global__ __launch_bounds__(256) void split_tr_kernel(
    const float* __restrict__ W, __half* __restrict__ oh, int K, int N)
{
    __shared__ float t[32][33];
    const int bx = blockIdx.x, by = blockIdx.y;
    const int tx = threadIdx.x, ty = threadIdx.y;
    #pragma unroll
    for (int i = 0; i < 4; i++) {
        int rr = ty + i * 8;
        t[rr][tx] = W[(size_t)(by * 32 + rr) * N + bx * 32 + tx];
    }
    __syncthreads();
    #pragma unroll
    for (int i = 0; i < 4; i++) {
        int rr = ty + i * 8;
        size_t o = (size_t)(bx * 32 + rr) * K + by * 32 + tx;
        oh[o] = __float2half_rn(t[tx][rr]);
    }
}

__global__ void pack_bias_kernel(const float* __restrict__ b0,
                                 const float* __restrict__ b1,
                                 const float* __restrict__ b2,
                                 float* __restrict__ dst)
{
    const float* src = (blockIdx.x == 0) ? b0 : (blockIdx.x == 1) ? b1 : b2;
    dst[blockIdx.x * DD + threadIdx.x] = src[threadIdx.x];
}

// ================= residual + LayerNorm (Y in fp16) =========================
template<int SPL>
__global__ __launch_bounds__(256) void residual_ln_kernel(
    const float* __restrict__ X, const __half* __restrict__ Y,
    const float* __restrict__ g, const float* __restrict__ beta,
    float* __restrict__ out, __half* __restrict__ oh)
{
    __shared__ float ws[8], ws2[8];
    const int row = blockIdx.x;
    const int tid = threadIdx.x;
    const int lane = tid & 31, warp = tid >> 5;
    const float*  px = X + (size_t)row * DD;
    const __half* py = Y + (size_t)row * DD;

    float v[4];
    float s = 0.f, s2 = 0.f;
    #pragma unroll
    for (int l = 0; l < 4; l++) {
        int c = tid + l * 256;
        float t = px[c] + __half2float(py[c]);
        v[l] = t; s += t; s2 += t * t;
    }
    #pragma unroll
    for (int off = 16; off; off >>= 1) {
        s  += __shfl_xor_sync(0xffffffffu, s,  off);
        s2 += __shfl_xor_sync(0xffffffffu, s2, off);
    }
    if (lane == 0) { ws[warp] = s; ws2[warp] = s2; }
    __syncthreads();
    if (warp == 0) {
        s  = (lane < 8) ? ws[lane]  : 0.f;
        s2 = (lane < 8) ? ws2[lane] : 0.f;
        #pragma unroll
        for (int off = 4; off; off >>= 1) {
            s  += __shfl_xor_sync(0xffffffffu, s,  off);
            s2 += __shfl_xor_sync(0xffffffffu, s2, off);
        }
        if (lane == 0) { ws[0] = s; ws2[0] = s2; }
    }
    __syncthreads();
    float mu  = ws[0] * (1.f / 1024.f);
    float var = fmaxf(ws2[0] * (1.f / 1024.f) - mu * mu, 0.f);
    float rstd = rsqrtf(var + 1e-6f);
    #pragma unroll
    for (int l = 0; l < 4; l++) {
        int c = tid + l * 256;
        float rv = g[c] * (v[l] - mu) * rstd + beta[c];
        out[(size_t)row * DD + c] = rv;
        if (SPL) oh[(size_t)row * DD + c] = __float2half_rn(rv);
    }
}

// ================= launch ===================================================
extern "C" void kernel_launch(void* const* d_in, const int* in_sizes, int n_in,
                              void* d_out, int out_size)
{
    const float* x    = (const float*)d_in[0];
    const float* mask = (const float*)d_in[1];
    const float* Wq   = (const float*)d_in[2];
    const float* bq   = (const float*)d_in[3];
    const float* Wk   = (const float*)d_in[4];
    const float* bk   = (const float*)d_in[5];
    const float* Wv   = (const float*)d_in[6];
    const float* bv   = (const float*)d_in[7];
    const float* Wo   = (const float*)d_in[8];
    const float* bo   = (const float*)d_in[9];
    const float* g1   = (const float*)d_in[10];
    const float* be1  = (const float*)d_in[11];
    const float* W1   = (const float*)d_in[12];
    const float* bf1  = (const float*)d_in[13];
    const float* W2   = (const float*)d_in[14];
    const float* bf2  = (const float*)d_in[15];
    const float* g2   = (const float*)d_in[16];
    const float* be2  = (const float*)d_in[17];
    float* out = (float*)d_out;

    float *x1, *bqkv;
    __half *ah, *qh, *kh, *vh, *hh, *t1h;
    __half *wqkv, *woh, *w1h, *w2h;
    cudaGetSymbolAddress((void**)&x1,   g_x1);
    cudaGetSymbolAddress((void**)&t1h,  g_t1h);
    cudaGetSymbolAddress((void**)&ah,   g_ah);
    cudaGetSymbolAddress((void**)&qh,   g_qh);
    cudaGetSymbolAddress((void**)&kh,   g_kh);
    cudaGetSymbolAddress((void**)&vh,   g_vh);
    cudaGetSymbolAddress((void**)&hh,   g_hh);
    cudaGetSymbolAddress((void**)&wqkv, g_wqkv);
    cudaGetSymbolAddress((void**)&bqkv, g_bqkv);
    cudaGetSymbolAddress((void**)&woh,  g_woh);
    cudaGetSymbolAddress((void**)&w1h,  g_w1h);
    cudaGetSymbolAddress((void**)&w2h,  g_w2h);

    cudaFuncSetAttribute(attn_mma,
                         cudaFuncAttributeMaxDynamicSharedMemorySize, A_SMEM);
    cudaFuncSetAttribute(gemm_mma<0, 3>,
                         cudaFuncAttributeMaxDynamicSharedMemorySize, G_SMEM);
    cudaFuncSetAttribute(gemm_mma<0, 2>,
                         cudaFuncAttributeMaxDynamicSharedMemorySize, G_SMEM);
    cudaFuncSetAttribute(gemm_mma<1, 2>,
                         cudaFuncAttributeMaxDynamicSharedMemorySize, G_SMEM);

    // streams: 0 = chain A, s2 = chain B, s3 = weight prep  (R12 topology)
    static cudaStream_t s2 = nullptr, s3 = nullptr;
    static cudaEvent_t evF, evQKVp, evO, ev1p, ev2p, evB;
    if (!s2) {
        cudaStreamCreateWithFlags(&s2, cudaStreamNonBlocking);
        cudaStreamCreateWithFlags(&s3, cudaStreamNonBlocking);
        cudaEventCreateWithFlags(&evF,    cudaEventDisableTiming);
        cudaEventCreateWithFlags(&evQKVp, cudaEventDisableTiming);
        cudaEventCreateWithFlags(&evO,    cudaEventDisableTiming);
        cudaEventCreateWithFlags(&ev1p,   cudaEventDisableTiming);
        cudaEventCreateWithFlags(&ev2p,   cudaEventDisableTiming);
        cudaEventCreateWithFlags(&evB,    cudaEventDisableTiming);
    }

    const dim3 trDD(DD / 32, DD / 32);
    const dim3 trDF(FF / 32, DD / 32);
    const dim3 trFD(DD / 32, FF / 32);
    const dim3 tb(32, 8);
    // per-chain grids (HR = 4096 rows each)
    const dim3 gQKV(3 * DD / 128, HR / 128);  // (24, 32)
    const dim3 gD(DD / 128, HR / 128);        // (8, 32)
    const dim3 gF(FF / 128, HR / 128);        // (32, 32)
    const dim3 gAttn(8, 64);                  // 4 batches x 16 heads
    const int  cvt_n4 = HR * DD / 4;

    // ---- fork ----
    cudaEventRecord(evF, 0);
    cudaStreamWaitEvent(s2, evF, 0);
    cudaStreamWaitEvent(s3, evF, 0);

    // s3: weight prep
    split_tr_kernel<<<trDD, tb, 0, s3>>>(Wq, wqkv,               DD, DD);
    split_tr_kernel<<<trDD, tb, 0, s3>>>(Wk, wqkv + DD * DD,     DD, DD);
    split_tr_kernel<<<trDD, tb, 0, s3>>>(Wv, wqkv + 2 * DD * DD, DD, DD);
    pack_bias_kernel<<<3, DD, 0, s3>>>(bq, bk, bv, bqkv);
    cudaEventRecord(evQKVp, s3);
    split_tr_kernel<<<trDD, tb, 0, s3>>>(Wo, woh, DD, DD);
    cudaEventRecord(evO, s3);
    split_tr_kernel<<<trDF, tb, 0, s3>>>(W1, w1h, DD, FF);
    cudaEventRecord(ev1p, s3);
    split_tr_kernel<<<trFD, tb, 0, s3>>>(W2, w2h, FF, DD);
    cudaEventRecord(ev2p, s3);

    // ---- two independent batch-half chains ----
    for (int c = 0; c < 2; c++) {
        cudaStream_t st = (c == 0) ? (cudaStream_t)0 : s2;
        const size_t R  = (size_t)c * HR;          // row offset
        const size_t RD = R * DD;
        const size_t RF = R * FF;

        // x -> fp16
        convert_kernel<<<(cvt_n4 + 255) / 256, 256, 0, st>>>(
            (const float4*)(x + RD), (__half2*)(ah + RD), cvt_n4);

        // fused QKV projection
        cudaStreamWaitEvent(st, evQKVp, 0);
        gemm_mma<0, 3><<<gQKV, 256, G_SMEM, st>>>(
            ah + RD, wqkv, bqkv, qh + RD, kh + RD, vh + RD, 3 * DD, DD);

        // attention for this half's 4 batches (bh_base = c*64)
        attn_mma<<<gAttn, 256, A_SMEM, st>>>(qh, kh, vh, mask, ah, c * 64);

        // output projection (fp16 t1) + residual LN
        cudaStreamWaitEvent(st, evO, 0);
        gemm_mma<0, 2><<<gD, 256, G_SMEM, st>>>(
            ah + RD, woh, bo, t1h + RD, nullptr, nullptr, DD, DD);
        residual_ln_kernel<1><<<HR, 256, 0, st>>>(
            x + RD, t1h + RD, g1, be1, x1 + RD, ah + RD);

        // FFN1
        cudaStreamWaitEvent(st, ev1p, 0);
        gemm_mma<1, 2><<<gF, 256, G_SMEM, st>>>(
            ah + RD, w1h, bf1, hh + RF, nullptr, nullptr, FF, DD);

        // FFN2 (fp16 t1) + final residual LN
        cudaStreamWaitEvent(st, ev2p, 0);
        gemm_mma<0, 2><<<gD, 256, G_SMEM, st>>>(
            hh + RF, w2h, bf2, t1h + RD, nullptr, nullptr, DD, FF);
        residual_ln_kernel<0><<<HR, 256, 0, st>>>(
            x1 + RD, t1h + RD, g2, be2, out + RD, nullptr);
    }

    // join: default stream waits for chain B
    cudaEventRecord(evB, s2);
    cudaStreamWaitEvent(0, evB, 0);
}

// round 15
// speedup vs baseline: 1.0901x; 1.0087x over previous
#include <cuda_runtime.h>
#include <cuda_fp16.h>
#include <math.h>
#include <stddef.h>
#include <stdint.h>

#define BB   8
#define SS   1024
#define DD   1024
#define HH   16
#define DHH  64
#define FF   4096
#define MR   (BB*SS)   // 8192 rows
#define HR   (MR/2)    // 4096 rows per chain

// ---------------- scratch (device globals) ----------------------------------
__device__ float  g_x1 [MR*DD];
__device__ __half g_t1h[MR*DD];           // fp16 GEMM outputs for LN

__device__ __half g_ah[MR*DD];            // activation fp16 (x / ctx / x1)
__device__ __half g_qh[MR*DD];
__device__ __half g_kh[MR*DD];
__device__ __half g_vh[MR*DD];
__device__ __half g_hh[(size_t)MR*FF];    // FFN hidden
// weights, [N,K] K-major
__device__ __half g_wqkv[3*DD*DD];        // packed Wq|Wk|Wv
__device__ __half g_woh[DD*DD];
__device__ __half g_w1h[(size_t)DD*FF];
__device__ __half g_w2h[(size_t)FF*DD];

// ================= PTX helpers ==============================================
__device__ __forceinline__ uint32_t smem_u32(const void* p) {
    uint32_t a;
    asm("{ .reg .u64 t; cvta.to.shared.u64 t, %1; cvt.u32.u64 %0, t; }"
        : "=r"(a) : "l"(p));
    return a;
}
__device__ __forceinline__ uint32_t sw128(uint32_t o) {
    return o ^ ((o >> 3) & 0x70);
}
__device__ __forceinline__ void cp16(uint32_t s, const void* g) {
    asm volatile("cp.async.cg.shared.global [%0], [%1], 16;" :: "r"(s), "l"(g));
}
#define CP_COMMIT()  asm volatile("cp.async.commit_group;" ::: "memory")
#define CP_WAIT0()   asm volatile("cp.async.wait_group 0;" ::: "memory")
#define CP_WAIT1()   asm volatile("cp.async.wait_group 1;" ::: "memory")

__device__ __forceinline__ void ldsm4(uint32_t* r, uint32_t addr) {
    asm volatile("ldmatrix.sync.aligned.m8n8.x4.shared.b16 {%0,%1,%2,%3}, [%4];"
                 : "=r"(r[0]), "=r"(r[1]), "=r"(r[2]), "=r"(r[3]) : "r"(addr));
}
__device__ __forceinline__ void ldsm4t(uint32_t* r, uint32_t addr) {
    asm volatile("ldmatrix.sync.aligned.m8n8.x4.trans.shared.b16 {%0,%1,%2,%3}, [%4];"
                 : "=r"(r[0]), "=r"(r[1]), "=r"(r[2]), "=r"(r[3]) : "r"(addr));
}
__device__ __forceinline__ void mma16816(float* d, const uint32_t* a,
                                         const uint32_t* b) {
    asm("mma.sync.aligned.m16n8k16.row.col.f32.f16.f16.f32 "
        "{%0,%1,%2,%3}, {%4,%5,%6,%7}, {%8,%9}, {%0,%1,%2,%3};"
        : "+f"(d[0]), "+f"(d[1]), "+f"(d[2]), "+f"(d[3])
        : "r"(a[0]), "r"(a[1]), "r"(a[2]), "r"(a[3]),
          "r"(b[0]), "r"(b[1]));
}

// ================= mma.sync GEMM (fp16, 128x128, 2-stage) ===================
// C[M,N] = A @ B^T (B stored [N,K] K-major) + bias.
// SPLITOUT: 2 fp16 C | 3 QKV route (q/k/v fp16, per-matrix bias)
#define G_STAGE  32768            // A 16K | B 16K
#define G_SMEM   (2*G_STAGE)      // 64 KB -> 2 CTAs/SM

template<int ACT, int SPLITOUT>
__global__ __launch_bounds__(256, 2)
void gemm_mma(const __half* __restrict__ Ah,
              const __half* __restrict__ Bh,
              const float* __restrict__ bias,
              const float* __restrict__ biasK,
              const float* __restrict__ biasV,
              __half* __restrict__ Ch,
              __half* __restrict__ Kh_,
              __half* __restrict__ Vh_,
              int N, int K)
{
    extern __shared__ __align__(128) char smem[];
    const uint32_t sb = smem_u32(smem);
    const int tid  = threadIdx.x;
    const int wid  = tid >> 5;
    const int lane = tid & 31;
    const int wm   = wid & 3;
    const int wn   = wid >> 2;
    const int bc = blockIdx.x, br = blockIdx.y;

    const __half* Ah_t = Ah + (size_t)br * 128 * K;
    const __half* Bh_t = Bh + (size_t)bc * 128 * K;
    const int NT = K >> 6;

    auto load_stage = [&](int kt, int s) {
        const uint32_t base = sb + s * G_STAGE;
        const int koff = kt * 64;
        #pragma unroll
        for (int t = 0; t < 4; t++) {
            int idx = t * 256 + tid;
            int row = idx >> 3, ch = idx & 7;
            uint32_t so = sw128((uint32_t)(row * 128 + ch * 16));
            size_t go = (size_t)row * K + koff + ch * 8;
            cp16(base + so,         Ah_t + go);
            cp16(base + 16384 + so, Bh_t + go);
        }
        CP_COMMIT();
    };

    float acc[2][8][4];
    #pragma unroll
    for (int mi = 0; mi < 2; mi++)
        #pragma unroll
        for (int nj = 0; nj < 8; nj++)
            #pragma unroll
            for (int e = 0; e < 4; e++) acc[mi][nj][e] = 0.f;

    const int g = lane >> 3, r = lane & 7;

    load_stage(0, 0);

    for (int kt = 0; kt < NT; kt++) {
        const int buf = kt & 1;
        if (kt + 1 < NT) { load_stage(kt + 1, buf ^ 1); CP_WAIT1(); }
        else             { CP_WAIT0(); }
        __syncthreads();

        const uint32_t sA = sb + buf * G_STAGE;
        const uint32_t sB = sA + 16384;

        #pragma unroll
        for (int kc = 0; kc < 4; kc++) {
            uint32_t a_h[2][4];
            #pragma unroll
            for (int mi = 0; mi < 2; mi++) {
                int arow = wm * 32 + mi * 16 + r + ((g & 1) << 3);
                uint32_t off = sw128((uint32_t)(arow * 128 + kc * 32 +
                                                ((g >> 1) << 4)));
                ldsm4(a_h[mi], sA + off);
            }
            uint32_t b_h[4][4];
            #pragma unroll
            for (int np = 0; np < 4; np++) {
                int brow = wn * 64 + np * 16 + r + ((g >> 1) << 3);
                uint32_t off = sw128((uint32_t)(brow * 128 + kc * 32 +
                                                ((g & 1) << 4)));
                ldsm4(b_h[np], sB + off);
            }
            #pragma unroll
            for (int np = 0; np < 4; np++)
                #pragma unroll
                for (int t = 0; t < 2; t++)
                    #pragma unroll
                    for (int mi = 0; mi < 2; mi++)
                        mma16816(acc[mi][np * 2 + t], a_h[mi], &b_h[np][2 * t]);
        }
        __syncthreads();
    }

    const int rbase = br * 128 + wm * 32 + (lane >> 2);

    if (SPLITOUT == 3) {
        // QKV routing: bc 0-7 -> Q, 8-15 -> K, 16-23 -> V (all fp16)
        const int sel   = bc >> 3;
        const int cloc0 = (bc & 7) * 128 + wn * 64 + (lane & 3) * 2;
        __half* dst = (sel == 0) ? Ch : (sel == 1) ? Kh_ : Vh_;
        const float* bp = (sel == 0) ? bias : (sel == 1) ? biasK : biasV;
        #pragma unroll
        for (int mi = 0; mi < 2; mi++) {
            #pragma unroll
            for (int nj = 0; nj < 8; nj++) {
                float2 bv = *(const float2*)(bp + cloc0 + nj * 8);
                float v0 = acc[mi][nj][0] + bv.x;
                float v1 = acc[mi][nj][1] + bv.y;
                float v2 = acc[mi][nj][2] + bv.x;
                float v3 = acc[mi][nj][3] + bv.y;
                size_t i0 = (size_t)(rbase + mi * 16)     * DD + cloc0 + nj * 8;
                size_t i1 = (size_t)(rbase + mi * 16 + 8) * DD + cloc0 + nj * 8;
                *(__half2*)(dst + i0) = __floats2half2_rn(v0, v1);
                *(__half2*)(dst + i1) = __floats2half2_rn(v2, v3);
            }
        }
        return;
    }

    const int cbase = bc * 128 + wn * 64 + (lane & 3) * 2;
    #pragma unroll
    for (int mi = 0; mi < 2; mi++) {
        #pragma unroll
        for (int nj = 0; nj < 8; nj++) {
            int c = cbase + nj * 8;
            float2 bv = *(const float2*)(bias + c);
            float v0 = acc[mi][nj][0] + bv.x;
            float v1 = acc[mi][nj][1] + bv.y;
            float v2 = acc[mi][nj][2] + bv.x;
            float v3 = acc[mi][nj][3] + bv.y;
            if (ACT) {
                v0 = fmaxf(v0, 0.f); v1 = fmaxf(v1, 0.f);
                v2 = fmaxf(v2, 0.f); v3 = fmaxf(v3, 0.f);
            }
            size_t i0 = (size_t)(rbase + mi * 16)     * N + c;
            size_t i1 = (size_t)(rbase + mi * 16 + 8) * N + c;
            *(__half2*)(Ch + i0) = __floats2half2_rn(v0, v1);
            *(__half2*)(Ch + i1) = __floats2half2_rn(v2, v3);
        }
    }
}

// ================= Flash attention (pure fp16, fp32 softmax) ================
#define A_QH   0
#define A_ST   16384            // 2 stages x (Kh 8K | Vh 8K)
#define A_MK   49152            // 2 x 256 B mask
#define A_SMEM (49152 + 512)

__global__ __launch_bounds__(256, 2)
void attn_mma(const __half* __restrict__ qh,
              const __half* __restrict__ kh,
              const __half* __restrict__ vh,
              const float* __restrict__ mask,
              __half* __restrict__ ch,
              int bh_base)
{
    extern __shared__ __align__(128) char smem[];
    const uint32_t sb = smem_u32(smem);
    const int tid  = threadIdx.x;
    const int wid  = tid >> 5;
    const int lane = tid & 31;
    const int g    = lane >> 3, r8 = lane & 7;
    const int c2   = (lane & 3) * 2;

    const int qt = blockIdx.x;
    const int bh = bh_base + blockIdx.y;
    const int b  = bh >> 4;
    const int h  = bh & 15;

    const size_t qrow0 = (size_t)b * SS + (size_t)qt * 128;
    const __half* qhg = qh + qrow0 * DD + h * DHH;
    const __half* khg = kh + (size_t)b * SS * DD + h * DHH;
    const __half* vhg = vh + (size_t)b * SS * DD + h * DHH;
    const float* mkg = mask + (size_t)b * SS;

    auto load_kv = [&](int t, int s) {
        const uint32_t base = sb + A_ST + s * 16384;
        const size_t koff = (size_t)(t * 64) * DD;
        #pragma unroll
        for (int it = 0; it < 4; it++) {
            int idx = it * 256 + tid;
            int mat = idx >> 9;
            int sub = idx & 511;
            int row = sub >> 3, chk = sub & 7;
            uint32_t so = sw128((uint32_t)(row * 128 + chk * 16));
            size_t go = koff + (size_t)row * DD + chk * 8;
            cp16(base + mat * 8192 + so, (mat ? vhg : khg) + go);
        }
        if (tid < 16)
            cp16(sb + A_MK + s * 256 + tid * 16, mkg + t * 64 + tid * 4);
        CP_COMMIT();
    };

    #pragma unroll
    for (int it = 0; it < 4; it++) {
        int idx = it * 256 + tid;
        int row = idx >> 3, chk = idx & 7;
        uint32_t so = sw128((uint32_t)(row * 128 + chk * 16));
        cp16(sb + A_QH + so, qhg + (size_t)row * DD + chk * 8);
    }
    load_kv(0, 0);

    float mA = -INFINITY, mB = -INFINITY, lA = 0.f, lB = 0.f;
    float O[8][4];
    #pragma unroll
    for (int j = 0; j < 8; j++)
        #pragma unroll
        for (int e = 0; e < 4; e++) O[j][e] = 0.f;

    #pragma unroll 1
    for (int t = 0; t < 16; t++) {
        const int buf = t & 1;
        if (t + 1 < 16) { load_kv(t + 1, buf ^ 1); CP_WAIT1(); }
        else            { CP_WAIT0(); }
        __syncthreads();

        const uint32_t sKh = sb + A_ST + buf * 16384;
        const uint32_t sVh = sKh + 8192;
        const float* mkv = (const float*)(smem + A_MK + buf * 256);

        float s_[8][4];
        #pragma unroll
        for (int j = 0; j < 8; j++)
            #pragma unroll
            for (int e = 0; e < 4; e++) s_[j][e] = 0.f;

        #pragma unroll
        for (int kc = 0; kc < 4; kc++) {
            uint32_t aqh[4];
            {
                int arow = wid * 16 + r8 + ((g & 1) << 3);
                uint32_t off = sw128((uint32_t)(arow * 128 + kc * 32 +
                                                ((g >> 1) << 4)));
                ldsm4(aqh, sb + A_QH + off);
            }
            uint32_t bkh[4][4];
            #pragma unroll
            for (int np = 0; np < 4; np++) {
                int brow = np * 16 + r8 + ((g >> 1) << 3);
                uint32_t off = sw128((uint32_t)(brow * 128 + kc * 32 +
                                                ((g & 1) << 4)));
                ldsm4(bkh[np], sKh + off);
            }
            #pragma unroll
            for (int np = 0; np < 4; np++)
                #pragma unroll
                for (int t2 = 0; t2 < 2; t2++)
                    mma16816(s_[np * 2 + t2], aqh, &bkh[np][2 * t2]);
        }

        float tmA = -INFINITY, tmB = -INFINITY;
        #pragma unroll
        for (int j = 0; j < 8; j++) {
            float mk0 = mkv[j * 8 + c2]     * (-1e9f);
            float mk1 = mkv[j * 8 + c2 + 1] * (-1e9f);
            s_[j][0] = s_[j][0] * 0.125f + mk0;
            s_[j][1] = s_[j][1] * 0.125f + mk1;
            s_[j][2] = s_[j][2] * 0.125f + mk0;
            s_[j][3] = s_[j][3] * 0.125f + mk1;
            tmA = fmaxf(tmA, fmaxf(s_[j][0], s_[j][1]));
            tmB = fmaxf(tmB, fmaxf(s_[j][2], s_[j][3]));
        }
        tmA = fmaxf(tmA, __shfl_xor_sync(0xffffffffu, tmA, 1));
        tmA = fmaxf(tmA, __shfl_xor_sync(0xffffffffu, tmA, 2));
        tmB = fmaxf(tmB, __shfl_xor_sync(0xffffffffu, tmB, 1));
        tmB = fmaxf(tmB, __shfl_xor_sync(0xffffffffu, tmB, 2));

        const float nmA = fmaxf(mA, tmA), nmB = fmaxf(mB, tmB);
        const float fA = __expf(mA - nmA), fB = __expf(mB - nmB);

        float sumA = 0.f, sumB = 0.f;
        #pragma unroll
        for (int j = 0; j < 8; j++) {
            s_[j][0] = __expf(s_[j][0] - nmA);
            s_[j][1] = __expf(s_[j][1] - nmA);
            s_[j][2] = __expf(s_[j][2] - nmB);
            s_[j][3] = __expf(s_[j][3] - nmB);
            sumA += s_[j][0] + s_[j][1];
            sumB += s_[j][2] + s_[j][3];
        }
        sumA += __shfl_xor_sync(0xffffffffu, sumA, 1);
        sumA += __shfl_xor_sync(0xffffffffu, sumA, 2);
        sumB += __shfl_xor_sync(0xffffffffu, sumB, 1);
        sumB += __shfl_xor_sync(0xffffffffu, sumB, 2);
        lA = lA * fA + sumA;  mA = nmA;
        lB = lB * fB + sumB;  mB = nmB;

        #pragma unroll
        for (int j = 0; j < 8; j++) {
            O[j][0] *= fA; O[j][1] *= fA;
            O[j][2] *= fB; O[j][3] *= fB;
        }

        #pragma unroll
        for (int c = 0; c < 4; c++) {
            uint32_t ap_h[4];
            __half2 p0 = __floats2half2_rn(s_[2 * c][0],     s_[2 * c][1]);
            __half2 p1 = __floats2half2_rn(s_[2 * c][2],     s_[2 * c][3]);
            __half2 p2 = __floats2half2_rn(s_[2 * c + 1][0], s_[2 * c + 1][1]);
            __half2 p3 = __floats2half2_rn(s_[2 * c + 1][2], s_[2 * c + 1][3]);
            ap_h[0] = *(uint32_t*)&p0; ap_h[1] = *(uint32_t*)&p1;
            ap_h[2] = *(uint32_t*)&p2; ap_h[3] = *(uint32_t*)&p3;
            uint32_t bvh[4][4];
            #pragma unroll
            for (int np2 = 0; np2 < 4; np2++) {
                int vrow = c * 16 + r8 + ((g & 1) << 3);
                uint32_t off = sw128((uint32_t)(vrow * 128 + np2 * 32 +
                                                ((g >> 1) << 4)));
                ldsm4t(bvh[np2], sVh + off);
            }
            #pragma unroll
            for (int np2 = 0; np2 < 4; np2++)
                #pragma unroll
                for (int t2 = 0; t2 < 2; t2++)
                    mma16816(O[np2 * 2 + t2], ap_h, &bvh[np2][2 * t2]);
        }
        __syncthreads();
    }

    const float liA = 1.f / lA, liB = 1.f / lB;
    const size_t rowA = qrow0 + wid * 16 + (lane >> 2);
    const size_t rowB = rowA + 8;
    const int    colb = h * DHH + c2;
    #pragma unroll
    for (int j = 0; j < 8; j++) {
        *(__half2*)(ch + rowA * DD + colb + j * 8) =
            __floats2half2_rn(O[j][0] * liA, O[j][1] * liA);
        *(__half2*)(ch + rowB * DD + colb + j * 8) =
            __floats2half2_rn(O[j][2] * liB, O[j][3] * liB);
    }
}

// ================= fp32 -> fp16 convert (4 float4/thread, MLP=4) ===========
__global__ __launch_bounds__(256) void convert_kernel(
    const float4* __restrict__ in, __half2* __restrict__ oh, int n4)
{
    int base = blockIdx.x * 1024 + threadIdx.x;
    #pragma unroll
    for (int u = 0; u < 4; u++) {
        int i = base + u * 256;
        if (i < n4) {
            float4 v = in[i];
            oh[2 * i]     = __floats2half2_rn(v.x, v.y);
            oh[2 * i + 1] = __floats2half2_rn(v.z, v.w);
        }
    }
}

// W[K,N] fp32 -> fp16 [N,K] (transpose); gridDim.z selects among 3 weights
__global__ __launch_bounds__(256) void split_tr3_kernel(
    const float* __restrict__ W0, const float* __restrict__ W1_,
    const float* __restrict__ W2_, __half* __restrict__ dst)
{
    const int z = blockIdx.z;
    const float* W = (z == 0) ? W0 : (z == 1) ? W1_ : W2_;
    __half* oh = dst + (size_t)z * DD * DD;
    __shared__ float t[32][33];
    const int bx = blockIdx.x, by = blockIdx.y;
    const int tx = threadIdx.x, ty = threadIdx.y;
    #pragma unroll
    for (int i = 0; i < 4; i++) {
        int rr = ty + i * 8;
        t[rr][tx] = W[(size_t)(by * 32 + rr) * DD + bx * 32 + tx];
    }
    __syncthreads();
    #pragma unroll
    for (int i = 0; i < 4; i++) {
        int rr = ty + i * 8;
        size_t o = (size_t)(bx * 32 + rr) * DD + by * 32 + tx;
        oh[o] = __float2half_rn(t[tx][rr]);
    }
}

// single-weight transpose (Wo, W1, W2)
__global__ __launch_bounds__(256) void split_tr_kernel(
    const float* __restrict__ W, __half* __restrict__ oh, int K, int N)
{
    __shared__ float t[32][33];
    const int bx = blockIdx.x, by = blockIdx.y;
    const int tx = threadIdx.x, ty = threadIdx.y;
    #pragma unroll
    for (int i = 0; i < 4; i++) {
        int rr = ty + i * 8;
        t[rr][tx] = W[(size_t)(by * 32 + rr) * N + bx * 32 + tx];
    }
    __syncthreads();
    #pragma unroll
    for (int i = 0; i < 4; i++) {
        int rr = ty + i * 8;
        size_t o = (size_t)(bx * 32 + rr) * K + by * 32 + tx;
        oh[o] = __float2half_rn(t[tx][rr]);
    }
}

// ================= residual + LayerNorm (vectorized, Y in fp16) ============
template<int SPL>
__global__ __launch_bounds__(256) void residual_ln_kernel(
    const float* __restrict__ X, const __half* __restrict__ Y,
    const float* __restrict__ g, const float* __restrict__ beta,
    float* __restrict__ out, __half* __restrict__ oh)
{
    __shared__ float ws[8], ws2[8];
    const int row = blockIdx.x;
    const int tid = threadIdx.x;
    const int lane = tid & 31, warp = tid >> 5;
    const int c4 = tid * 4;

    float4 xv = *(const float4*)(X + (size_t)row * DD + c4);
    __half2 y0 = *(const __half2*)(Y + (size_t)row * DD + c4);
    __half2 y1 = *(const __half2*)(Y + (size_t)row * DD + c4 + 2);
    float2 yf0 = __half22float2(y0), yf1 = __half22float2(y1);

    float v0 = xv.x + yf0.x, v1 = xv.y + yf0.y;
    float v2 = xv.z + yf1.x, v3 = xv.w + yf1.y;
    float s  = v0 + v1 + v2 + v3;
    float s2 = v0 * v0 + v1 * v1 + v2 * v2 + v3 * v3;

    #pragma unroll
    for (int off = 16; off; off >>= 1) {
        s  += __shfl_xor_sync(0xffffffffu, s,  off);
        s2 += __shfl_xor_sync(0xffffffffu, s2, off);
    }
    if (lane == 0) { ws[warp] = s; ws2[warp] = s2; }
    __syncthreads();
    if (warp == 0) {
        s  = (lane < 8) ? ws[lane]  : 0.f;
        s2 = (lane < 8) ? ws2[lane] : 0.f;
        #pragma unroll
        for (int off = 4; off; off >>= 1) {
            s  += __shfl_xor_sync(0xffffffffu, s,  off);
            s2 += __shfl_xor_sync(0xffffffffu, s2, off);
        }
        if (lane == 0) { ws[0] = s; ws2[0] = s2; }
    }
    __syncthreads();
    float mu  = ws[0] * (1.f / 1024.f);
    float var = fmaxf(ws2[0] * (1.f / 1024.f) - mu * mu, 0.f);
    float rstd = rsqrtf(var + 1e-6f);

    float4 gv = *(const float4*)(g + c4);
    float4 bv = *(const float4*)(beta + c4);
    float4 o;
    o.x = gv.x * (v0 - mu) * rstd + bv.x;
    o.y = gv.y * (v1 - mu) * rstd + bv.y;
    o.z = gv.z * (v2 - mu) * rstd + bv.z;
    o.w = gv.w * (v3 - mu) * rstd + bv.w;
    *(float4*)(out + (size_t)row * DD + c4) = o;
    if (SPL) {
        *(__half2*)(oh + (size_t)row * DD + c4)     = __floats2half2_rn(o.x, o.y);
        *(__half2*)(oh + (size_t)row * DD + c4 + 2) = __floats2half2_rn(o.z, o.w);
    }
}

// ================= launch ===================================================
extern "C" void kernel_launch(void* const* d_in, const int* in_sizes, int n_in,
                              void* d_out, int out_size)
{
    const float* x    = (const float*)d_in[0];
    const float* mask = (const float*)d_in[1];
    const float* Wq   = (const float*)d_in[2];
    const float* bq   = (const float*)d_in[3];
    const float* Wk   = (const float*)d_in[4];
    const float* bk   = (const float*)d_in[5];
    const float* Wv   = (const float*)d_in[6];
    const float* bv   = (const float*)d_in[7];
    const float* Wo   = (const float*)d_in[8];
    const float* bo   = (const float*)d_in[9];
    const float* g1   = (const float*)d_in[10];
    const float* be1  = (const float*)d_in[11];
    const float* W1   = (const float*)d_in[12];
    const float* bf1  = (const float*)d_in[13];
    const float* W2   = (const float*)d_in[14];
    const float* bf2  = (const float*)d_in[15];
    const float* g2   = (const float*)d_in[16];
    const float* be2  = (const float*)d_in[17];
    float* out = (float*)d_out;

    float *x1;
    __half *ah, *qh, *kh, *vh, *hh, *t1h;
    __half *wqkv, *woh, *w1h, *w2h;
    cudaGetSymbolAddress((void**)&x1,   g_x1);
    cudaGetSymbolAddress((void**)&t1h,  g_t1h);
    cudaGetSymbolAddress((void**)&ah,   g_ah);
    cudaGetSymbolAddress((void**)&qh,   g_qh);
    cudaGetSymbolAddress((void**)&kh,   g_kh);
    cudaGetSymbolAddress((void**)&vh,   g_vh);
    cudaGetSymbolAddress((void**)&hh,   g_hh);
    cudaGetSymbolAddress((void**)&wqkv, g_wqkv);
    cudaGetSymbolAddress((void**)&woh,  g_woh);
    cudaGetSymbolAddress((void**)&w1h,  g_w1h);
    cudaGetSymbolAddress((void**)&w2h,  g_w2h);

    cudaFuncSetAttribute(attn_mma,
                         cudaFuncAttributeMaxDynamicSharedMemorySize, A_SMEM);
    cudaFuncSetAttribute(gemm_mma<0, 3>,
                         cudaFuncAttributeMaxDynamicSharedMemorySize, G_SMEM);
    cudaFuncSetAttribute(gemm_mma<0, 2>,
                         cudaFuncAttributeMaxDynamicSharedMemorySize, G_SMEM);
    cudaFuncSetAttribute(gemm_mma<1, 2>,
                         cudaFuncAttributeMaxDynamicSharedMemorySize, G_SMEM);

    // streams: 0 = chain A, s2 = chain B, s3 = weight prep
    static cudaStream_t s2 = nullptr, s3 = nullptr;
    static cudaEvent_t evF, evQKVp, evO, ev1p, ev2p, evB;
    if (!s2) {
        cudaStreamCreateWithFlags(&s2, cudaStreamNonBlocking);
        cudaStreamCreateWithFlags(&s3, cudaStreamNonBlocking);
        cudaEventCreateWithFlags(&evF,    cudaEventDisableTiming);
        cudaEventCreateWithFlags(&evQKVp, cudaEventDisableTiming);
        cudaEventCreateWithFlags(&evO,    cudaEventDisableTiming);
        cudaEventCreateWithFlags(&ev1p,   cudaEventDisableTiming);
        cudaEventCreateWithFlags(&ev2p,   cudaEventDisableTiming);
        cudaEventCreateWithFlags(&evB,    cudaEventDisableTiming);
    }

    const dim3 trQKV(DD / 32, DD / 32, 3);
    const dim3 trDD(DD / 32, DD / 32);
    const dim3 trDF(FF / 32, DD / 32);
    const dim3 trFD(DD / 32, FF / 32);
    const dim3 tb(32, 8);
    // per-chain grids (HR = 4096 rows each)
    const dim3 gQKV(3 * DD / 128, HR / 128);  // (24, 32)
    const dim3 gD(DD / 128, HR / 128);        // (8, 32)
    const dim3 gF(FF / 128, HR / 128);        // (32, 32)
    const dim3 gAttn(8, 64);                  // 4 batches x 16 heads
    const int  cvt_n4 = HR * DD / 4;

    // ---- fork ----
    cudaEventRecord(evF, 0);
    cudaStreamWaitEvent(s2, evF, 0);
    cudaStreamWaitEvent(s3, evF, 0);

    // s3: weight prep (QKV weights in ONE launch; no bias packing needed)
    split_tr3_kernel<<<trQKV, tb, 0, s3>>>(Wq, Wk, Wv, wqkv);
    cudaEventRecord(evQKVp, s3);
    split_tr_kernel<<<trDD, tb, 0, s3>>>(Wo, woh, DD, DD);
    cudaEventRecord(evO, s3);
    split_tr_kernel<<<trDF, tb, 0, s3>>>(W1, w1h, DD, FF);
    cudaEventRecord(ev1p, s3);
    split_tr_kernel<<<trFD, tb, 0, s3>>>(W2, w2h, FF, DD);
    cudaEventRecord(ev2p, s3);

    // ---- two independent batch-half chains ----
    for (int c = 0; c < 2; c++) {
        cudaStream_t st = (c == 0) ? (cudaStream_t)0 : s2;
        const size_t R  = (size_t)c * HR;          // row offset
        const size_t RD = R * DD;
        const size_t RF = R * FF;

        // x -> fp16
        convert_kernel<<<(cvt_n4 + 1023) / 1024, 256, 0, st>>>(
            (const float4*)(x + RD), (__half2*)(ah + RD), cvt_n4);

        // fused QKV projection (per-matrix bias selection in epilogue)
        cudaStreamWaitEvent(st, evQKVp, 0);
        gemm_mma<0, 3><<<gQKV, 256, G_SMEM, st>>>(
            ah + RD, wqkv, bq, bk, bv, qh + RD, kh + RD, vh + RD, 3 * DD, DD);

        // attention for this half's 4 batches (bh_base = c*64)
        attn_mma<<<gAttn, 256, A_SMEM, st>>>(qh, kh, vh, mask, ah, c * 64);

        // output projection (fp16 t1) + residual LN
        cudaStreamWaitEvent(st, evO, 0);
        gemm_mma<0, 2><<<gD, 256, G_SMEM, st>>>(
            ah + RD, woh, bo, nullptr, nullptr, t1h + RD, nullptr, nullptr,
            DD, DD);
        residual_ln_kernel<1><<<HR, 256, 0, st>>>(
            x + RD, t1h + RD, g1, be1, x1 + RD, ah + RD);

        // FFN1
        cudaStreamWaitEvent(st, ev1p, 0);
        gemm_mma<1, 2><<<gF, 256, G_SMEM, st>>>(
            ah + RD, w1h, bf1, nullptr, nullptr, hh + RF, nullptr, nullptr,
            FF, DD);

        // FFN2 (fp16 t1) + final residual LN
        cudaStreamWaitEvent(st, ev2p, 0);
        gemm_mma<0, 2><<<gD, 256, G_SMEM, st>>>(
            hh + RF, w2h, bf2, nullptr, nullptr, t1h + RD, nullptr, nullptr,
            DD, FF);
        residual_ln_kernel<0><<<HR, 256, 0, st>>>(
            x1 + RD, t1h + RD, g2, be2, out + RD, nullptr);
    }

    // join: default stream waits for chain B
    cudaEventRecord(evB, s2);
    cudaStreamWaitEvent(0, evB, 0);
}

// round 16
// speedup vs baseline: 1.1208x; 1.0282x over previous
#include <cuda_runtime.h>
#include <cuda_fp16.h>
#include <math.h>
#include <stddef.h>
#include <stdint.h>

#define BB   8
#define SS   1024
#define DD   1024
#define HH   16
#define DHH  64
#define FF   4096
#define MR   (BB*SS)   // 8192 rows
#define HR   (MR/2)    // 4096 rows per chain

// ---------------- scratch (device globals) ----------------------------------
__device__ __half g_t1h[MR*DD];           // fp16 GEMM outputs for LN
__device__ __half g_ah[MR*DD];            // activation fp16 (x / ctx / x1)
__device__ __half g_qh[MR*DD];
__device__ __half g_kh[MR*DD];
__device__ __half g_vh[MR*DD];
__device__ __half g_hh[(size_t)MR*FF];    // FFN hidden
// weights, fp16, SAME layout as source ([K,N] row-major)
__device__ __half g_wqkv[3*DD*DD];        // Wq|Wk|Wv
__device__ __half g_woh[DD*DD];
__device__ __half g_w1h[(size_t)DD*FF];
__device__ __half g_w2h[(size_t)FF*DD];

// ================= PTX helpers ==============================================
__device__ __forceinline__ uint32_t smem_u32(const void* p) {
    uint32_t a;
    asm("{ .reg .u64 t; cvta.to.shared.u64 t, %1; cvt.u32.u64 %0, t; }"
        : "=r"(a) : "l"(p));
    return a;
}
__device__ __forceinline__ uint32_t sw128(uint32_t o) {
    return o ^ ((o >> 3) & 0x70);
}
__device__ __forceinline__ void cp16(uint32_t s, const void* g) {
    asm volatile("cp.async.cg.shared.global [%0], [%1], 16;" :: "r"(s), "l"(g));
}
#define CP_COMMIT()  asm volatile("cp.async.commit_group;" ::: "memory")
#define CP_WAIT0()   asm volatile("cp.async.wait_group 0;" ::: "memory")
#define CP_WAIT1()   asm volatile("cp.async.wait_group 1;" ::: "memory")

__device__ __forceinline__ void ldsm4(uint32_t* r, uint32_t addr) {
    asm volatile("ldmatrix.sync.aligned.m8n8.x4.shared.b16 {%0,%1,%2,%3}, [%4];"
                 : "=r"(r[0]), "=r"(r[1]), "=r"(r[2]), "=r"(r[3]) : "r"(addr));
}
__device__ __forceinline__ void ldsm4t(uint32_t* r, uint32_t addr) {
    asm volatile("ldmatrix.sync.aligned.m8n8.x4.trans.shared.b16 {%0,%1,%2,%3}, [%4];"
                 : "=r"(r[0]), "=r"(r[1]), "=r"(r[2]), "=r"(r[3]) : "r"(addr));
}
__device__ __forceinline__ void mma16816(float* d, const uint32_t* a,
                                         const uint32_t* b) {
    asm("mma.sync.aligned.m16n8k16.row.col.f32.f16.f16.f32 "
        "{%0,%1,%2,%3}, {%4,%5,%6,%7}, {%8,%9}, {%0,%1,%2,%3};"
        : "+f"(d[0]), "+f"(d[1]), "+f"(d[2]), "+f"(d[3])
        : "r"(a[0]), "r"(a[1]), "r"(a[2]), "r"(a[3]),
          "r"(b[0]), "r"(b[1]));
}

// ================= mma.sync GEMM (fp16, 128x128, 2-stage, [K,N] B) ==========
// C[M,N] = A[M,K] @ B[K,N] + bias.  B is row-major [K,N] fp16 (weight layout).
// B smem tile: two [64 k-rows][64 n-cols] subtiles stacked (warp wn owns one);
// fragments via ldmatrix.trans — identical geometry to attention's V path.
// SPLITOUT: 2 fp16 C | 3 QKV route (q/k/v fp16, per-matrix weight+bias)
#define G_STAGE  32768            // A 16K | B 16K
#define G_SMEM   (2*G_STAGE)      // 64 KB -> 2 CTAs/SM

template<int ACT, int SPLITOUT>
__global__ __launch_bounds__(256, 2)
void gemm_mma(const __half* __restrict__ Ah,
              const __half* __restrict__ Bq,
              const __half* __restrict__ Bk,
              const __half* __restrict__ Bv,
              const float* __restrict__ bias,
              const float* __restrict__ biasK,
              const float* __restrict__ biasV,
              __half* __restrict__ Ch,
              __half* __restrict__ Kh_,
              __half* __restrict__ Vh_,
              int N, int K)
{
    extern __shared__ __align__(128) char smem[];
    const uint32_t sb = smem_u32(smem);
    const int tid  = threadIdx.x;
    const int wid  = tid >> 5;
    const int lane = tid & 31;
    const int wm   = wid & 3;
    const int wn   = wid >> 2;
    const int bc = blockIdx.x, br = blockIdx.y;

    const __half* Ah_t = Ah + (size_t)br * 128 * K;
    const __half* Bg;
    int colbase;
    if (SPLITOUT == 3) {
        const int sel = bc >> 3;
        Bg = (sel == 0) ? Bq : (sel == 1) ? Bk : Bv;
        colbase = (bc & 7) * 128;
    } else {
        Bg = Bq;
        colbase = bc * 128;
    }
    const int NT = K >> 6;

    auto load_stage = [&](int kt, int s) {
        const uint32_t base = sb + s * G_STAGE;
        const int koff = kt * 64;
        #pragma unroll
        for (int t = 0; t < 4; t++) {
            int idx = t * 256 + tid;
            int row = idx >> 3, ch = idx & 7;
            uint32_t so = sw128((uint32_t)(row * 128 + ch * 16));
            // A: [M rows][K cols]
            cp16(base + so, Ah_t + (size_t)row * K + koff + ch * 8);
            // B: [K,N] row-major; smem row = nh*64 + k
            int nh = row >> 6, kk = row & 63;
            cp16(base + 16384 + so,
                 Bg + (size_t)(koff + kk) * N + colbase + nh * 64 + ch * 8);
        }
        CP_COMMIT();
    };

    float acc[2][8][4];
    #pragma unroll
    for (int mi = 0; mi < 2; mi++)
        #pragma unroll
        for (int nj = 0; nj < 8; nj++)
            #pragma unroll
            for (int e = 0; e < 4; e++) acc[mi][nj][e] = 0.f;

    const int g = lane >> 3, r = lane & 7;

    load_stage(0, 0);

    for (int kt = 0; kt < NT; kt++) {
        const int buf = kt & 1;
        if (kt + 1 < NT) { load_stage(kt + 1, buf ^ 1); CP_WAIT1(); }
        else             { CP_WAIT0(); }
        __syncthreads();

        const uint32_t sA = sb + buf * G_STAGE;
        const uint32_t sB = sA + 16384;

        #pragma unroll
        for (int kc = 0; kc < 4; kc++) {
            uint32_t a_h[2][4];
            #pragma unroll
            for (int mi = 0; mi < 2; mi++) {
                int arow = wm * 32 + mi * 16 + r + ((g & 1) << 3);
                uint32_t off = sw128((uint32_t)(arow * 128 + kc * 32 +
                                                ((g >> 1) << 4)));
                ldsm4(a_h[mi], sA + off);
            }
            // B fragments: attention-V geometry, subtile selected by wn
            uint32_t b_h[4][4];
            const int brow = wn * 64 + kc * 16 + r + ((g & 1) << 3);
            #pragma unroll
            for (int np = 0; np < 4; np++) {
                uint32_t off = sw128((uint32_t)(brow * 128 + np * 32 +
                                                ((g >> 1) << 4)));
                ldsm4t(b_h[np], sB + off);
            }
            #pragma unroll
            for (int np = 0; np < 4; np++)
                #pragma unroll
                for (int t = 0; t < 2; t++)
                    #pragma unroll
                    for (int mi = 0; mi < 2; mi++)
                        mma16816(acc[mi][np * 2 + t], a_h[mi], &b_h[np][2 * t]);
        }
        __syncthreads();
    }

    const int rbase = br * 128 + wm * 32 + (lane >> 2);

    if (SPLITOUT == 3) {
        const int sel   = bc >> 3;
        const int cloc0 = (bc & 7) * 128 + wn * 64 + (lane & 3) * 2;
        __half* dst = (sel == 0) ? Ch : (sel == 1) ? Kh_ : Vh_;
        const float* bp = (sel == 0) ? bias : (sel == 1) ? biasK : biasV;
        #pragma unroll
        for (int mi = 0; mi < 2; mi++) {
            #pragma unroll
            for (int nj = 0; nj < 8; nj++) {
                float2 bv = *(const float2*)(bp + cloc0 + nj * 8);
                float v0 = acc[mi][nj][0] + bv.x;
                float v1 = acc[mi][nj][1] + bv.y;
                float v2 = acc[mi][nj][2] + bv.x;
                float v3 = acc[mi][nj][3] + bv.y;
                size_t i0 = (size_t)(rbase + mi * 16)     * DD + cloc0 + nj * 8;
                size_t i1 = (size_t)(rbase + mi * 16 + 8) * DD + cloc0 + nj * 8;
                *(__half2*)(dst + i0) = __floats2half2_rn(v0, v1);
                *(__half2*)(dst + i1) = __floats2half2_rn(v2, v3);
            }
        }
        return;
    }

    const int cbase = bc * 128 + wn * 64 + (lane & 3) * 2;
    #pragma unroll
    for (int mi = 0; mi < 2; mi++) {
        #pragma unroll
        for (int nj = 0; nj < 8; nj++) {
            int c = cbase + nj * 8;
            float2 bv = *(const float2*)(bias + c);
            float v0 = acc[mi][nj][0] + bv.x;
            float v1 = acc[mi][nj][1] + bv.y;
            float v2 = acc[mi][nj][2] + bv.x;
            float v3 = acc[mi][nj][3] + bv.y;
            if (ACT) {
                v0 = fmaxf(v0, 0.f); v1 = fmaxf(v1, 0.f);
                v2 = fmaxf(v2, 0.f); v3 = fmaxf(v3, 0.f);
            }
            size_t i0 = (size_t)(rbase + mi * 16)     * N + c;
            size_t i1 = (size_t)(rbase + mi * 16 + 8) * N + c;
            *(__half2*)(Ch + i0) = __floats2half2_rn(v0, v1);
            *(__half2*)(Ch + i1) = __floats2half2_rn(v2, v3);
        }
    }
}

// ================= Flash attention (pure fp16, fp32 softmax) ================
#define A_QH   0
#define A_ST   16384            // 2 stages x (Kh 8K | Vh 8K)
#define A_MK   49152            // 2 x 256 B mask
#define A_SMEM (49152 + 512)

__global__ __launch_bounds__(256, 2)
void attn_mma(const __half* __restrict__ qh,
              const __half* __restrict__ kh,
              const __half* __restrict__ vh,
              const float* __restrict__ mask,
              __half* __restrict__ ch,
              int bh_base)
{
    extern __shared__ __align__(128) char smem[];
    const uint32_t sb = smem_u32(smem);
    const int tid  = threadIdx.x;
    const int wid  = tid >> 5;
    const int lane = tid & 31;
    const int g    = lane >> 3, r8 = lane & 7;
    const int c2   = (lane & 3) * 2;

    const int qt = blockIdx.x;
    const int bh = bh_base + blockIdx.y;
    const int b  = bh >> 4;
    const int h  = bh & 15;

    const size_t qrow0 = (size_t)b * SS + (size_t)qt * 128;
    const __half* qhg = qh + qrow0 * DD + h * DHH;
    const __half* khg = kh + (size_t)b * SS * DD + h * DHH;
    const __half* vhg = vh + (size_t)b * SS * DD + h * DHH;
    const float* mkg = mask + (size_t)b * SS;

    auto load_kv = [&](int t, int s) {
        const uint32_t base = sb + A_ST + s * 16384;
        const size_t koff = (size_t)(t * 64) * DD;
        #pragma unroll
        for (int it = 0; it < 4; it++) {
            int idx = it * 256 + tid;
            int mat = idx >> 9;
            int sub = idx & 511;
            int row = sub >> 3, chk = sub & 7;
            uint32_t so = sw128((uint32_t)(row * 128 + chk * 16));
            size_t go = koff + (size_t)row * DD + chk * 8;
            cp16(base + mat * 8192 + so, (mat ? vhg : khg) + go);
        }
        if (tid < 16)
            cp16(sb + A_MK + s * 256 + tid * 16, mkg + t * 64 + tid * 4);
        CP_COMMIT();
    };

    #pragma unroll
    for (int it = 0; it < 4; it++) {
        int idx = it * 256 + tid;
        int row = idx >> 3, chk = idx & 7;
        uint32_t so = sw128((uint32_t)(row * 128 + chk * 16));
        cp16(sb + A_QH + so, qhg + (size_t)row * DD + chk * 8);
    }
    load_kv(0, 0);

    float mA = -INFINITY, mB = -INFINITY, lA = 0.f, lB = 0.f;
    float O[8][4];
    #pragma unroll
    for (int j = 0; j < 8; j++)
        #pragma unroll
        for (int e = 0; e < 4; e++) O[j][e] = 0.f;

    #pragma unroll 1
    for (int t = 0; t < 16; t++) {
        const int buf = t & 1;
        if (t + 1 < 16) { load_kv(t + 1, buf ^ 1); CP_WAIT1(); }
        else            { CP_WAIT0(); }
        __syncthreads();

        const uint32_t sKh = sb + A_ST + buf * 16384;
        const uint32_t sVh = sKh + 8192;
        const float* mkv = (const float*)(smem + A_MK + buf * 256);

        float s_[8][4];
        #pragma unroll
        for (int j = 0; j < 8; j++)
            #pragma unroll
            for (int e = 0; e < 4; e++) s_[j][e] = 0.f;

        #pragma unroll
        for (int kc = 0; kc < 4; kc++) {
            uint32_t aqh[4];
            {
                int arow = wid * 16 + r8 + ((g & 1) << 3);
                uint32_t off = sw128((uint32_t)(arow * 128 + kc * 32 +
                                                ((g >> 1) << 4)));
                ldsm4(aqh, sb + A_QH + off);
            }
            uint32_t bkh[4][4];
            #pragma unroll
            for (int np = 0; np < 4; np++) {
                int brow = np * 16 + r8 + ((g >> 1) << 3);
                uint32_t off = sw128((uint32_t)(brow * 128 + kc * 32 +
                                                ((g & 1) << 4)));
                ldsm4(bkh[np], sKh + off);
            }
            #pragma unroll
            for (int np = 0; np < 4; np++)
                #pragma unroll
                for (int t2 = 0; t2 < 2; t2++)
                    mma16816(s_[np * 2 + t2], aqh, &bkh[np][2 * t2]);
        }

        float tmA = -INFINITY, tmB = -INFINITY;
        #pragma unroll
        for (int j = 0; j < 8; j++) {
            float mk0 = mkv[j * 8 + c2]     * (-1e9f);
            float mk1 = mkv[j * 8 + c2 + 1] * (-1e9f);
            s_[j][0] = s_[j][0] * 0.125f + mk0;
            s_[j][1] = s_[j][1] * 0.125f + mk1;
            s_[j][2] = s_[j][2] * 0.125f + mk0;
            s_[j][3] = s_[j][3] * 0.125f + mk1;
            tmA = fmaxf(tmA, fmaxf(s_[j][0], s_[j][1]));
            tmB = fmaxf(tmB, fmaxf(s_[j][2], s_[j][3]));
        }
        tmA = fmaxf(tmA, __shfl_xor_sync(0xffffffffu, tmA, 1));
        tmA = fmaxf(tmA, __shfl_xor_sync(0xffffffffu, tmA, 2));
        tmB = fmaxf(tmB, __shfl_xor_sync(0xffffffffu, tmB, 1));
        tmB = fmaxf(tmB, __shfl_xor_sync(0xffffffffu, tmB, 2));

        const float nmA = fmaxf(mA, tmA), nmB = fmaxf(mB, tmB);
        const float fA = __expf(mA - nmA), fB = __expf(mB - nmB);

        float sumA = 0.f, sumB = 0.f;
        #pragma unroll
        for (int j = 0; j < 8; j++) {
            s_[j][0] = __expf(s_[j][0] - nmA);
            s_[j][1] = __expf(s_[j][1] - nmA);
            s_[j][2] = __expf(s_[j][2] - nmB);
            s_[j][3] = __expf(s_[j][3] - nmB);
            sumA += s_[j][0] + s_[j][1];
            sumB += s_[j][2] + s_[j][3];
        }
        sumA += __shfl_xor_sync(0xffffffffu, sumA, 1);
        sumA += __shfl_xor_sync(0xffffffffu, sumA, 2);
        sumB += __shfl_xor_sync(0xffffffffu, sumB, 1);
        sumB += __shfl_xor_sync(0xffffffffu, sumB, 2);
        lA = lA * fA + sumA;  mA = nmA;
        lB = lB * fB + sumB;  mB = nmB;

        #pragma unroll
        for (int j = 0; j < 8; j++) {
            O[j][0] *= fA; O[j][1] *= fA;
            O[j][2] *= fB; O[j][3] *= fB;
        }

        #pragma unroll
        for (int c = 0; c < 4; c++) {
            uint32_t ap_h[4];
            __half2 p0 = __floats2half2_rn(s_[2 * c][0],     s_[2 * c][1]);
            __half2 p1 = __floats2half2_rn(s_[2 * c][2],     s_[2 * c][3]);
            __half2 p2 = __floats2half2_rn(s_[2 * c + 1][0], s_[2 * c + 1][1]);
            __half2 p3 = __floats2half2_rn(s_[2 * c + 1][2], s_[2 * c + 1][3]);
            ap_h[0] = *(uint32_t*)&p0; ap_h[1] = *(uint32_t*)&p1;
            ap_h[2] = *(uint32_t*)&p2; ap_h[3] = *(uint32_t*)&p3;
            uint32_t bvh[4][4];
            #pragma unroll
            for (int np2 = 0; np2 < 4; np2++) {
                int vrow = c * 16 + r8 + ((g & 1) << 3);
                uint32_t off = sw128((uint32_t)(vrow * 128 + np2 * 32 +
                                                ((g >> 1) << 4)));
                ldsm4t(bvh[np2], sVh + off);
            }
            #pragma unroll
            for (int np2 = 0; np2 < 4; np2++)
                #pragma unroll
                for (int t2 = 0; t2 < 2; t2++)
                    mma16816(O[np2 * 2 + t2], ap_h, &bvh[np2][2 * t2]);
        }
        __syncthreads();
    }

    const float liA = 1.f / lA, liB = 1.f / lB;
    const size_t rowA = qrow0 + wid * 16 + (lane >> 2);
    const size_t rowB = rowA + 8;
    const int    colb = h * DHH + c2;
    #pragma unroll
    for (int j = 0; j < 8; j++) {
        *(__half2*)(ch + rowA * DD + colb + j * 8) =
            __floats2half2_rn(O[j][0] * liA, O[j][1] * liA);
        *(__half2*)(ch + rowB * DD + colb + j * 8) =
            __floats2half2_rn(O[j][2] * liB, O[j][3] * liB);
    }
}

// ================= fp32 -> fp16 convert (x) =================================
__global__ __launch_bounds__(256) void convert_kernel(
    const float4* __restrict__ in, __half2* __restrict__ oh, int n4)
{
    int base = blockIdx.x * 1024 + threadIdx.x;
    #pragma unroll
    for (int u = 0; u < 4; u++) {
        int i = base + u * 256;
        if (i < n4) {
            float4 v = in[i];
            oh[2 * i]     = __floats2half2_rn(v.x, v.y);
            oh[2 * i + 1] = __floats2half2_rn(v.z, v.w);
        }
    }
}

// ALL weights fp32 -> fp16, identity layout, one launch (blockIdx.y selects)
__global__ __launch_bounds__(256) void prep_weights_kernel(
    const float* __restrict__ Wq, const float* __restrict__ Wk,
    const float* __restrict__ Wv, const float* __restrict__ Wo,
    const float* __restrict__ W1, const float* __restrict__ W2,
    __half* __restrict__ wqkv, __half* __restrict__ woh,
    __half* __restrict__ w1h,  __half* __restrict__ w2h)
{
    const int z = blockIdx.y;
    const float* src;
    __half* dst;
    int cnt4;
    switch (z) {
        case 0: src = Wq; dst = wqkv;               cnt4 = DD * DD / 4; break;
        case 1: src = Wk; dst = wqkv + DD * DD;     cnt4 = DD * DD / 4; break;
        case 2: src = Wv; dst = wqkv + 2 * DD * DD; cnt4 = DD * DD / 4; break;
        case 3: src = Wo; dst = woh;                cnt4 = DD * DD / 4; break;
        case 4: src = W1; dst = w1h;                cnt4 = DD * FF / 4; break;
        default: src = W2; dst = w2h;               cnt4 = DD * FF / 4; break;
    }
    const int stride = gridDim.x * 256;
    for (int i = blockIdx.x * 256 + threadIdx.x; i < cnt4; i += stride) {
        float4 v = ((const float4*)src)[i];
        ((__half2*)dst)[2 * i]     = __floats2half2_rn(v.x, v.y);
        ((__half2*)dst)[2 * i + 1] = __floats2half2_rn(v.z, v.w);
    }
}

// ================= residual + LayerNorm =====================================
// XHALF: residual X dtype (0 fp32, 1 fp16).  OUT32: write fp32 out vs fp16 oh.
template<int XHALF, int OUT32>
__global__ __launch_bounds__(256) void residual_ln_kernel(
    const void* __restrict__ Xv, const __half* __restrict__ Y,
    const float* __restrict__ g, const float* __restrict__ beta,
    float* __restrict__ out, __half* __restrict__ oh)
{
    __shared__ float ws[8], ws2[8];
    const int row = blockIdx.x;
    const int tid = threadIdx.x;
    const int lane = tid & 31, warp = tid >> 5;
    const int c4 = tid * 4;

    float v0, v1, v2, v3;
    {
        __half2 y0 = *(const __half2*)(Y + (size_t)row * DD + c4);
        __half2 y1 = *(const __half2*)(Y + (size_t)row * DD + c4 + 2);
        float2 yf0 = __half22float2(y0), yf1 = __half22float2(y1);
        if (XHALF) {
            const __half* X = (const __half*)Xv;
            __half2 x0 = *(const __half2*)(X + (size_t)row * DD + c4);
            __half2 x1 = *(const __half2*)(X + (size_t)row * DD + c4 + 2);
            float2 xf0 = __half22float2(x0), xf1 = __half22float2(x1);
            v0 = xf0.x + yf0.x; v1 = xf0.y + yf0.y;
            v2 = xf1.x + yf1.x; v3 = xf1.y + yf1.y;
        } else {
            float4 xv = *(const float4*)((const float*)Xv + (size_t)row * DD + c4);
            v0 = xv.x + yf0.x; v1 = xv.y + yf0.y;
            v2 = xv.z + yf1.x; v3 = xv.w + yf1.y;
        }
    }
    float s  = v0 + v1 + v2 + v3;
    float s2 = v0 * v0 + v1 * v1 + v2 * v2 + v3 * v3;

    #pragma unroll
    for (int off = 16; off; off >>= 1) {
        s  += __shfl_xor_sync(0xffffffffu, s,  off);
        s2 += __shfl_xor_sync(0xffffffffu, s2, off);
    }
    if (lane == 0) { ws[warp] = s; ws2[warp] = s2; }
    __syncthreads();
    if (warp == 0) {
        s  = (lane < 8) ? ws[lane]  : 0.f;
        s2 = (lane < 8) ? ws2[lane] : 0.f;
        #pragma unroll
        for (int off = 4; off; off >>= 1) {
            s  += __shfl_xor_sync(0xffffffffu, s,  off);
            s2 += __shfl_xor_sync(0xffffffffu, s2, off);
        }
        if (lane == 0) { ws[0] = s; ws2[0] = s2; }
    }
    __syncthreads();
    float mu  = ws[0] * (1.f / 1024.f);
    float var = fmaxf(ws2[0] * (1.f / 1024.f) - mu * mu, 0.f);
    float rstd = rsqrtf(var + 1e-6f);

    float4 gv = *(const float4*)(g + c4);
    float4 bv = *(const float4*)(beta + c4);
    float4 o;
    o.x = gv.x * (v0 - mu) * rstd + bv.x;
    o.y = gv.y * (v1 - mu) * rstd + bv.y;
    o.z = gv.z * (v2 - mu) * rstd + bv.z;
    o.w = gv.w * (v3 - mu) * rstd + bv.w;
    if (OUT32) {
        *(float4*)(out + (size_t)row * DD + c4) = o;
    } else {
        *(__half2*)(oh + (size_t)row * DD + c4)     = __floats2half2_rn(o.x, o.y);
        *(__half2*)(oh + (size_t)row * DD + c4 + 2) = __floats2half2_rn(o.z, o.w);
    }
}

// ================= launch ===================================================
extern "C" void kernel_launch(void* const* d_in, const int* in_sizes, int n_in,
                              void* d_out, int out_size)
{
    const float* x    = (const float*)d_in[0];
    const float* mask = (const float*)d_in[1];
    const float* Wq   = (const float*)d_in[2];
    const float* bq   = (const float*)d_in[3];
    const float* Wk   = (const float*)d_in[4];
    const float* bk   = (const float*)d_in[5];
    const float* Wv   = (const float*)d_in[6];
    const float* bv   = (const float*)d_in[7];
    const float* Wo   = (const float*)d_in[8];
    const float* bo   = (const float*)d_in[9];
    const float* g1   = (const float*)d_in[10];
    const float* be1  = (const float*)d_in[11];
    const float* W1   = (const float*)d_in[12];
    const float* bf1  = (const float*)d_in[13];
    const float* W2   = (const float*)d_in[14];
    const float* bf2  = (const float*)d_in[15];
    const float* g2   = (const float*)d_in[16];
    const float* be2  = (const float*)d_in[17];
    float* out = (float*)d_out;

    __half *ah, *qh, *kh, *vh, *hh, *t1h;
    __half *wqkv, *woh, *w1h, *w2h;
    cudaGetSymbolAddress((void**)&t1h,  g_t1h);
    cudaGetSymbolAddress((void**)&ah,   g_ah);
    cudaGetSymbolAddress((void**)&qh,   g_qh);
    cudaGetSymbolAddress((void**)&kh,   g_kh);
    cudaGetSymbolAddress((void**)&vh,   g_vh);
    cudaGetSymbolAddress((void**)&hh,   g_hh);
    cudaGetSymbolAddress((void**)&wqkv, g_wqkv);
    cudaGetSymbolAddress((void**)&woh,  g_woh);
    cudaGetSymbolAddress((void**)&w1h,  g_w1h);
    cudaGetSymbolAddress((void**)&w2h,  g_w2h);

    cudaFuncSetAttribute(attn_mma,
                         cudaFuncAttributeMaxDynamicSharedMemorySize, A_SMEM);
    cudaFuncSetAttribute(gemm_mma<0, 3>,
                         cudaFuncAttributeMaxDynamicSharedMemorySize, G_SMEM);
    cudaFuncSetAttribute(gemm_mma<0, 2>,
                         cudaFuncAttributeMaxDynamicSharedMemorySize, G_SMEM);
    cudaFuncSetAttribute(gemm_mma<1, 2>,
                         cudaFuncAttributeMaxDynamicSharedMemorySize, G_SMEM);

    // streams: 0 = chain A, s2 = chain B, s3 = weight prep
    static cudaStream_t s2 = nullptr, s3 = nullptr;
    static cudaEvent_t evF, evW, evB;
    if (!s2) {
        cudaStreamCreateWithFlags(&s2, cudaStreamNonBlocking);
        cudaStreamCreateWithFlags(&s3, cudaStreamNonBlocking);
        cudaEventCreateWithFlags(&evF, cudaEventDisableTiming);
        cudaEventCreateWithFlags(&evW, cudaEventDisableTiming);
        cudaEventCreateWithFlags(&evB, cudaEventDisableTiming);
    }

    // per-chain grids (HR = 4096 rows each)
    const dim3 gQKV(3 * DD / 128, HR / 128);  // (24, 32)
    const dim3 gD(DD / 128, HR / 128);        // (8, 32)
    const dim3 gF(FF / 128, HR / 128);        // (32, 32)
    const dim3 gAttn(8, 64);                  // 4 batches x 16 heads
    const int  cvt_n4 = HR * DD / 4;

    // ---- fork ----
    cudaEventRecord(evF, 0);
    cudaStreamWaitEvent(s2, evF, 0);
    cudaStreamWaitEvent(s3, evF, 0);

    // s3: ALL weight conversion in one launch
    prep_weights_kernel<<<dim3(512, 6), 256, 0, s3>>>(
        Wq, Wk, Wv, Wo, W1, W2, wqkv, woh, w1h, w2h);
    cudaEventRecord(evW, s3);

    // ---- two independent batch-half chains ----
    for (int c = 0; c < 2; c++) {
        cudaStream_t st = (c == 0) ? (cudaStream_t)0 : s2;
        const size_t R  = (size_t)c * HR;          // row offset
        const size_t RD = R * DD;
        const size_t RF = R * FF;

        // x -> fp16
        convert_kernel<<<(cvt_n4 + 1023) / 1024, 256, 0, st>>>(
            (const float4*)(x + RD), (__half2*)(ah + RD), cvt_n4);

        // all GEMMs on this stream are after weight prep
        cudaStreamWaitEvent(st, evW, 0);

        // fused QKV projection
        gemm_mma<0, 3><<<gQKV, 256, G_SMEM, st>>>(
            ah + RD, wqkv, wqkv + DD * DD, wqkv + 2 * DD * DD,
            bq, bk, bv, qh + RD, kh + RD, vh + RD, DD, DD);

        // attention for this half's 4 batches (bh_base = c*64)
        attn_mma<<<gAttn, 256, A_SMEM, st>>>(qh, kh, vh, mask, ah, c * 64);

        // output projection (fp16 t1) + residual LN (x fp32 -> ah fp16)
        gemm_mma<0, 2><<<gD, 256, G_SMEM, st>>>(
            ah + RD, woh, nullptr, nullptr, bo, nullptr, nullptr,
            t1h + RD, nullptr, nullptr, DD, DD);
        residual_ln_kernel<0, 0><<<HR, 256, 0, st>>>(
            x + RD, t1h + RD, g1, be1, nullptr, ah + RD);

        // FFN1
        gemm_mma<1, 2><<<gF, 256, G_SMEM, st>>>(
            ah + RD, w1h, nullptr, nullptr, bf1, nullptr, nullptr,
            hh + RF, nullptr, nullptr, FF, DD);

        // FFN2 (fp16 t1) + final residual LN (residual = ah fp16, out fp32)
        gemm_mma<0, 2><<<gD, 256, G_SMEM, st>>>(
            hh + RF, w2h, nullptr, nullptr, bf2, nullptr, nullptr,
            t1h + RD, nullptr, nullptr, DD, FF);
        residual_ln_kernel<1, 1><<<HR, 256, 0, st>>>(
            ah + RD, t1h + RD, g2, be2, out + RD, nullptr);
    }

    // join: default stream waits for chain B
    cudaEventRecord(evB, s2);
    cudaStreamWaitEvent(0, evB, 0);
}

// round 17
// speedup vs baseline: 1.1426x; 1.0194x over previous
#include <cuda_runtime.h>
#include <cuda_fp16.h>
#include <math.h>
#include <stddef.h>
#include <stdint.h>

#define BB   8
#define SS   1024
#define DD   1024
#define HH   16
#define DHH  64
#define FF   4096
#define MR   (BB*SS)   // 8192 rows
#define HR   (MR/2)    // 4096 rows per chain

// attention scale folded with log2(e): S_mma arrives in exp2 domain
#define QSCALE   (0.125f * 1.4426950408889634f)
#define MSCALE   (-1e9f  * 1.4426950408889634f)

// ---------------- scratch (device globals) ----------------------------------
__device__ __half g_t1h[MR*DD];           // fp16 GEMM outputs for LN
__device__ __half g_ah[MR*DD];            // activation fp16 (x / ctx / x1)
__device__ __half g_qh[MR*DD];
__device__ __half g_kh[MR*DD];
__device__ __half g_vh[MR*DD];
__device__ __half g_hh[(size_t)MR*FF];    // FFN hidden
// weights, fp16, SAME layout as source ([K,N] row-major)
__device__ __half g_wqkv[3*DD*DD];        // Wq|Wk|Wv
__device__ __half g_woh[DD*DD];
__device__ __half g_w1h[(size_t)DD*FF];
__device__ __half g_w2h[(size_t)FF*DD];

// ================= PTX helpers ==============================================
__device__ __forceinline__ uint32_t smem_u32(const void* p) {
    uint32_t a;
    asm("{ .reg .u64 t; cvta.to.shared.u64 t, %1; cvt.u32.u64 %0, t; }"
        : "=r"(a) : "l"(p));
    return a;
}
__device__ __forceinline__ uint32_t sw128(uint32_t o) {
    return o ^ ((o >> 3) & 0x70);
}
__device__ __forceinline__ void cp16(uint32_t s, const void* g) {
    asm volatile("cp.async.cg.shared.global [%0], [%1], 16;" :: "r"(s), "l"(g));
}
#define CP_COMMIT()  asm volatile("cp.async.commit_group;" ::: "memory")
#define CP_WAIT0()   asm volatile("cp.async.wait_group 0;" ::: "memory")
#define CP_WAIT1()   asm volatile("cp.async.wait_group 1;" ::: "memory")

__device__ __forceinline__ void ldsm4(uint32_t* r, uint32_t addr) {
    asm volatile("ldmatrix.sync.aligned.m8n8.x4.shared.b16 {%0,%1,%2,%3}, [%4];"
                 : "=r"(r[0]), "=r"(r[1]), "=r"(r[2]), "=r"(r[3]) : "r"(addr));
}
__device__ __forceinline__ void ldsm4t(uint32_t* r, uint32_t addr) {
    asm volatile("ldmatrix.sync.aligned.m8n8.x4.trans.shared.b16 {%0,%1,%2,%3}, [%4];"
                 : "=r"(r[0]), "=r"(r[1]), "=r"(r[2]), "=r"(r[3]) : "r"(addr));
}
__device__ __forceinline__ void mma16816(float* d, const uint32_t* a,
                                         const uint32_t* b) {
    asm("mma.sync.aligned.m16n8k16.row.col.f32.f16.f16.f32 "
        "{%0,%1,%2,%3}, {%4,%5,%6,%7}, {%8,%9}, {%0,%1,%2,%3};"
        : "+f"(d[0]), "+f"(d[1]), "+f"(d[2]), "+f"(d[3])
        : "r"(a[0]), "r"(a[1]), "r"(a[2]), "r"(a[3]),
          "r"(b[0]), "r"(b[1]));
}

// ================= mma.sync GEMM (fp16, 128x128, 2-stage, [K,N] B) ==========
// C[M,N] = A[M,K] @ B[K,N] + bias.  B is row-major [K,N] fp16 (weight layout).
// SPLITOUT: 2 fp16 C | 3 QKV route (q/k/v fp16; Q pre-scaled by QSCALE)
#define G_STAGE  32768            // A 16K | B 16K
#define G_SMEM   (2*G_STAGE)      // 64 KB -> 2 CTAs/SM

template<int ACT, int SPLITOUT>
__global__ __launch_bounds__(256, 2)
void gemm_mma(const __half* __restrict__ Ah,
              const __half* __restrict__ Bq,
              const __half* __restrict__ Bk,
              const __half* __restrict__ Bv,
              const float* __restrict__ bias,
              const float* __restrict__ biasK,
              const float* __restrict__ biasV,
              __half* __restrict__ Ch,
              __half* __restrict__ Kh_,
              __half* __restrict__ Vh_,
              int N, int K)
{
    extern __shared__ __align__(128) char smem[];
    const uint32_t sb = smem_u32(smem);
    const int tid  = threadIdx.x;
    const int wid  = tid >> 5;
    const int lane = tid & 31;
    const int wm   = wid & 3;
    const int wn   = wid >> 2;
    const int bc = blockIdx.x, br = blockIdx.y;

    const __half* Ah_t = Ah + (size_t)br * 128 * K;
    const __half* Bg;
    int colbase;
    if (SPLITOUT == 3) {
        const int sel = bc >> 3;
        Bg = (sel == 0) ? Bq : (sel == 1) ? Bk : Bv;
        colbase = (bc & 7) * 128;
    } else {
        Bg = Bq;
        colbase = bc * 128;
    }
    const int NT = K >> 6;

    auto load_stage = [&](int kt, int s) {
        const uint32_t base = sb + s * G_STAGE;
        const int koff = kt * 64;
        #pragma unroll
        for (int t = 0; t < 4; t++) {
            int idx = t * 256 + tid;
            int row = idx >> 3, ch = idx & 7;
            uint32_t so = sw128((uint32_t)(row * 128 + ch * 16));
            cp16(base + so, Ah_t + (size_t)row * K + koff + ch * 8);
            int nh = row >> 6, kk = row & 63;
            cp16(base + 16384 + so,
                 Bg + (size_t)(koff + kk) * N + colbase + nh * 64 + ch * 8);
        }
        CP_COMMIT();
    };

    float acc[2][8][4];
    #pragma unroll
    for (int mi = 0; mi < 2; mi++)
        #pragma unroll
        for (int nj = 0; nj < 8; nj++)
            #pragma unroll
            for (int e = 0; e < 4; e++) acc[mi][nj][e] = 0.f;

    const int g = lane >> 3, r = lane & 7;

    load_stage(0, 0);

    for (int kt = 0; kt < NT; kt++) {
        const int buf = kt & 1;
        if (kt + 1 < NT) { load_stage(kt + 1, buf ^ 1); CP_WAIT1(); }
        else             { CP_WAIT0(); }
        __syncthreads();

        const uint32_t sA = sb + buf * G_STAGE;
        const uint32_t sB = sA + 16384;

        #pragma unroll
        for (int kc = 0; kc < 4; kc++) {
            uint32_t a_h[2][4];
            #pragma unroll
            for (int mi = 0; mi < 2; mi++) {
                int arow = wm * 32 + mi * 16 + r + ((g & 1) << 3);
                uint32_t off = sw128((uint32_t)(arow * 128 + kc * 32 +
                                                ((g >> 1) << 4)));
                ldsm4(a_h[mi], sA + off);
            }
            uint32_t b_h[4][4];
            const int brow = wn * 64 + kc * 16 + r + ((g & 1) << 3);
            #pragma unroll
            for (int np = 0; np < 4; np++) {
                uint32_t off = sw128((uint32_t)(brow * 128 + np * 32 +
                                                ((g >> 1) << 4)));
                ldsm4t(b_h[np], sB + off);
            }
            #pragma unroll
            for (int np = 0; np < 4; np++)
                #pragma unroll
                for (int t = 0; t < 2; t++)
                    #pragma unroll
                    for (int mi = 0; mi < 2; mi++)
                        mma16816(acc[mi][np * 2 + t], a_h[mi], &b_h[np][2 * t]);
        }
        __syncthreads();
    }

    const int rbase = br * 128 + wm * 32 + (lane >> 2);

    if (SPLITOUT == 3) {
        const int sel   = bc >> 3;
        const int cloc0 = (bc & 7) * 128 + wn * 64 + (lane & 3) * 2;
        __half* dst = (sel == 0) ? Ch : (sel == 1) ? Kh_ : Vh_;
        const float* bp = (sel == 0) ? bias : (sel == 1) ? biasK : biasV;
        const float sc = (sel == 0) ? QSCALE : 1.f;
        #pragma unroll
        for (int mi = 0; mi < 2; mi++) {
            #pragma unroll
            for (int nj = 0; nj < 8; nj++) {
                float2 bv = *(const float2*)(bp + cloc0 + nj * 8);
                float v0 = (acc[mi][nj][0] + bv.x) * sc;
                float v1 = (acc[mi][nj][1] + bv.y) * sc;
                float v2 = (acc[mi][nj][2] + bv.x) * sc;
                float v3 = (acc[mi][nj][3] + bv.y) * sc;
                size_t i0 = (size_t)(rbase + mi * 16)     * DD + cloc0 + nj * 8;
                size_t i1 = (size_t)(rbase + mi * 16 + 8) * DD + cloc0 + nj * 8;
                *(__half2*)(dst + i0) = __floats2half2_rn(v0, v1);
                *(__half2*)(dst + i1) = __floats2half2_rn(v2, v3);
            }
        }
        return;
    }

    const int cbase = bc * 128 + wn * 64 + (lane & 3) * 2;
    #pragma unroll
    for (int mi = 0; mi < 2; mi++) {
        #pragma unroll
        for (int nj = 0; nj < 8; nj++) {
            int c = cbase + nj * 8;
            float2 bv = *(const float2*)(bias + c);
            float v0 = acc[mi][nj][0] + bv.x;
            float v1 = acc[mi][nj][1] + bv.y;
            float v2 = acc[mi][nj][2] + bv.x;
            float v3 = acc[mi][nj][3] + bv.y;
            if (ACT) {
                v0 = fmaxf(v0, 0.f); v1 = fmaxf(v1, 0.f);
                v2 = fmaxf(v2, 0.f); v3 = fmaxf(v3, 0.f);
            }
            size_t i0 = (size_t)(rbase + mi * 16)     * N + c;
            size_t i1 = (size_t)(rbase + mi * 16 + 8) * N + c;
            *(__half2*)(Ch + i0) = __floats2half2_rn(v0, v1);
            *(__half2*)(Ch + i1) = __floats2half2_rn(v2, v3);
        }
    }
}

// ================= Flash attention (fp16, exp2-domain softmax) ==============
// Q pre-scaled by QSCALE, mask scaled by MSCALE: S arrives in exp2 domain.
#define A_QH   0
#define A_ST   16384            // 2 stages x (Kh 8K | Vh 8K)
#define A_MK   49152            // 2 x 256 B mask
#define A_SMEM (49152 + 512)

__global__ __launch_bounds__(256, 2)
void attn_mma(const __half* __restrict__ qh,
              const __half* __restrict__ kh,
              const __half* __restrict__ vh,
              const float* __restrict__ mask,
              __half* __restrict__ ch,
              int bh_base)
{
    extern __shared__ __align__(128) char smem[];
    const uint32_t sb = smem_u32(smem);
    const int tid  = threadIdx.x;
    const int wid  = tid >> 5;
    const int lane = tid & 31;
    const int g    = lane >> 3, r8 = lane & 7;
    const int c2   = (lane & 3) * 2;

    const int qt = blockIdx.x;
    const int bh = bh_base + blockIdx.y;
    const int b  = bh >> 4;
    const int h  = bh & 15;

    const size_t qrow0 = (size_t)b * SS + (size_t)qt * 128;
    const __half* qhg = qh + qrow0 * DD + h * DHH;
    const __half* khg = kh + (size_t)b * SS * DD + h * DHH;
    const __half* vhg = vh + (size_t)b * SS * DD + h * DHH;
    const float* mkg = mask + (size_t)b * SS;

    auto load_kv = [&](int t, int s) {
        const uint32_t base = sb + A_ST + s * 16384;
        const size_t koff = (size_t)(t * 64) * DD;
        #pragma unroll
        for (int it = 0; it < 4; it++) {
            int idx = it * 256 + tid;
            int mat = idx >> 9;
            int sub = idx & 511;
            int row = sub >> 3, chk = sub & 7;
            uint32_t so = sw128((uint32_t)(row * 128 + chk * 16));
            size_t go = koff + (size_t)row * DD + chk * 8;
            cp16(base + mat * 8192 + so, (mat ? vhg : khg) + go);
        }
        if (tid < 16)
            cp16(sb + A_MK + s * 256 + tid * 16, mkg + t * 64 + tid * 4);
        CP_COMMIT();
    };

    #pragma unroll
    for (int it = 0; it < 4; it++) {
        int idx = it * 256 + tid;
        int row = idx >> 3, chk = idx & 7;
        uint32_t so = sw128((uint32_t)(row * 128 + chk * 16));
        cp16(sb + A_QH + so, qhg + (size_t)row * DD + chk * 8);
    }
    load_kv(0, 0);

    float mA = -INFINITY, mB = -INFINITY, lA = 0.f, lB = 0.f;
    float O[8][4];
    #pragma unroll
    for (int j = 0; j < 8; j++)
        #pragma unroll
        for (int e = 0; e < 4; e++) O[j][e] = 0.f;

    #pragma unroll 1
    for (int t = 0; t < 16; t++) {
        const int buf = t & 1;
        if (t + 1 < 16) { load_kv(t + 1, buf ^ 1); CP_WAIT1(); }
        else            { CP_WAIT0(); }
        __syncthreads();

        const uint32_t sKh = sb + A_ST + buf * 16384;
        const uint32_t sVh = sKh + 8192;
        const float* mkv = (const float*)(smem + A_MK + buf * 256);

        float s_[8][4];
        #pragma unroll
        for (int j = 0; j < 8; j++)
            #pragma unroll
            for (int e = 0; e < 4; e++) s_[j][e] = 0.f;

        #pragma unroll
        for (int kc = 0; kc < 4; kc++) {
            uint32_t aqh[4];
            {
                int arow = wid * 16 + r8 + ((g & 1) << 3);
                uint32_t off = sw128((uint32_t)(arow * 128 + kc * 32 +
                                                ((g >> 1) << 4)));
                ldsm4(aqh, sb + A_QH + off);
            }
            uint32_t bkh[4][4];
            #pragma unroll
            for (int np = 0; np < 4; np++) {
                int brow = np * 16 + r8 + ((g >> 1) << 3);
                uint32_t off = sw128((uint32_t)(brow * 128 + kc * 32 +
                                                ((g & 1) << 4)));
                ldsm4(bkh[np], sKh + off);
            }
            #pragma unroll
            for (int np = 0; np < 4; np++)
                #pragma unroll
                for (int t2 = 0; t2 < 2; t2++)
                    mma16816(s_[np * 2 + t2], aqh, &bkh[np][2 * t2]);
        }

        // ---- mask add (exp2 domain), row max ----
        float tmA = -INFINITY, tmB = -INFINITY;
        #pragma unroll
        for (int j = 0; j < 8; j++) {
            float mk0 = mkv[j * 8 + c2]     * MSCALE;
            float mk1 = mkv[j * 8 + c2 + 1] * MSCALE;
            s_[j][0] += mk0;
            s_[j][1] += mk1;
            s_[j][2] += mk0;
            s_[j][3] += mk1;
            tmA = fmaxf(tmA, fmaxf(s_[j][0], s_[j][1]));
            tmB = fmaxf(tmB, fmaxf(s_[j][2], s_[j][3]));
        }
        tmA = fmaxf(tmA, __shfl_xor_sync(0xffffffffu, tmA, 1));
        tmA = fmaxf(tmA, __shfl_xor_sync(0xffffffffu, tmA, 2));
        tmB = fmaxf(tmB, __shfl_xor_sync(0xffffffffu, tmB, 1));
        tmB = fmaxf(tmB, __shfl_xor_sync(0xffffffffu, tmB, 2));

        const float nmA = fmaxf(mA, tmA), nmB = fmaxf(mB, tmB);
        const float fA = exp2f(mA - nmA), fB = exp2f(mB - nmB);

        float sumA = 0.f, sumB = 0.f;
        #pragma unroll
        for (int j = 0; j < 8; j++) {
            s_[j][0] = exp2f(s_[j][0] - nmA);
            s_[j][1] = exp2f(s_[j][1] - nmA);
            s_[j][2] = exp2f(s_[j][2] - nmB);
            s_[j][3] = exp2f(s_[j][3] - nmB);
            sumA += s_[j][0] + s_[j][1];
            sumB += s_[j][2] + s_[j][3];
        }
        sumA += __shfl_xor_sync(0xffffffffu, sumA, 1);
        sumA += __shfl_xor_sync(0xffffffffu, sumA, 2);
        sumB += __shfl_xor_sync(0xffffffffu, sumB, 1);
        sumB += __shfl_xor_sync(0xffffffffu, sumB, 2);
        lA = lA * fA + sumA;  mA = nmA;
        lB = lB * fB + sumB;  mB = nmB;

        #pragma unroll
        for (int j = 0; j < 8; j++) {
            O[j][0] *= fA; O[j][1] *= fA;
            O[j][2] *= fB; O[j][3] *= fB;
        }

        #pragma unroll
        for (int c = 0; c < 4; c++) {
            uint32_t ap_h[4];
            __half2 p0 = __floats2half2_rn(s_[2 * c][0],     s_[2 * c][1]);
            __half2 p1 = __floats2half2_rn(s_[2 * c][2],     s_[2 * c][3]);
            __half2 p2 = __floats2half2_rn(s_[2 * c + 1][0], s_[2 * c + 1][1]);
            __half2 p3 = __floats2half2_rn(s_[2 * c + 1][2], s_[2 * c + 1][3]);
            ap_h[0] = *(uint32_t*)&p0; ap_h[1] = *(uint32_t*)&p1;
            ap_h[2] = *(uint32_t*)&p2; ap_h[3] = *(uint32_t*)&p3;
            uint32_t bvh[4][4];
            #pragma unroll
            for (int np2 = 0; np2 < 4; np2++) {
                int vrow = c * 16 + r8 + ((g & 1) << 3);
                uint32_t off = sw128((uint32_t)(vrow * 128 + np2 * 32 +
                                                ((g >> 1) << 4)));
                ldsm4t(bvh[np2], sVh + off);
            }
            #pragma unroll
            for (int np2 = 0; np2 < 4; np2++)
                #pragma unroll
                for (int t2 = 0; t2 < 2; t2++)
                    mma16816(O[np2 * 2 + t2], ap_h, &bvh[np2][2 * t2]);
        }
        __syncthreads();
    }

    const float liA = 1.f / lA, liB = 1.f / lB;
    const size_t rowA = qrow0 + wid * 16 + (lane >> 2);
    const size_t rowB = rowA + 8;
    const int    colb = h * DHH + c2;
    #pragma unroll
    for (int j = 0; j < 8; j++) {
        *(__half2*)(ch + rowA * DD + colb + j * 8) =
            __floats2half2_rn(O[j][0] * liA, O[j][1] * liA);
        *(__half2*)(ch + rowB * DD + colb + j * 8) =
            __floats2half2_rn(O[j][2] * liB, O[j][3] * liB);
    }
}

// ================= fp32 -> fp16 convert (x) =================================
__global__ __launch_bounds__(256) void convert_kernel(
    const float4* __restrict__ in, __half2* __restrict__ oh, int n4)
{
    int base = blockIdx.x * 1024 + threadIdx.x;
    #pragma unroll
    for (int u = 0; u < 4; u++) {
        int i = base + u * 256;
        if (i < n4) {
            float4 v = in[i];
            oh[2 * i]     = __floats2half2_rn(v.x, v.y);
            oh[2 * i + 1] = __floats2half2_rn(v.z, v.w);
        }
    }
}

// ALL weights fp32 -> fp16, identity layout, one launch (blockIdx.y selects)
__global__ __launch_bounds__(256) void prep_weights_kernel(
    const float* __restrict__ Wq, const float* __restrict__ Wk,
    const float* __restrict__ Wv, const float* __restrict__ Wo,
    const float* __restrict__ W1, const float* __restrict__ W2,
    __half* __restrict__ wqkv, __half* __restrict__ woh,
    __half* __restrict__ w1h,  __half* __restrict__ w2h)
{
    const int z = blockIdx.y;
    const float* src;
    __half* dst;
    int cnt4;
    switch (z) {
        case 0: src = Wq; dst = wqkv;               cnt4 = DD * DD / 4; break;
        case 1: src = Wk; dst = wqkv + DD * DD;     cnt4 = DD * DD / 4; break;
        case 2: src = Wv; dst = wqkv + 2 * DD * DD; cnt4 = DD * DD / 4; break;
        case 3: src = Wo; dst = woh;                cnt4 = DD * DD / 4; break;
        case 4: src = W1; dst = w1h;                cnt4 = DD * FF / 4; break;
        default: src = W2; dst = w2h;               cnt4 = DD * FF / 4; break;
    }
    const int stride = gridDim.x * 256;
    for (int i = blockIdx.x * 256 + threadIdx.x; i < cnt4; i += stride) {
        float4 v = ((const float4*)src)[i];
        ((__half2*)dst)[2 * i]     = __floats2half2_rn(v.x, v.y);
        ((__half2*)dst)[2 * i + 1] = __floats2half2_rn(v.z, v.w);
    }
}

// ================= residual + LayerNorm =====================================
// XHALF: residual X dtype (0 fp32, 1 fp16).  OUT32: write fp32 out vs fp16 oh.
template<int XHALF, int OUT32>
__global__ __launch_bounds__(256) void residual_ln_kernel(
    const void* __restrict__ Xv, const __half* __restrict__ Y,
    const float* __restrict__ g, const float* __restrict__ beta,
    float* __restrict__ out, __half* __restrict__ oh)
{
    __shared__ float ws[8], ws2[8];
    const int row = blockIdx.x;
    const int tid = threadIdx.x;
    const int lane = tid & 31, warp = tid >> 5;
    const int c4 = tid * 4;

    float v0, v1, v2, v3;
    {
        __half2 y0 = *(const __half2*)(Y + (size_t)row * DD + c4);
        __half2 y1 = *(const __half2*)(Y + (size_t)row * DD + c4 + 2);
        float2 yf0 = __half22float2(y0), yf1 = __half22float2(y1);
        if (XHALF) {
            const __half* X = (const __half*)Xv;
            __half2 x0 = *(const __half2*)(X + (size_t)row * DD + c4);
            __half2 x1 = *(const __half2*)(X + (size_t)row * DD + c4 + 2);
            float2 xf0 = __half22float2(x0), xf1 = __half22float2(x1);
            v0 = xf0.x + yf0.x; v1 = xf0.y + yf0.y;
            v2 = xf1.x + yf1.x; v3 = xf1.y + yf1.y;
        } else {
            float4 xv = *(const float4*)((const float*)Xv + (size_t)row * DD + c4);
            v0 = xv.x + yf0.x; v1 = xv.y + yf0.y;
            v2 = xv.z + yf1.x; v3 = xv.w + yf1.y;
        }
    }
    float s  = v0 + v1 + v2 + v3;
    float s2 = v0 * v0 + v1 * v1 + v2 * v2 + v3 * v3;

    #pragma unroll
    for (int off = 16; off; off >>= 1) {
        s  += __shfl_xor_sync(0xffffffffu, s,  off);
        s2 += __shfl_xor_sync(0xffffffffu, s2, off);
    }
    if (lane == 0) { ws[warp] = s; ws2[warp] = s2; }
    __syncthreads();
    if (warp == 0) {
        s  = (lane < 8) ? ws[lane]  : 0.f;
        s2 = (lane < 8) ? ws2[lane] : 0.f;
        #pragma unroll
        for (int off = 4; off; off >>= 1) {
            s  += __shfl_xor_sync(0xffffffffu, s,  off);
            s2 += __shfl_xor_sync(0xffffffffu, s2, off);
        }
        if (lane == 0) { ws[0] = s; ws2[0] = s2; }
    }
    __syncthreads();
    float mu  = ws[0] * (1.f / 1024.f);
    float var = fmaxf(ws2[0] * (1.f / 1024.f) - mu * mu, 0.f);
    float rstd = rsqrtf(var + 1e-6f);

    float4 gv = *(const float4*)(g + c4);
    float4 bv = *(const float4*)(beta + c4);
    float4 o;
    o.x = gv.x * (v0 - mu) * rstd + bv.x;
    o.y = gv.y * (v1 - mu) * rstd + bv.y;
    o.z = gv.z * (v2 - mu) * rstd + bv.z;
    o.w = gv.w * (v3 - mu) * rstd + bv.w;
    if (OUT32) {
        *(float4*)(out + (size_t)row * DD + c4) = o;
    } else {
        *(__half2*)(oh + (size_t)row * DD + c4)     = __floats2half2_rn(o.x, o.y);
        *(__half2*)(oh + (size_t)row * DD + c4 + 2) = __floats2half2_rn(o.z, o.w);
    }
}

// ================= launch ===================================================
extern "C" void kernel_launch(void* const* d_in, const int* in_sizes, int n_in,
                              void* d_out, int out_size)
{
    const float* x    = (const float*)d_in[0];
    const float* mask = (const float*)d_in[1];
    const float* Wq   = (const float*)d_in[2];
    const float* bq   = (const float*)d_in[3];
    const float* Wk   = (const float*)d_in[4];
    const float* bk   = (const float*)d_in[5];
    const float* Wv   = (const float*)d_in[6];
    const float* bv   = (const float*)d_in[7];
    const float* Wo   = (const float*)d_in[8];
    const float* bo   = (const float*)d_in[9];
    const float* g1   = (const float*)d_in[10];
    const float* be1  = (const float*)d_in[11];
    const float* W1   = (const float*)d_in[12];
    const float* bf1  = (const float*)d_in[13];
    const float* W2   = (const float*)d_in[14];
    const float* bf2  = (const float*)d_in[15];
    const float* g2   = (const float*)d_in[16];
    const float* be2  = (const float*)d_in[17];
    float* out = (float*)d_out;

    __half *ah, *qh, *kh, *vh, *hh, *t1h;
    __half *wqkv, *woh, *w1h, *w2h;
    cudaGetSymbolAddress((void**)&t1h,  g_t1h);
    cudaGetSymbolAddress((void**)&ah,   g_ah);
    cudaGetSymbolAddress((void**)&qh,   g_qh);
    cudaGetSymbolAddress((void**)&kh,   g_kh);
    cudaGetSymbolAddress((void**)&vh,   g_vh);
    cudaGetSymbolAddress((void**)&hh,   g_hh);
    cudaGetSymbolAddress((void**)&wqkv, g_wqkv);
    cudaGetSymbolAddress((void**)&woh,  g_woh);
    cudaGetSymbolAddress((void**)&w1h,  g_w1h);
    cudaGetSymbolAddress((void**)&w2h,  g_w2h);

    cudaFuncSetAttribute(attn_mma,
                         cudaFuncAttributeMaxDynamicSharedMemorySize, A_SMEM);
    cudaFuncSetAttribute(gemm_mma<0, 3>,
                         cudaFuncAttributeMaxDynamicSharedMemorySize, G_SMEM);
    cudaFuncSetAttribute(gemm_mma<0, 2>,
                         cudaFuncAttributeMaxDynamicSharedMemorySize, G_SMEM);
    cudaFuncSetAttribute(gemm_mma<1, 2>,
                         cudaFuncAttributeMaxDynamicSharedMemorySize, G_SMEM);

    // streams: 0 = chain A, s2 = chain B, s3 = weight prep
    static cudaStream_t s2 = nullptr, s3 = nullptr;
    static cudaEvent_t evF, evW, evB;
    if (!s2) {
        cudaStreamCreateWithFlags(&s2, cudaStreamNonBlocking);
        cudaStreamCreateWithFlags(&s3, cudaStreamNonBlocking);
        cudaEventCreateWithFlags(&evF, cudaEventDisableTiming);
        cudaEventCreateWithFlags(&evW, cudaEventDisableTiming);
        cudaEventCreateWithFlags(&evB, cudaEventDisableTiming);
    }

    const dim3 gQKV(3 * DD / 128, HR / 128);  // (24, 32)
    const dim3 gD(DD / 128, HR / 128);        // (8, 32)
    const dim3 gF(FF / 128, HR / 128);        // (32, 32)
    const dim3 gAttn(8, 64);                  // 4 batches x 16 heads
    const int  cvt_n4 = HR * DD / 4;

    // ---- fork ----
    cudaEventRecord(evF, 0);
    cudaStreamWaitEvent(s2, evF, 0);
    cudaStreamWaitEvent(s3, evF, 0);

    // s3: ALL weight conversion in one launch
    prep_weights_kernel<<<dim3(512, 6), 256, 0, s3>>>(
        Wq, Wk, Wv, Wo, W1, W2, wqkv, woh, w1h, w2h);
    cudaEventRecord(evW, s3);

    // ---- two independent batch-half chains ----
    for (int c = 0; c < 2; c++) {
        cudaStream_t st = (c == 0) ? (cudaStream_t)0 : s2;
        const size_t R  = (size_t)c * HR;          // row offset
        const size_t RD = R * DD;
        const size_t RF = R * FF;

        // x -> fp16
        convert_kernel<<<(cvt_n4 + 1023) / 1024, 256, 0, st>>>(
            (const float4*)(x + RD), (__half2*)(ah + RD), cvt_n4);

        // all GEMMs on this stream are after weight prep
        cudaStreamWaitEvent(st, evW, 0);

        // fused QKV projection (Q pre-scaled by QSCALE in epilogue)
        gemm_mma<0, 3><<<gQKV, 256, G_SMEM, st>>>(
            ah + RD, wqkv, wqkv + DD * DD, wqkv + 2 * DD * DD,
            bq, bk, bv, qh + RD, kh + RD, vh + RD, DD, DD);

        // attention for this half's 4 batches (bh_base = c*64)
        attn_mma<<<gAttn, 256, A_SMEM, st>>>(qh, kh, vh, mask, ah, c * 64);

        // output projection (fp16 t1) + residual LN (x fp32 -> ah fp16)
        gemm_mma<0, 2><<<gD, 256, G_SMEM, st>>>(
            ah + RD, woh, nullptr, nullptr, bo, nullptr, nullptr,
            t1h + RD, nullptr, nullptr, DD, DD);
        residual_ln_kernel<0, 0><<<HR, 256, 0, st>>>(
            x + RD, t1h + RD, g1, be1, nullptr, ah + RD);

        // FFN1
        gemm_mma<1, 2><<<gF, 256, G_SMEM, st>>>(
            ah + RD, w1h, nullptr, nullptr, bf1, nullptr, nullptr,
            hh + RF, nullptr, nullptr, FF, DD);

        // FFN2 (fp16 t1) + final residual LN (residual = ah fp16, out fp32)
        gemm_mma<0, 2><<<gD, 256, G_SMEM, st>>>(
            hh + RF, w2h, nullptr, nullptr, bf2, nullptr, nullptr,
            t1h + RD, nullptr, nullptr, DD, FF);
        residual_ln_kernel<1, 1><<<HR, 256, 0, st>>>(
            ah + RD, t1h + RD, g2, be2, out + RD, nullptr);
    }

    // join: default stream waits for chain B
    cudaEventRecord(evB, s2);
    cudaStreamWaitEvent(0, evB, 0);
}